// round 6
// baseline (speedup 1.0000x reference)
#include <cuda_runtime.h>
#include <cuda_bf16.h>
#include <math.h>
#include <stdint.h>

typedef __nv_bfloat16 bf16;

// Problem constants
#define DM    1024
#define DFF   4096
#define NTOK  8192
#define SEQ   2048
#define BATCH 4
#define NH    16
#define DK    64
#define QKVN  3072
#define QKVS  3072

// GEMM tiling
#define BM 256
#define BN 128
#define BK 64
#define AOFF(buf, t) (1024u + ((buf) * 2 + (t)) * 32768u)
#define BOFF(buf, t) (132096u + ((buf) * 2 + (t)) * 16384u)
#define SMEM_TOTAL   (132096 + 4 * 16384)    // 197632 B

// idesc kind::f16: F32 acc, BF16 a/b, N=128, M=128
#define IDESC 0x8200490u
#define SWZ(x) ((x) ^ (((x) >> 3) & 0x70))

// ---------------------------------------------------------------------------
// Scratch (device globals)
// ---------------------------------------------------------------------------
__device__ bf16  g_xn1h[NTOK * DM], g_xn1l[NTOK * DM];
__device__ bf16  g_xn2h[NTOK * DM], g_xn2l[NTOK * DM];
__device__ bf16  g_oh  [NTOK * DM], g_ol  [NTOK * DM];
__device__ bf16  g_h1h [NTOK * DFF], g_h1l[NTOK * DFF];
__device__ float g_qkv [NTOK * QKVS];
__device__ float g_x1  [NTOK * DM];
__device__ float g_mpart[BATCH * NH * 8 * DK * DK];
__device__ bf16 g_wqkvTh[QKVN * DM], g_wqkvTl[QKVN * DM];
__device__ bf16 g_woTh[DM * DM],   g_woTl[DM * DM];
__device__ bf16 g_w1Th[DFF * DM],  g_w1Tl[DFF * DM];
__device__ bf16 g_w2Th[DM * DFF],  g_w2Tl[DM * DFF];

// ---------------------------------------------------------------------------
// Common helpers
// ---------------------------------------------------------------------------
__device__ __forceinline__ uint32_t smem_u32(const void* p) {
    return (uint32_t)__cvta_generic_to_shared(p);
}
__device__ __forceinline__ void cp16(uint32_t dst, const void* src) {
    asm volatile("cp.async.cg.shared.global [%0], [%1], 16;\n" :: "r"(dst), "l"(src));
}
__device__ __forceinline__ void split2(float v, bf16& h, bf16& l) {
    h = __float2bfloat16(v);
    l = __float2bfloat16(v - __bfloat162float(h));
}
__device__ __forceinline__ void ldmx4u(uint32_t* r, uint32_t addr) {
    asm volatile("ldmatrix.sync.aligned.m8n8.x4.shared.b16 {%0,%1,%2,%3}, [%4];\n"
                 : "=r"(r[0]), "=r"(r[1]), "=r"(r[2]), "=r"(r[3]) : "r"(addr));
}
__device__ __forceinline__ void mma16816(float* d, const uint32_t* a, uint32_t b0, uint32_t b1) {
    asm volatile(
        "mma.sync.aligned.m16n8k16.row.col.f32.bf16.bf16.f32 "
        "{%0,%1,%2,%3},{%4,%5,%6,%7},{%8,%9},{%0,%1,%2,%3};\n"
        : "+f"(d[0]), "+f"(d[1]), "+f"(d[2]), "+f"(d[3])
        : "r"(a[0]), "r"(a[1]), "r"(a[2]), "r"(a[3]), "r"(b0), "r"(b1));
}

// ---------------------------------------------------------------------------
// Stage loader: A(hi,lo) 256x64, B(hi,lo) 128x64 bf16, SW128, via cp.async.
// ---------------------------------------------------------------------------
__device__ __forceinline__ void stage_load(
    uint32_t smem_base,
    const bf16* __restrict__ Ah, const bf16* __restrict__ Al,
    const bf16* __restrict__ Bh, const bf16* __restrict__ Bl,
    int m0, int n0, int k0, int K, int tid, int buf)
{
    #pragma unroll
    for (int t = 0; t < 2; t++) {
        const bf16* src = t ? Al : Ah;
        uint32_t base = smem_base + AOFF(buf, t);
        #pragma unroll
        for (int i = 0; i < 8; i++) {
            int chunk = tid + i * 256;
            int r = chunk >> 3, c = chunk & 7;
            uint32_t off = (uint32_t)(r * 128 + c * 16);
            cp16(base + SWZ(off), src + (size_t)(m0 + r) * K + k0 + c * 8);
        }
    }
    #pragma unroll
    for (int t = 0; t < 2; t++) {
        const bf16* src = t ? Bl : Bh;
        uint32_t base = smem_base + BOFF(buf, t);
        #pragma unroll
        for (int i = 0; i < 4; i++) {
            int chunk = tid + i * 256;
            int r = chunk >> 3, c = chunk & 7;
            uint32_t off = (uint32_t)(r * 128 + c * 16);
            cp16(base + SWZ(off), src + (size_t)(n0 + r) * K + k0 + c * 8);
        }
    }
}

// ===========================================================================
// tcgen05-only helpers (compiled only when an 'a' feature target exists)
// ===========================================================================
#if defined(__CUDA_ARCH_FEAT_SM103_ALL) || defined(__CUDA_ARCH_FEAT_SM100_ALL)
__device__ __forceinline__ uint32_t elect_one() {
    uint32_t pred;
    asm volatile("{\n .reg .pred p;\n elect.sync _|p, 0xFFFFFFFF;\n selp.b32 %0, 1, 0, p;\n}"
                 : "=r"(pred));
    return pred;
}
__device__ __forceinline__ uint64_t make_desc(uint32_t addr) {
    return ((uint64_t)2 << 61) | ((uint64_t)1 << 46) | ((uint64_t)64 << 32) |
           ((uint64_t)1 << 16) | ((uint64_t)(addr >> 4) & 0x3FFF);
}
__device__ __forceinline__ void mma_f16_ss(uint32_t d, uint64_t a, uint64_t b,
                                           uint32_t idesc, bool en) {
    uint32_t e = en ? 1u : 0u;
    asm volatile(
        "{\n\t"
        ".reg .pred p;\n\t"
        "setp.ne.u32 p, %4, 0;\n\t"
        "tcgen05.mma.cta_group::1.kind::f16 [%0], %1, %2, %3, {%5,%5,%5,%5}, p;\n\t"
        "}"
        :: "r"(d), "l"(a), "l"(b), "r"(idesc), "r"(e), "r"(0u) : "memory");
}
__device__ __forceinline__ void mbar_init(uint32_t a, uint32_t c) {
    asm volatile("mbarrier.init.shared.b64 [%0], %1;" :: "r"(a), "r"(c) : "memory");
}
__device__ __forceinline__ void mbar_wait(uint32_t mbar, uint32_t parity) {
    asm volatile(
        "{\n\t"
        ".reg .pred P1;\n\t"
        "WAIT_LOOP_%=:\n\t"
        "mbarrier.try_wait.parity.acquire.cta.shared::cta.b64 P1, [%0], %1, 0x989680;\n\t"
        "@P1 bra.uni WAIT_DONE_%=;\n\t"
        "bra.uni WAIT_LOOP_%=;\n\t"
        "WAIT_DONE_%=:\n\t"
        "}" :: "r"(mbar), "r"(parity) : "memory");
}
#define TC_ALLOC(sm, n)  asm volatile("tcgen05.alloc.cta_group::1.sync.aligned.shared::cta.b32 [%0], %1;" :: "r"(sm), "r"((uint32_t)(n)) : "memory")
#define TC_RELINQ()      asm volatile("tcgen05.relinquish_alloc_permit.cta_group::1.sync.aligned;")
#define TC_DEALLOC(t, n) asm volatile("tcgen05.dealloc.cta_group::1.sync.aligned.b32 %0, %1;" :: "r"(t), "r"((uint32_t)(n)))
#define TC_COMMIT(mb)    asm volatile("tcgen05.commit.cta_group::1.mbarrier::arrive::one.shared::cluster.b64 [%0];" :: "r"(mb) : "memory")
#define TC_FENCE_AFTER() asm volatile("tcgen05.fence::after_thread_sync;" ::: "memory")
#define TC_FENCE_BEFORE() asm volatile("tcgen05.fence::before_thread_sync;" ::: "memory")
#define TC_WAIT_LD()     asm volatile("tcgen05.wait::ld.sync.aligned;" ::: "memory")
#define FENCE_ASYNC()    asm volatile("fence.proxy.async.shared::cta;" ::: "memory")
#define TC_LD_X32(r, ta) \
    asm volatile( \
        "tcgen05.ld.sync.aligned.32x32b.x32.b32 " \
        "{%0, %1, %2, %3, %4, %5, %6, %7, " \
        " %8, %9, %10, %11, %12, %13, %14, %15, " \
        " %16, %17, %18, %19, %20, %21, %22, %23, " \
        " %24, %25, %26, %27, %28, %29, %30, %31}, [%32];" \
        : "=r"((r)[0]),  "=r"((r)[1]),  "=r"((r)[2]),  "=r"((r)[3]), \
          "=r"((r)[4]),  "=r"((r)[5]),  "=r"((r)[6]),  "=r"((r)[7]), \
          "=r"((r)[8]),  "=r"((r)[9]),  "=r"((r)[10]), "=r"((r)[11]), \
          "=r"((r)[12]), "=r"((r)[13]), "=r"((r)[14]), "=r"((r)[15]), \
          "=r"((r)[16]), "=r"((r)[17]), "=r"((r)[18]), "=r"((r)[19]), \
          "=r"((r)[20]), "=r"((r)[21]), "=r"((r)[22]), "=r"((r)[23]), \
          "=r"((r)[24]), "=r"((r)[25]), "=r"((r)[26]), "=r"((r)[27]), \
          "=r"((r)[28]), "=r"((r)[29]), "=r"((r)[30]), "=r"((r)[31]) \
        : "r"(ta))

// Epilogue: read one tile's D from TMEM (half-parity tp), fuse, store.
template<int MODE>
__device__ __forceinline__ void tc_epilogue(
    uint32_t smem_base, uint32_t tmem, int tp, int glast,
    int m0, int n0, int wid, int lane, int N,
    float* __restrict__ C, bf16* __restrict__ Ch, bf16* __restrict__ Cl,
    const float* __restrict__ bias, const float* __restrict__ resid)
{
    mbar_wait(smem_base + 8 + (glast & 1) * 8, (glast >> 1) & 1);
    TC_FENCE_AFTER();
    int half = wid >> 2;
    int grow = m0 + half * 128 + ((wid & 3) << 5) + lane;
    #pragma unroll
    for (int cb = 0; cb < 4; cb++) {
        uint32_t r[32];
        TC_LD_X32(r, tmem + tp * 256 + half * 128 + cb * 32);
        TC_WAIT_LD();
        int gcol = n0 + cb * 32;
        size_t base = (size_t)grow * N + gcol;
        #pragma unroll
        for (int j = 0; j < 32; j += 4) {
            float v0 = __uint_as_float(r[j]);
            float v1 = __uint_as_float(r[j + 1]);
            float v2 = __uint_as_float(r[j + 2]);
            float v3 = __uint_as_float(r[j + 3]);
            if (MODE == 2 || MODE == 3) {
                float4 bb = *reinterpret_cast<const float4*>(bias + gcol + j);
                v0 += bb.x; v1 += bb.y; v2 += bb.z; v3 += bb.w;
            }
            if (MODE == 2) {
                v0 = fmaxf(v0, 0.f); v1 = fmaxf(v1, 0.f);
                v2 = fmaxf(v2, 0.f); v3 = fmaxf(v3, 0.f);
            }
            if (MODE == 1 || MODE == 3) {
                float4 rr = *reinterpret_cast<const float4*>(resid + base + j);
                v0 += rr.x; v1 += rr.y; v2 += rr.z; v3 += rr.w;
            }
            if (MODE == 2) {
                bf16 h0, h1, h2, h3, l0, l1, l2, l3;
                split2(v0, h0, l0); split2(v1, h1, l1);
                split2(v2, h2, l2); split2(v3, h3, l3);
                __nv_bfloat162 hp0(h0, h1), hp1(h2, h3), lp0(l0, l1), lp1(l2, l3);
                uint2 hu, lu;
                hu.x = *reinterpret_cast<uint32_t*>(&hp0);
                hu.y = *reinterpret_cast<uint32_t*>(&hp1);
                lu.x = *reinterpret_cast<uint32_t*>(&lp0);
                lu.y = *reinterpret_cast<uint32_t*>(&lp1);
                *reinterpret_cast<uint2*>(Ch + base + j) = hu;
                *reinterpret_cast<uint2*>(Cl + base + j) = lu;
            } else {
                float4 o; o.x = v0; o.y = v1; o.z = v2; o.w = v3;
                *reinterpret_cast<float4*>(C + base + j) = o;
            }
        }
    }
    TC_FENCE_BEFORE();
}
#endif

// ---------------------------------------------------------------------------
// Persistent GEMM, 256x128 tiles, 3-term bf16 split (hh+hl+lh), fp32 acc.
// MODE: 0=plain fp32, 1=+resid fp32, 2=relu(D+bias)->split bf16,
//       3=D+bias+resid fp32.
// ---------------------------------------------------------------------------
template<int MODE>
__global__ __launch_bounds__(256)
void gemm_tc(
    const bf16* __restrict__ Ah, const bf16* __restrict__ Al,
    const bf16* __restrict__ Bh, const bf16* __restrict__ Bl,
    float* __restrict__ C, bf16* __restrict__ Ch, bf16* __restrict__ Cl,
    int N, int K, int ntiles,
    const float* __restrict__ bias, const float* __restrict__ resid)
{
    extern __shared__ char smem[];
    uint32_t smem_base = smem_u32(smem);
    int tid = threadIdx.x;
    int wid = tid >> 5, lane = tid & 31;
    int ntn = N / BN;
    int S = K / BK;

#if defined(__CUDA_ARCH_FEAT_SM103_ALL) || defined(__CUDA_ARCH_FEAT_SM100_ALL)
    // ======================= tcgen05 persistent path =======================
    if (wid == 0) { TC_ALLOC(smem_base, 512); }
    else if (wid == 1) { TC_RELINQ(); }
    if (tid == 0) { mbar_init(smem_base + 8, 1); mbar_init(smem_base + 16, 1); }
    __syncthreads();
    uint32_t tmem;
    asm volatile("ld.shared.b32 %0, [%1];" : "=r"(tmem) : "r"(smem_base));

    int g = 0, tcount = 0;
    int pm0 = 0, pn0 = 0, ptp = 0, pg = 0;
    bool havePrev = false;

    for (int tl = blockIdx.x; tl < ntiles; tl += gridDim.x) {
        int m0 = (tl / ntn) * BM, n0 = (tl % ntn) * BN;
        int tp = tcount & 1; tcount++;
        for (int s = 0; s < S; s++, g++) {
            int buf = g & 1;
            if (g >= 2) mbar_wait(smem_base + 8 + buf * 8, ((g - 2) >> 1) & 1);
            stage_load(smem_base, Ah, Al, Bh, Bl, m0, n0, s * BK, K, tid, buf);
            asm volatile("cp.async.commit_group;\n");
            // Overlap previous tile's epilogue with this stage-0 load flight.
            if (s == 0 && havePrev) {
                tc_epilogue<MODE>(smem_base, tmem, ptp, pg, pm0, pn0, wid, lane,
                                  N, C, Ch, Cl, bias, resid);
                havePrev = false;
            }
            asm volatile("cp.async.wait_group 0;\n");
            __syncthreads();
            FENCE_ASYNC();

            if (wid == 0 && elect_one()) {
                TC_FENCE_AFTER();
                uint64_t aH = make_desc(smem_base + AOFF(buf, 0));
                uint64_t aL = make_desc(smem_base + AOFF(buf, 1));
                uint64_t bH = make_desc(smem_base + BOFF(buf, 0));
                uint64_t bL = make_desc(smem_base + BOFF(buf, 1));
                #pragma unroll
                for (int ks = 0; ks < 4; ks++) {
                    #pragma unroll
                    for (int h = 0; h < 2; h++) {
                        uint64_t ah = aH + h * 1024 + ks * 2;
                        uint64_t al = aL + h * 1024 + ks * 2;
                        uint64_t bh = bH + ks * 2;
                        uint64_t bl = bL + ks * 2;
                        uint32_t d = tmem + tp * 256 + h * 128;
                        mma_f16_ss(d, ah, bh, IDESC, !(s == 0 && ks == 0));
                        mma_f16_ss(d, ah, bl, IDESC, true);
                        mma_f16_ss(d, al, bh, IDESC, true);
                    }
                }
                TC_COMMIT(smem_base + 8 + buf * 8);
            }
        }
        pm0 = m0; pn0 = n0; ptp = tp; pg = g - 1; havePrev = true;
    }
    if (havePrev) {
        tc_epilogue<MODE>(smem_base, tmem, ptp, pg, pm0, pn0, wid, lane,
                          N, C, Ch, Cl, bias, resid);
    }
    __syncthreads();
    if (wid == 0) { TC_DEALLOC(tmem, 512); }

#else
    // ======================= mma.sync persistent fallback =======================
    // 8 warps, warp tile 64x64: wm in {0..3}, wn in {0,1}.
    int wm = wid & 3, wn = wid >> 2;
    int arow = wm * 64 + (lane & 15);
    int brow = wn * 64 + (lane & 15);

    for (int tl = blockIdx.x; tl < ntiles; tl += gridDim.x) {
        int m0 = (tl / ntn) * BM, n0 = (tl % ntn) * BN;

        float acc[4][8][4];
        #pragma unroll
        for (int i = 0; i < 4; i++)
            #pragma unroll
            for (int j = 0; j < 8; j++)
                #pragma unroll
                for (int d = 0; d < 4; d++) acc[i][j][d] = 0.0f;

        stage_load(smem_base, Ah, Al, Bh, Bl, m0, n0, 0, K, tid, 0);
        asm volatile("cp.async.commit_group;\n");

        for (int s = 0; s < S; s++) {
            int buf = s & 1;
            if (s + 1 < S) {
                stage_load(smem_base, Ah, Al, Bh, Bl, m0, n0, (s + 1) * BK, K, tid, buf ^ 1);
                asm volatile("cp.async.commit_group;\n");
                asm volatile("cp.async.wait_group 1;\n");
            } else {
                asm volatile("cp.async.wait_group 0;\n");
            }
            __syncthreads();

            uint32_t aHb = smem_base + AOFF(buf, 0);
            uint32_t aLb = smem_base + AOFF(buf, 1);
            uint32_t bHb = smem_base + BOFF(buf, 0);
            uint32_t bLb = smem_base + BOFF(buf, 1);

            #pragma unroll
            for (int ks = 0; ks < 4; ks++) {
                int colb = ks * 32 + (lane >> 4) * 16;
                uint32_t faH[4][4], faL[4][4], fb[4][4];
                #pragma unroll
                for (int mi = 0; mi < 4; mi++) {
                    uint32_t off = (uint32_t)((arow + mi * 16) * 128 + colb);
                    ldmx4u(faH[mi], aHb + SWZ(off));
                }
                #pragma unroll
                for (int mi = 0; mi < 4; mi++) {
                    uint32_t off = (uint32_t)((arow + mi * 16) * 128 + colb);
                    ldmx4u(faL[mi], aLb + SWZ(off));
                }
                #pragma unroll
                for (int ni = 0; ni < 4; ni++) {
                    uint32_t off = (uint32_t)((brow + ni * 16) * 128 + colb);
                    ldmx4u(fb[ni], bHb + SWZ(off));
                }
                // hh
                #pragma unroll
                for (int mi = 0; mi < 4; mi++)
                    #pragma unroll
                    for (int ni = 0; ni < 4; ni++) {
                        mma16816(acc[mi][2 * ni],     faH[mi], fb[ni][0], fb[ni][2]);
                        mma16816(acc[mi][2 * ni + 1], faH[mi], fb[ni][1], fb[ni][3]);
                    }
                // lh (B-hi still resident)
                #pragma unroll
                for (int mi = 0; mi < 4; mi++)
                    #pragma unroll
                    for (int ni = 0; ni < 4; ni++) {
                        mma16816(acc[mi][2 * ni],     faL[mi], fb[ni][0], fb[ni][2]);
                        mma16816(acc[mi][2 * ni + 1], faL[mi], fb[ni][1], fb[ni][3]);
                    }
                // hl (load B-lo into fb, reuse A-hi)
                #pragma unroll
                for (int ni = 0; ni < 4; ni++) {
                    uint32_t off = (uint32_t)((brow + ni * 16) * 128 + colb);
                    ldmx4u(fb[ni], bLb + SWZ(off));
                }
                #pragma unroll
                for (int mi = 0; mi < 4; mi++)
                    #pragma unroll
                    for (int ni = 0; ni < 4; ni++) {
                        mma16816(acc[mi][2 * ni],     faH[mi], fb[ni][0], fb[ni][2]);
                        mma16816(acc[mi][2 * ni + 1], faH[mi], fb[ni][1], fb[ni][3]);
                    }
            }
            __syncthreads();
        }

        // Epilogue
        int r0 = lane >> 2, c0 = (lane & 3) * 2;
        #pragma unroll
        for (int mi = 0; mi < 4; mi++) {
            #pragma unroll
            for (int t = 0; t < 8; t++) {
                int col = n0 + wn * 64 + t * 8 + c0;
                #pragma unroll
                for (int hh = 0; hh < 2; hh++) {
                    int row = m0 + wm * 64 + mi * 16 + r0 + hh * 8;
                    float v0 = acc[mi][t][hh * 2];
                    float v1 = acc[mi][t][hh * 2 + 1];
                    size_t base = (size_t)row * N + col;
                    if (MODE == 2 || MODE == 3) { v0 += bias[col]; v1 += bias[col + 1]; }
                    if (MODE == 2) { v0 = fmaxf(v0, 0.f); v1 = fmaxf(v1, 0.f); }
                    if (MODE == 1 || MODE == 3) {
                        float2 rr = *reinterpret_cast<const float2*>(resid + base);
                        v0 += rr.x; v1 += rr.y;
                    }
                    if (MODE == 2) {
                        bf16 h0, h1, l0, l1;
                        split2(v0, h0, l0); split2(v1, h1, l1);
                        __nv_bfloat162 hp(h0, h1), lp(l0, l1);
                        *reinterpret_cast<uint32_t*>(Ch + base) = *reinterpret_cast<uint32_t*>(&hp);
                        *reinterpret_cast<uint32_t*>(Cl + base) = *reinterpret_cast<uint32_t*>(&lp);
                    } else {
                        float2 o; o.x = v0; o.y = v1;
                        *reinterpret_cast<float2*>(C + base) = o;
                    }
                }
            }
        }
        __syncthreads();
    }
#endif
}

// ---------------------------------------------------------------------------
// Weight transpose + split: w[K,N] fp32 -> out[N,K] bf16 hi/lo
// ---------------------------------------------------------------------------
__global__ __launch_bounds__(256) void tsplit_kernel(
    const float* __restrict__ w, bf16* __restrict__ oh, bf16* __restrict__ ol,
    int K, int N)
{
    __shared__ float t[32][33];
    int k0 = blockIdx.y * 32, n0 = blockIdx.x * 32;
    int tx = threadIdx.x & 31, ty = threadIdx.x >> 5;
    #pragma unroll
    for (int i = 0; i < 4; i++)
        t[ty + 8 * i][tx] = w[(size_t)(k0 + ty + 8 * i) * N + n0 + tx];
    __syncthreads();
    #pragma unroll
    for (int i = 0; i < 4; i++) {
        float v = t[tx][ty + 8 * i];
        bf16 h, l; split2(v, h, l);
        size_t idx = (size_t)(n0 + ty + 8 * i) * K + k0 + tx;
        oh[idx] = h; ol[idx] = l;
    }
}

// ---------------------------------------------------------------------------
// LayerNorm (ddof=1, eps on STD) fused with bf16 split output.
// ---------------------------------------------------------------------------
__global__ __launch_bounds__(256) void ln_split_kernel(
    const float* __restrict__ x, const float* __restrict__ alpha,
    const float* __restrict__ bias, bf16* __restrict__ yh, bf16* __restrict__ yl)
{
    int row = blockIdx.x;
    int t = threadIdx.x;
    float4 v = reinterpret_cast<const float4*>(x + (size_t)row * DM)[t];
    float s  = v.x + v.y + v.z + v.w;
    float ss = v.x*v.x + v.y*v.y + v.z*v.z + v.w*v.w;

    __shared__ float reds[8], redss[8], bcast[2];
    #pragma unroll
    for (int off = 16; off; off >>= 1) {
        s  += __shfl_xor_sync(0xffffffffu, s,  off);
        ss += __shfl_xor_sync(0xffffffffu, ss, off);
    }
    int wid = t >> 5, lid = t & 31;
    if (lid == 0) { reds[wid] = s; redss[wid] = ss; }
    __syncthreads();
    if (t == 0) {
        float S = 0.f, SS = 0.f;
        #pragma unroll
        for (int i = 0; i < 8; i++) { S += reds[i]; SS += redss[i]; }
        float mean = S * (1.0f / DM);
        float var = (SS - (float)DM * mean * mean) * (1.0f / (DM - 1));
        var = fmaxf(var, 0.0f);
        bcast[0] = mean;
        bcast[1] = 1.0f / (sqrtf(var) + 1e-6f);
    }
    __syncthreads();
    float mean = bcast[0], inv = bcast[1];

    float4 av = reinterpret_cast<const float4*>(alpha)[t];
    float4 bv = reinterpret_cast<const float4*>(bias)[t];
    float o0 = av.x * (v.x - mean) * inv + bv.x;
    float o1 = av.y * (v.y - mean) * inv + bv.y;
    float o2 = av.z * (v.z - mean) * inv + bv.z;
    float o3 = av.w * (v.w - mean) * inv + bv.w;
    bf16 h0,h1,h2,h3,l0,l1,l2,l3;
    split2(o0,h0,l0); split2(o1,h1,l1); split2(o2,h2,l2); split2(o3,h3,l3);
    __nv_bfloat162* hp = reinterpret_cast<__nv_bfloat162*>(yh + (size_t)row * DM + t * 4);
    __nv_bfloat162* lp = reinterpret_cast<__nv_bfloat162*>(yl + (size_t)row * DM + t * 4);
    hp[0] = __nv_bfloat162(h0, h1); hp[1] = __nv_bfloat162(h2, h3);
    lp[0] = __nv_bfloat162(l0, l1); lp[1] = __nv_bfloat162(l2, l3);
}

// ---------------------------------------------------------------------------
// KtV partial: per (b,h,chunk of 256 seq rows), Mpart[64,64] = K^T V (fp32).
// ---------------------------------------------------------------------------
__global__ __launch_bounds__(256) void ktv_kernel(
    const float* __restrict__ qkv, float* __restrict__ Mpart)
{
    int bh = blockIdx.x >> 3, cch = blockIdx.x & 7;
    int b = bh >> 4, h = bh & 15;
    const float* Kb = qkv + (size_t)b * SEQ * QKVS + 1024 + h * DK;
    const float* Vb = qkv + (size_t)b * SEQ * QKVS + 2048 + h * DK;

    __shared__ float Ks[64][68];
    __shared__ float Vs[64][68];

    int tid = threadIdx.x;
    int tx = tid & 15, ty = tid >> 4;
    int lr = tid >> 4;
    int lc = (tid & 15) << 2;

    float acc[4][4];
    #pragma unroll
    for (int i = 0; i < 4; i++)
        #pragma unroll
        for (int j = 0; j < 4; j++) acc[i][j] = 0.0f;

    int sbeg = cch * 256;
    for (int s0 = sbeg; s0 < sbeg + 256; s0 += 64) {
        __syncthreads();
        #pragma unroll
        for (int p = 0; p < 4; p++) {
            int r = lr + p * 16;
            *reinterpret_cast<float4*>(&Ks[r][lc]) =
                *reinterpret_cast<const float4*>(Kb + (size_t)(s0 + r) * QKVS + lc);
            *reinterpret_cast<float4*>(&Vs[r][lc]) =
                *reinterpret_cast<const float4*>(Vb + (size_t)(s0 + r) * QKVS + lc);
        }
        __syncthreads();
        #pragma unroll 8
        for (int s = 0; s < 64; s++) {
            float kf[4], vf[4];
            #pragma unroll
            for (int i = 0; i < 4; i++) kf[i] = Ks[s][ty * 4 + i];
            #pragma unroll
            for (int j = 0; j < 4; j++) vf[j] = Vs[s][tx * 4 + j];
            #pragma unroll
            for (int i = 0; i < 4; i++)
                #pragma unroll
                for (int j = 0; j < 4; j++)
                    acc[i][j] = fmaf(kf[i], vf[j], acc[i][j]);
        }
    }

    float* Mb = Mpart + (size_t)blockIdx.x * DK * DK;
    #pragma unroll
    for (int i = 0; i < 4; i++)
        #pragma unroll
        for (int j = 0; j < 4; j++)
            Mb[(ty * 4 + i) * DK + (tx * 4 + j)] = acc[i][j];
}

// ---------------------------------------------------------------------------
// QM: O_bh = (Q_bh @ sum_c Mpart_bh_c) * 0.125, output split bf16 hi/lo.
// ---------------------------------------------------------------------------
__global__ __launch_bounds__(256) void qm_kernel(
    const float* __restrict__ qkv, const float* __restrict__ Mp,
    bf16* __restrict__ Oh, bf16* __restrict__ Ol)
{
    int bh = blockIdx.y;
    int b = bh >> 4, h = bh & 15;
    int rt = blockIdx.x;
    const float* Qb = qkv + (size_t)b * SEQ * QKVS + (size_t)rt * 64 * QKVS + h * DK;
    const float* Mb = Mp + (size_t)bh * 8 * DK * DK;
    size_t obase = (size_t)b * SEQ * DM + (size_t)rt * 64 * DM + h * DK;

    __shared__ float Qs[64][68];
    __shared__ float Ms[64][68];

    int tid = threadIdx.x;
    int tx = tid & 15, ty = tid >> 4;
    int lr = tid >> 4;
    int lc = (tid & 15) << 2;

    #pragma unroll
    for (int p = 0; p < 4; p++) {
        int r = lr + p * 16;
        *reinterpret_cast<float4*>(&Qs[r][lc]) =
            *reinterpret_cast<const float4*>(Qb + (size_t)r * QKVS + lc);
        float4 a = make_float4(0.f, 0.f, 0.f, 0.f);
        #pragma unroll
        for (int cc = 0; cc < 8; cc++) {
            float4 t4 = *reinterpret_cast<const float4*>(Mb + (size_t)cc * DK * DK + (size_t)r * DK + lc);
            a.x += t4.x; a.y += t4.y; a.z += t4.z; a.w += t4.w;
        }
        *reinterpret_cast<float4*>(&Ms[r][lc]) = a;
    }
    __syncthreads();

    float acc[4][4];
    #pragma unroll
    for (int i = 0; i < 4; i++)
        #pragma unroll
        for (int j = 0; j < 4; j++) acc[i][j] = 0.0f;

    #pragma unroll 8
    for (int k = 0; k < 64; k++) {
        float qf[4], mf[4];
        #pragma unroll
        for (int i = 0; i < 4; i++) qf[i] = Qs[ty * 4 + i][k];
        #pragma unroll
        for (int j = 0; j < 4; j++) mf[j] = Ms[k][tx * 4 + j];
        #pragma unroll
        for (int i = 0; i < 4; i++)
            #pragma unroll
            for (int j = 0; j < 4; j++)
                acc[i][j] = fmaf(qf[i], mf[j], acc[i][j]);
    }

    #pragma unroll
    for (int i = 0; i < 4; i++) {
        float v0 = acc[i][0] * 0.125f, v1 = acc[i][1] * 0.125f;
        float v2 = acc[i][2] * 0.125f, v3 = acc[i][3] * 0.125f;
        bf16 h0,h1,h2,h3,l0,l1,l2,l3;
        split2(v0,h0,l0); split2(v1,h1,l1); split2(v2,h2,l2); split2(v3,h3,l3);
        size_t off = obase + (size_t)(ty * 4 + i) * DM + tx * 4;
        __nv_bfloat162* hp = reinterpret_cast<__nv_bfloat162*>(Oh + off);
        __nv_bfloat162* lp = reinterpret_cast<__nv_bfloat162*>(Ol + off);
        hp[0] = __nv_bfloat162(h0, h1); hp[1] = __nv_bfloat162(h2, h3);
        lp[0] = __nv_bfloat162(l0, l1); lp[1] = __nv_bfloat162(l2, l3);
    }
}

// ---------------------------------------------------------------------------
// Launch
// ---------------------------------------------------------------------------
extern "C" void kernel_launch(void* const* d_in, const int* in_sizes, int n_in,
                              void* d_out, int out_size)
{
    const float* x    = (const float*)d_in[0];
    const float* wq   = (const float*)d_in[2];
    const float* wk   = (const float*)d_in[3];
    const float* wv   = (const float*)d_in[4];
    const float* wo   = (const float*)d_in[5];
    const float* w1   = (const float*)d_in[6];
    const float* b1   = (const float*)d_in[7];
    const float* w2   = (const float*)d_in[8];
    const float* b2   = (const float*)d_in[9];
    const float* ln1a = (const float*)d_in[10];
    const float* ln1b = (const float*)d_in[11];
    const float* ln2a = (const float*)d_in[12];
    const float* ln2b = (const float*)d_in[13];
    float* out = (float*)d_out;

    bf16 *xn1h,*xn1l,*xn2h,*xn2l,*oh,*ol,*h1h,*h1l;
    bf16 *wqkvTh,*wqkvTl,*woTh,*woTl,*w1Th,*w1Tl,*w2Th,*w2Tl;
    float *qkv,*x1,*mpart;
    cudaGetSymbolAddress((void**)&xn1h, g_xn1h); cudaGetSymbolAddress((void**)&xn1l, g_xn1l);
    cudaGetSymbolAddress((void**)&xn2h, g_xn2h); cudaGetSymbolAddress((void**)&xn2l, g_xn2l);
    cudaGetSymbolAddress((void**)&oh,   g_oh);   cudaGetSymbolAddress((void**)&ol,   g_ol);
    cudaGetSymbolAddress((void**)&h1h,  g_h1h);  cudaGetSymbolAddress((void**)&h1l,  g_h1l);
    cudaGetSymbolAddress((void**)&qkv,  g_qkv);  cudaGetSymbolAddress((void**)&x1,   g_x1);
    cudaGetSymbolAddress((void**)&mpart,g_mpart);
    cudaGetSymbolAddress((void**)&wqkvTh, g_wqkvTh); cudaGetSymbolAddress((void**)&wqkvTl, g_wqkvTl);
    cudaGetSymbolAddress((void**)&woTh, g_woTh); cudaGetSymbolAddress((void**)&woTl, g_woTl);
    cudaGetSymbolAddress((void**)&w1Th, g_w1Th); cudaGetSymbolAddress((void**)&w1Tl, g_w1Tl);
    cudaGetSymbolAddress((void**)&w2Th, g_w2Th); cudaGetSymbolAddress((void**)&w2Tl, g_w2Tl);

    cudaFuncSetAttribute(gemm_tc<0>, cudaFuncAttributeMaxDynamicSharedMemorySize, SMEM_TOTAL);
    cudaFuncSetAttribute(gemm_tc<1>, cudaFuncAttributeMaxDynamicSharedMemorySize, SMEM_TOTAL);
    cudaFuncSetAttribute(gemm_tc<2>, cudaFuncAttributeMaxDynamicSharedMemorySize, SMEM_TOTAL);
    cudaFuncSetAttribute(gemm_tc<3>, cudaFuncAttributeMaxDynamicSharedMemorySize, SMEM_TOTAL);

    int nsm = 148;
    cudaDeviceGetAttribute(&nsm, cudaDevAttrMultiProcessorCount, 0);

    // Transpose + split weights into [N, K] bf16 hi/lo.
    tsplit_kernel<<<dim3(DM / 32, DM / 32), 256>>>(wq, wqkvTh,             wqkvTl,             DM, DM);
    tsplit_kernel<<<dim3(DM / 32, DM / 32), 256>>>(wk, wqkvTh + 1024 * DM, wqkvTl + 1024 * DM, DM, DM);
    tsplit_kernel<<<dim3(DM / 32, DM / 32), 256>>>(wv, wqkvTh + 2048 * DM, wqkvTl + 2048 * DM, DM, DM);
    tsplit_kernel<<<dim3(DM / 32, DM / 32), 256>>>(wo, woTh, woTl, DM, DM);
    tsplit_kernel<<<dim3(DFF / 32, DM / 32), 256>>>(w1, w1Th, w1Tl, DM, DFF);
    tsplit_kernel<<<dim3(DM / 32, DFF / 32), 256>>>(w2, w2Th, w2Tl, DFF, DM);

    int tQKV = (NTOK / BM) * (QKVN / BN);   // 768
    int tDM  = (NTOK / BM) * (DM / BN);     // 256
    int tFF  = (NTOK / BM) * (DFF / BN);    // 1024
    int gQKV = tQKV < nsm ? tQKV : nsm;
    int gDM  = tDM  < nsm ? tDM  : nsm;
    int gFF  = tFF  < nsm ? tFF  : nsm;

    // 1) xn1 = LN(x) -> split bf16
    ln_split_kernel<<<NTOK, 256>>>(x, ln1a, ln1b, xn1h, xn1l);
    // 2) fused QKV projection: qkv[M, 3072]
    gemm_tc<0><<<gQKV, 256, SMEM_TOTAL>>>(
        xn1h, xn1l, wqkvTh, wqkvTl, qkv, nullptr, nullptr, QKVN, DM, tQKV, nullptr, nullptr);
    // 3) M = K^T V partials (linear attention; no softmax in reference)
    ktv_kernel<<<BATCH * NH * 8, 256>>>(qkv, mpart);
    // 4) O = Q @ M / 8 -> split bf16
    qm_kernel<<<dim3(SEQ / 64, BATCH * NH), 256>>>(qkv, mpart, oh, ol);
    // 5) x1 = x + O @ wo
    gemm_tc<1><<<gDM, 256, SMEM_TOTAL>>>(
        oh, ol, woTh, woTl, x1, nullptr, nullptr, DM, DM, tDM, nullptr, x);
    // 6) xn2 = LN(x1) -> split bf16
    ln_split_kernel<<<NTOK, 256>>>(x1, ln2a, ln2b, xn2h, xn2l);
    // 7) h1 = relu(xn2 @ w1 + b1) -> split bf16
    gemm_tc<2><<<gFF, 256, SMEM_TOTAL>>>(
        xn2h, xn2l, w1Th, w1Tl, nullptr, h1h, h1l, DFF, DM, tFF, b1, nullptr);
    // 8) out = x1 + h1 @ w2 + b2
    gemm_tc<3><<<gDM, 256, SMEM_TOTAL>>>(
        h1h, h1l, w2Th, w2Tl, out, nullptr, nullptr, DM, DFF, tDM, b2, x1);
}

// round 8
// speedup vs baseline: 1.1905x; 1.1905x over previous
#include <cuda_runtime.h>
#include <cuda_fp16.h>
#include <math.h>
#include <stdint.h>

typedef __half half_t;

// Problem constants
#define DM    1024
#define DFF   4096
#define NTOK  8192
#define SEQ   2048
#define BATCH 4
#define NH    16
#define DK    64
#define QKVN  3072
#define QKVS  3072

// GEMM tiling
#define BM 256
#define BN 128
#define BK 64
#define SMEM_TOTAL 197632
#define SWZ(x) ((x) ^ (((x) >> 3) & 0x70))

// SMEM slot offsets.
// ASPLIT=1 (2-stage): A(hi,lo) 4 slots of 32KB at 1024; B(hi,lo) 4 slots of 16KB at 132096.
// ASPLIT=0 (3-stage): A 3 slots of 32KB at 1024;        B(hi,lo) 6 slots of 16KB at 99328.
template<bool ASPLIT>
__device__ __forceinline__ uint32_t AOFFS(int buf, int t) {
    return ASPLIT ? (1024u + (uint32_t)(buf * 2 + t) * 32768u)
                  : (1024u + (uint32_t)buf * 32768u);
}
template<bool ASPLIT>
__device__ __forceinline__ uint32_t BOFFS(int buf, int t) {
    return ASPLIT ? (132096u + (uint32_t)(buf * 2 + t) * 16384u)
                  : (99328u  + (uint32_t)(buf * 2 + t) * 16384u);
}

// ---------------------------------------------------------------------------
// Scratch (device globals)
// ---------------------------------------------------------------------------
__device__ half_t g_xn1h[NTOK * DM], g_xn1l[NTOK * DM];
__device__ half_t g_xn2h[NTOK * DM];
__device__ half_t g_oh  [NTOK * DM];
__device__ half_t g_h1h [NTOK * DFF];
__device__ float  g_qkv [NTOK * QKVS];
__device__ float  g_x1  [NTOK * DM];
__device__ float  g_mpart[BATCH * NH * 8 * DK * DK];
__device__ half_t g_wqkvTh[QKVN * DM], g_wqkvTl[QKVN * DM];
__device__ half_t g_woTh[DM * DM],   g_woTl[DM * DM];
__device__ half_t g_w1Th[DFF * DM],  g_w1Tl[DFF * DM];
__device__ half_t g_w2Th[DM * DFF],  g_w2Tl[DM * DFF];

// ---------------------------------------------------------------------------
// Helpers
// ---------------------------------------------------------------------------
__device__ __forceinline__ uint32_t smem_u32(const void* p) {
    return (uint32_t)__cvta_generic_to_shared(p);
}
__device__ __forceinline__ void cp16(uint32_t dst, const void* src) {
    asm volatile("cp.async.cg.shared.global [%0], [%1], 16;\n" :: "r"(dst), "l"(src));
}
__device__ __forceinline__ void split2h(float v, half_t& h, half_t& l) {
    h = __float2half_rn(v);
    l = __float2half_rn(v - __half2float(h));
}
__device__ __forceinline__ void ldmx4u(uint32_t* r, uint32_t addr) {
    asm volatile("ldmatrix.sync.aligned.m8n8.x4.shared.b16 {%0,%1,%2,%3}, [%4];\n"
                 : "=r"(r[0]), "=r"(r[1]), "=r"(r[2]), "=r"(r[3]) : "r"(addr));
}
__device__ __forceinline__ void mma16816h(float* d, const uint32_t* a, uint32_t b0, uint32_t b1) {
    asm volatile(
        "mma.sync.aligned.m16n8k16.row.col.f32.f16.f16.f32 "
        "{%0,%1,%2,%3},{%4,%5,%6,%7},{%8,%9},{%0,%1,%2,%3};\n"
        : "+f"(d[0]), "+f"(d[1]), "+f"(d[2]), "+f"(d[3])
        : "r"(a[0]), "r"(a[1]), "r"(a[2]), "r"(a[3]), "r"(b0), "r"(b1));
}

// ---------------------------------------------------------------------------
// Stage loader: A 256x64 (hi [,lo]) + B(hi,lo) 128x64 fp16, SW128, cp.async.
// ---------------------------------------------------------------------------
template<bool ASPLIT>
__device__ __forceinline__ void stage_load(
    uint32_t smem_base,
    const half_t* __restrict__ Ah, const half_t* __restrict__ Al,
    const half_t* __restrict__ Bh, const half_t* __restrict__ Bl,
    int m0, int n0, int k0, int K, int tid, int buf)
{
    #pragma unroll
    for (int t = 0; t < (ASPLIT ? 2 : 1); t++) {
        const half_t* src = t ? Al : Ah;
        uint32_t base = smem_base + AOFFS<ASPLIT>(buf, t);
        #pragma unroll
        for (int i = 0; i < 8; i++) {
            int chunk = tid + i * 256;
            int r = chunk >> 3, c = chunk & 7;
            uint32_t off = (uint32_t)(r * 128 + c * 16);
            cp16(base + SWZ(off), src + (size_t)(m0 + r) * K + k0 + c * 8);
        }
    }
    #pragma unroll
    for (int t = 0; t < 2; t++) {
        const half_t* src = t ? Bl : Bh;
        uint32_t base = smem_base + BOFFS<ASPLIT>(buf, t);
        #pragma unroll
        for (int i = 0; i < 4; i++) {
            int chunk = tid + i * 256;
            int r = chunk >> 3, c = chunk & 7;
            uint32_t off = (uint32_t)(r * 128 + c * 16);
            cp16(base + SWZ(off), src + (size_t)(n0 + r) * K + k0 + c * 8);
        }
    }
}

// ===========================================================================
// tcgen05-only helpers (compiled only when an 'a' feature target exists)
// ===========================================================================
#if defined(__CUDA_ARCH_FEAT_SM103_ALL) || defined(__CUDA_ARCH_FEAT_SM100_ALL)
#define IDESC_F16 ((1u << 4) | (16u << 17) | (8u << 24))
__device__ __forceinline__ uint32_t elect_one() {
    uint32_t pred;
    asm volatile("{\n .reg .pred p;\n elect.sync _|p, 0xFFFFFFFF;\n selp.b32 %0, 1, 0, p;\n}"
                 : "=r"(pred));
    return pred;
}
__device__ __forceinline__ uint64_t make_desc(uint32_t addr) {
    return ((uint64_t)2 << 61) | ((uint64_t)1 << 46) | ((uint64_t)64 << 32) |
           ((uint64_t)1 << 16) | ((uint64_t)(addr >> 4) & 0x3FFF);
}
__device__ __forceinline__ void mma_f16_ss(uint32_t d, uint64_t a, uint64_t b,
                                           uint32_t idesc, bool en) {
    uint32_t e = en ? 1u : 0u;
    asm volatile(
        "{\n\t"
        ".reg .pred p;\n\t"
        "setp.ne.u32 p, %4, 0;\n\t"
        "tcgen05.mma.cta_group::1.kind::f16 [%0], %1, %2, %3, {%5,%5,%5,%5}, p;\n\t"
        "}"
        :: "r"(d), "l"(a), "l"(b), "r"(idesc), "r"(e), "r"(0u) : "memory");
}
__device__ __forceinline__ void mbar_init(uint32_t a, uint32_t c) {
    asm volatile("mbarrier.init.shared.b64 [%0], %1;" :: "r"(a), "r"(c) : "memory");
}
__device__ __forceinline__ void mbar_wait(uint32_t mbar, uint32_t parity) {
    asm volatile(
        "{\n\t"
        ".reg .pred P1;\n\t"
        "WAIT_LOOP_%=:\n\t"
        "mbarrier.try_wait.parity.acquire.cta.shared::cta.b64 P1, [%0], %1, 0x989680;\n\t"
        "@P1 bra.uni WAIT_DONE_%=;\n\t"
        "bra.uni WAIT_LOOP_%=;\n\t"
        "WAIT_DONE_%=:\n\t"
        "}" :: "r"(mbar), "r"(parity) : "memory");
}
#define TC_ALLOC(sm, n)  asm volatile("tcgen05.alloc.cta_group::1.sync.aligned.shared::cta.b32 [%0], %1;" :: "r"(sm), "r"((uint32_t)(n)) : "memory")
#define TC_RELINQ()      asm volatile("tcgen05.relinquish_alloc_permit.cta_group::1.sync.aligned;")
#define TC_DEALLOC(t, n) asm volatile("tcgen05.dealloc.cta_group::1.sync.aligned.b32 %0, %1;" :: "r"(t), "r"((uint32_t)(n)))
#define TC_COMMIT(mb)    asm volatile("tcgen05.commit.cta_group::1.mbarrier::arrive::one.shared::cluster.b64 [%0];" :: "r"(mb) : "memory")
#define TC_FENCE_AFTER() asm volatile("tcgen05.fence::after_thread_sync;" ::: "memory")
#define TC_FENCE_BEFORE() asm volatile("tcgen05.fence::before_thread_sync;" ::: "memory")
#define TC_WAIT_LD()     asm volatile("tcgen05.wait::ld.sync.aligned;" ::: "memory")
#define FENCE_ASYNC()    asm volatile("fence.proxy.async.shared::cta;" ::: "memory")
#define TC_LD_X32(r, ta) \
    asm volatile( \
        "tcgen05.ld.sync.aligned.32x32b.x32.b32 " \
        "{%0, %1, %2, %3, %4, %5, %6, %7, " \
        " %8, %9, %10, %11, %12, %13, %14, %15, " \
        " %16, %17, %18, %19, %20, %21, %22, %23, " \
        " %24, %25, %26, %27, %28, %29, %30, %31}, [%32];" \
        : "=r"((r)[0]),  "=r"((r)[1]),  "=r"((r)[2]),  "=r"((r)[3]), \
          "=r"((r)[4]),  "=r"((r)[5]),  "=r"((r)[6]),  "=r"((r)[7]), \
          "=r"((r)[8]),  "=r"((r)[9]),  "=r"((r)[10]), "=r"((r)[11]), \
          "=r"((r)[12]), "=r"((r)[13]), "=r"((r)[14]), "=r"((r)[15]), \
          "=r"((r)[16]), "=r"((r)[17]), "=r"((r)[18]), "=r"((r)[19]), \
          "=r"((r)[20]), "=r"((r)[21]), "=r"((r)[22]), "=r"((r)[23]), \
          "=r"((r)[24]), "=r"((r)[25]), "=r"((r)[26]), "=r"((r)[27]), \
          "=r"((r)[28]), "=r"((r)[29]), "=r"((r)[30]), "=r"((r)[31]) \
        : "r"(ta))
#endif

// ---------------------------------------------------------------------------
// Persistent GEMM, 256x128 tiles, fp16.
//   ASPLIT=1: D = ah*bh + al*bh + ah*bl  (3 MMA, 2-stage ring)
//   ASPLIT=0: D = a*bh + a*bl            (2 MMA, 3-stage ring)
// MODE: 0=plain fp32, 1=+resid fp32, 2=relu(D+bias)->fp16, 3=D+bias+resid fp32.
// ---------------------------------------------------------------------------
template<int MODE, bool ASPLIT>
__global__ __launch_bounds__(256)
void gemm_tc(
    const half_t* __restrict__ Ah, const half_t* __restrict__ Al,
    const half_t* __restrict__ Bh, const half_t* __restrict__ Bl,
    float* __restrict__ C, half_t* __restrict__ Ch,
    int N, int K, int ntiles,
    const float* __restrict__ bias, const float* __restrict__ resid)
{
    extern __shared__ char smem[];
    uint32_t smem_base = smem_u32(smem);
    int tid = threadIdx.x;
    int wid = tid >> 5, lane = tid & 31;
    int ntn = N / BN;
    int S = K / BK;
    constexpr int NSTAGE = ASPLIT ? 2 : 3;

#if defined(__CUDA_ARCH_FEAT_SM103_ALL) || defined(__CUDA_ARCH_FEAT_SM100_ALL)
    // ======================= tcgen05 path (2-buffer) =======================
    if (wid == 0) { TC_ALLOC(smem_base, 512); }
    else if (wid == 1) { TC_RELINQ(); }
    if (tid == 0) { mbar_init(smem_base + 8, 1); mbar_init(smem_base + 16, 1); }
    __syncthreads();
    uint32_t tmem;
    asm volatile("ld.shared.b32 %0, [%1];" : "=r"(tmem) : "r"(smem_base));

    int g = 0, tcount = 0;
    for (int tl = blockIdx.x; tl < ntiles; tl += gridDim.x) {
        int m0 = (tl / ntn) * BM, n0 = (tl % ntn) * BN;
        int tp = tcount & 1; tcount++;
        for (int s = 0; s < S; s++, g++) {
            int buf = g & 1;
            if (g >= 2) mbar_wait(smem_base + 8 + buf * 8, ((g - 2) >> 1) & 1);
            stage_load<ASPLIT>(smem_base, Ah, Al, Bh, Bl, m0, n0, s * BK, K, tid, buf);
            asm volatile("cp.async.commit_group;\n");
            asm volatile("cp.async.wait_group 0;\n");
            __syncthreads();
            FENCE_ASYNC();
            if (wid == 0 && elect_one()) {
                TC_FENCE_AFTER();
                uint64_t aH = make_desc(smem_base + AOFFS<ASPLIT>(buf, 0));
                uint64_t bH = make_desc(smem_base + BOFFS<ASPLIT>(buf, 0));
                uint64_t bL = make_desc(smem_base + BOFFS<ASPLIT>(buf, 1));
                #pragma unroll
                for (int ks = 0; ks < 4; ks++) {
                    #pragma unroll
                    for (int h = 0; h < 2; h++) {
                        uint64_t ah = aH + h * 1024 + ks * 2;
                        uint32_t d = tmem + tp * 256 + h * 128;
                        mma_f16_ss(d, ah, bH + ks * 2, IDESC_F16, !(s == 0 && ks == 0));
                        mma_f16_ss(d, ah, bL + ks * 2, IDESC_F16, true);
                        if (ASPLIT) {
                            uint64_t al = make_desc(smem_base + AOFFS<ASPLIT>(buf, 1)) + h * 1024 + ks * 2;
                            mma_f16_ss(d, al, bH + ks * 2, IDESC_F16, true);
                        }
                    }
                }
                TC_COMMIT(smem_base + 8 + buf * 8);
            }
        }
        {
            int buf = (g - 1) & 1;
            mbar_wait(smem_base + 8 + buf * 8, ((g - 1) >> 1) & 1);
        }
        TC_FENCE_AFTER();
        int half0 = wid >> 2;
        int grow = m0 + half0 * 128 + ((wid & 3) << 5) + lane;
        #pragma unroll
        for (int cb = 0; cb < 4; cb++) {
            uint32_t r[32];
            TC_LD_X32(r, tmem + tp * 256 + half0 * 128 + cb * 32);
            TC_WAIT_LD();
            int gcol = n0 + cb * 32;
            size_t base = (size_t)grow * N + gcol;
            #pragma unroll
            for (int j = 0; j < 32; j += 4) {
                float v0 = __uint_as_float(r[j]);
                float v1 = __uint_as_float(r[j + 1]);
                float v2 = __uint_as_float(r[j + 2]);
                float v3 = __uint_as_float(r[j + 3]);
                if (MODE == 2 || MODE == 3) {
                    float4 bb = *reinterpret_cast<const float4*>(bias + gcol + j);
                    v0 += bb.x; v1 += bb.y; v2 += bb.z; v3 += bb.w;
                }
                if (MODE == 2) {
                    v0 = fmaxf(v0, 0.f); v1 = fmaxf(v1, 0.f);
                    v2 = fmaxf(v2, 0.f); v3 = fmaxf(v3, 0.f);
                }
                if (MODE == 1 || MODE == 3) {
                    float4 rr = *reinterpret_cast<const float4*>(resid + base + j);
                    v0 += rr.x; v1 += rr.y; v2 += rr.z; v3 += rr.w;
                }
                if (MODE == 2) {
                    __half2 p0 = __floats2half2_rn(v0, v1);
                    __half2 p1 = __floats2half2_rn(v2, v3);
                    uint2 u;
                    u.x = *reinterpret_cast<uint32_t*>(&p0);
                    u.y = *reinterpret_cast<uint32_t*>(&p1);
                    *reinterpret_cast<uint2*>(Ch + base + j) = u;
                } else {
                    float4 o; o.x = v0; o.y = v1; o.z = v2; o.w = v3;
                    *reinterpret_cast<float4*>(C + base + j) = o;
                }
            }
        }
        TC_FENCE_BEFORE();
        __syncthreads();
    }
    __syncthreads();
    if (wid == 0) { TC_DEALLOC(tmem, 512); }

#else
    // ======================= mma.sync path =======================
    int wm = wid & 3, wn = wid >> 2;
    int arow = wm * 64 + (lane & 15);
    int brow = wn * 64 + (lane & 15);

    for (int tl = blockIdx.x; tl < ntiles; tl += gridDim.x) {
        int m0 = (tl / ntn) * BM, n0 = (tl % ntn) * BN;

        float acc[4][8][4];
        #pragma unroll
        for (int i = 0; i < 4; i++)
            #pragma unroll
            for (int j = 0; j < 8; j++)
                #pragma unroll
                for (int d = 0; d < 4; d++) acc[i][j][d] = 0.0f;

        #pragma unroll
        for (int p = 0; p < NSTAGE - 1; p++) {
            stage_load<ASPLIT>(smem_base, Ah, Al, Bh, Bl, m0, n0, p * BK, K, tid, p);
            asm volatile("cp.async.commit_group;\n");
        }

        for (int s = 0; s < S; s++) {
            if (s + NSTAGE - 1 <= S) {
                asm volatile("cp.async.wait_group %0;\n" :: "n"(NSTAGE - 2));
            } else {
                asm volatile("cp.async.wait_group 0;\n");
            }
            __syncthreads();
            if (s + NSTAGE - 1 < S) {
                stage_load<ASPLIT>(smem_base, Ah, Al, Bh, Bl, m0, n0,
                                   (s + NSTAGE - 1) * BK, K, tid, (s + NSTAGE - 1) % NSTAGE);
                asm volatile("cp.async.commit_group;\n");
            }
            int buf = s % NSTAGE;
            uint32_t aHb = smem_base + AOFFS<ASPLIT>(buf, 0);
            uint32_t bHb = smem_base + BOFFS<ASPLIT>(buf, 0);
            uint32_t bLb = smem_base + BOFFS<ASPLIT>(buf, 1);

            #pragma unroll
            for (int ks = 0; ks < 4; ks++) {
                int colb = ks * 32 + (lane >> 4) * 16;
                uint32_t fa[4][4], fbH[4][4], fbL[4][4];
                #pragma unroll
                for (int mi = 0; mi < 4; mi++) {
                    uint32_t off = (uint32_t)((arow + mi * 16) * 128 + colb);
                    ldmx4u(fa[mi], aHb + SWZ(off));
                }
                #pragma unroll
                for (int ni = 0; ni < 4; ni++) {
                    uint32_t off = (uint32_t)((brow + ni * 16) * 128 + colb);
                    ldmx4u(fbH[ni], bHb + SWZ(off));
                }
                #pragma unroll
                for (int ni = 0; ni < 4; ni++) {
                    uint32_t off = (uint32_t)((brow + ni * 16) * 128 + colb);
                    ldmx4u(fbL[ni], bLb + SWZ(off));
                }
                // a(hi) * b_hi
                #pragma unroll
                for (int mi = 0; mi < 4; mi++)
                    #pragma unroll
                    for (int ni = 0; ni < 4; ni++) {
                        mma16816h(acc[mi][2 * ni],     fa[mi], fbH[ni][0], fbH[ni][2]);
                        mma16816h(acc[mi][2 * ni + 1], fa[mi], fbH[ni][1], fbH[ni][3]);
                    }
                // a(hi) * b_lo
                #pragma unroll
                for (int mi = 0; mi < 4; mi++)
                    #pragma unroll
                    for (int ni = 0; ni < 4; ni++) {
                        mma16816h(acc[mi][2 * ni],     fa[mi], fbL[ni][0], fbL[ni][2]);
                        mma16816h(acc[mi][2 * ni + 1], fa[mi], fbL[ni][1], fbL[ni][3]);
                    }
                if (ASPLIT) {
                    // a_lo * b_hi  (reuse fa for A-lo)
                    uint32_t aLb = smem_base + AOFFS<ASPLIT>(buf, 1);
                    #pragma unroll
                    for (int mi = 0; mi < 4; mi++) {
                        uint32_t off = (uint32_t)((arow + mi * 16) * 128 + colb);
                        ldmx4u(fa[mi], aLb + SWZ(off));
                    }
                    #pragma unroll
                    for (int mi = 0; mi < 4; mi++)
                        #pragma unroll
                        for (int ni = 0; ni < 4; ni++) {
                            mma16816h(acc[mi][2 * ni],     fa[mi], fbH[ni][0], fbH[ni][2]);
                            mma16816h(acc[mi][2 * ni + 1], fa[mi], fbH[ni][1], fbH[ni][3]);
                        }
                }
            }
        }

        // Epilogue
        int r0 = lane >> 2, c0 = (lane & 3) * 2;
        #pragma unroll
        for (int mi = 0; mi < 4; mi++) {
            #pragma unroll
            for (int t = 0; t < 8; t++) {
                int col = n0 + wn * 64 + t * 8 + c0;
                #pragma unroll
                for (int hh = 0; hh < 2; hh++) {
                    int row = m0 + wm * 64 + mi * 16 + r0 + hh * 8;
                    float v0 = acc[mi][t][hh * 2];
                    float v1 = acc[mi][t][hh * 2 + 1];
                    size_t base = (size_t)row * N + col;
                    if (MODE == 2 || MODE == 3) { v0 += bias[col]; v1 += bias[col + 1]; }
                    if (MODE == 2) { v0 = fmaxf(v0, 0.f); v1 = fmaxf(v1, 0.f); }
                    if (MODE == 1 || MODE == 3) {
                        float2 rr = *reinterpret_cast<const float2*>(resid + base);
                        v0 += rr.x; v1 += rr.y;
                    }
                    if (MODE == 2) {
                        __half2 hp = __floats2half2_rn(v0, v1);
                        *reinterpret_cast<uint32_t*>(Ch + base) = *reinterpret_cast<uint32_t*>(&hp);
                    } else {
                        float2 o; o.x = v0; o.y = v1;
                        *reinterpret_cast<float2*>(C + base) = o;
                    }
                }
            }
        }
        __syncthreads();
    }
#endif
}

// ---------------------------------------------------------------------------
// Weight transpose + split: w[K,N] fp32 -> out[N,K] fp16 hi/lo
// ---------------------------------------------------------------------------
__global__ __launch_bounds__(256) void tsplit_kernel(
    const float* __restrict__ w, half_t* __restrict__ oh, half_t* __restrict__ ol,
    int K, int N)
{
    __shared__ float t[32][33];
    int k0 = blockIdx.y * 32, n0 = blockIdx.x * 32;
    int tx = threadIdx.x & 31, ty = threadIdx.x >> 5;
    #pragma unroll
    for (int i = 0; i < 4; i++)
        t[ty + 8 * i][tx] = w[(size_t)(k0 + ty + 8 * i) * N + n0 + tx];
    __syncthreads();
    #pragma unroll
    for (int i = 0; i < 4; i++) {
        float v = t[tx][ty + 8 * i];
        half_t h, l; split2h(v, h, l);
        size_t idx = (size_t)(n0 + ty + 8 * i) * K + k0 + tx;
        oh[idx] = h; ol[idx] = l;
    }
}

// ---------------------------------------------------------------------------
// LayerNorm (ddof=1, eps on STD), fp16 output (hi [,lo]).
// ---------------------------------------------------------------------------
template<bool LO>
__global__ __launch_bounds__(256) void ln_kernel(
    const float* __restrict__ x, const float* __restrict__ alpha,
    const float* __restrict__ bias, half_t* __restrict__ yh, half_t* __restrict__ yl)
{
    int row = blockIdx.x;
    int t = threadIdx.x;
    float4 v = reinterpret_cast<const float4*>(x + (size_t)row * DM)[t];
    float s  = v.x + v.y + v.z + v.w;
    float ss = v.x*v.x + v.y*v.y + v.z*v.z + v.w*v.w;

    __shared__ float reds[8], redss[8], bcast[2];
    #pragma unroll
    for (int off = 16; off; off >>= 1) {
        s  += __shfl_xor_sync(0xffffffffu, s,  off);
        ss += __shfl_xor_sync(0xffffffffu, ss, off);
    }
    int wid = t >> 5, lid = t & 31;
    if (lid == 0) { reds[wid] = s; redss[wid] = ss; }
    __syncthreads();
    if (t == 0) {
        float S = 0.f, SS = 0.f;
        #pragma unroll
        for (int i = 0; i < 8; i++) { S += reds[i]; SS += redss[i]; }
        float mean = S * (1.0f / DM);
        float var = (SS - (float)DM * mean * mean) * (1.0f / (DM - 1));
        var = fmaxf(var, 0.0f);
        bcast[0] = mean;
        bcast[1] = 1.0f / (sqrtf(var) + 1e-6f);
    }
    __syncthreads();
    float mean = bcast[0], inv = bcast[1];

    float4 av = reinterpret_cast<const float4*>(alpha)[t];
    float4 bv = reinterpret_cast<const float4*>(bias)[t];
    float o0 = av.x * (v.x - mean) * inv + bv.x;
    float o1 = av.y * (v.y - mean) * inv + bv.y;
    float o2 = av.z * (v.z - mean) * inv + bv.z;
    float o3 = av.w * (v.w - mean) * inv + bv.w;
    half_t h0,h1,h2,h3,l0,l1,l2,l3;
    split2h(o0,h0,l0); split2h(o1,h1,l1); split2h(o2,h2,l2); split2h(o3,h3,l3);
    {
        __half2 p0(h0, h1), p1(h2, h3);
        uint2 u;
        u.x = *reinterpret_cast<uint32_t*>(&p0);
        u.y = *reinterpret_cast<uint32_t*>(&p1);
        *reinterpret_cast<uint2*>(yh + (size_t)row * DM + t * 4) = u;
    }
    if (LO) {
        __half2 p0(l0, l1), p1(l2, l3);
        uint2 u;
        u.x = *reinterpret_cast<uint32_t*>(&p0);
        u.y = *reinterpret_cast<uint32_t*>(&p1);
        *reinterpret_cast<uint2*>(yl + (size_t)row * DM + t * 4) = u;
    }
}

// ---------------------------------------------------------------------------
// KtV partial: per (b,h,chunk of 256 seq rows), Mpart[64,64] = K^T V (fp32).
// ---------------------------------------------------------------------------
__global__ __launch_bounds__(256) void ktv_kernel(
    const float* __restrict__ qkv, float* __restrict__ Mpart)
{
    int bh = blockIdx.x >> 3, cch = blockIdx.x & 7;
    int b = bh >> 4, h = bh & 15;
    const float* Kb = qkv + (size_t)b * SEQ * QKVS + 1024 + h * DK;
    const float* Vb = qkv + (size_t)b * SEQ * QKVS + 2048 + h * DK;

    __shared__ float Ks[64][68];
    __shared__ float Vs[64][68];

    int tid = threadIdx.x;
    int tx = tid & 15, ty = tid >> 4;
    int lr = tid >> 4;
    int lc = (tid & 15) << 2;

    float acc[4][4];
    #pragma unroll
    for (int i = 0; i < 4; i++)
        #pragma unroll
        for (int j = 0; j < 4; j++) acc[i][j] = 0.0f;

    int sbeg = cch * 256;
    for (int s0 = sbeg; s0 < sbeg + 256; s0 += 64) {
        __syncthreads();
        #pragma unroll
        for (int p = 0; p < 4; p++) {
            int r = lr + p * 16;
            *reinterpret_cast<float4*>(&Ks[r][lc]) =
                *reinterpret_cast<const float4*>(Kb + (size_t)(s0 + r) * QKVS + lc);
            *reinterpret_cast<float4*>(&Vs[r][lc]) =
                *reinterpret_cast<const float4*>(Vb + (size_t)(s0 + r) * QKVS + lc);
        }
        __syncthreads();
        #pragma unroll 8
        for (int s = 0; s < 64; s++) {
            float kf[4], vf[4];
            #pragma unroll
            for (int i = 0; i < 4; i++) kf[i] = Ks[s][ty * 4 + i];
            #pragma unroll
            for (int j = 0; j < 4; j++) vf[j] = Vs[s][tx * 4 + j];
            #pragma unroll
            for (int i = 0; i < 4; i++)
                #pragma unroll
                for (int j = 0; j < 4; j++)
                    acc[i][j] = fmaf(kf[i], vf[j], acc[i][j]);
        }
    }

    float* Mb = Mpart + (size_t)blockIdx.x * DK * DK;
    #pragma unroll
    for (int i = 0; i < 4; i++)
        #pragma unroll
        for (int j = 0; j < 4; j++)
            Mb[(ty * 4 + i) * DK + (tx * 4 + j)] = acc[i][j];
}

// ---------------------------------------------------------------------------
// QM: O_bh = (Q_bh @ sum_c Mpart_bh_c) * 0.125, output fp16.
// ---------------------------------------------------------------------------
__global__ __launch_bounds__(256) void qm_kernel(
    const float* __restrict__ qkv, const float* __restrict__ Mp,
    half_t* __restrict__ Oh)
{
    int bh = blockIdx.y;
    int b = bh >> 4, h = bh & 15;
    int rt = blockIdx.x;
    const float* Qb = qkv + (size_t)b * SEQ * QKVS + (size_t)rt * 64 * QKVS + h * DK;
    const float* Mb = Mp + (size_t)bh * 8 * DK * DK;
    size_t obase = (size_t)b * SEQ * DM + (size_t)rt * 64 * DM + h * DK;

    __shared__ float Qs[64][68];
    __shared__ float Ms[64][68];

    int tid = threadIdx.x;
    int tx = tid & 15, ty = tid >> 4;
    int lr = tid >> 4;
    int lc = (tid & 15) << 2;

    #pragma unroll
    for (int p = 0; p < 4; p++) {
        int r = lr + p * 16;
        *reinterpret_cast<float4*>(&Qs[r][lc]) =
            *reinterpret_cast<const float4*>(Qb + (size_t)r * QKVS + lc);
        float4 a = make_float4(0.f, 0.f, 0.f, 0.f);
        #pragma unroll
        for (int cc = 0; cc < 8; cc++) {
            float4 t4 = *reinterpret_cast<const float4*>(Mb + (size_t)cc * DK * DK + (size_t)r * DK + lc);
            a.x += t4.x; a.y += t4.y; a.z += t4.z; a.w += t4.w;
        }
        *reinterpret_cast<float4*>(&Ms[r][lc]) = a;
    }
    __syncthreads();

    float acc[4][4];
    #pragma unroll
    for (int i = 0; i < 4; i++)
        #pragma unroll
        for (int j = 0; j < 4; j++) acc[i][j] = 0.0f;

    #pragma unroll 8
    for (int k = 0; k < 64; k++) {
        float qf[4], mf[4];
        #pragma unroll
        for (int i = 0; i < 4; i++) qf[i] = Qs[ty * 4 + i][k];
        #pragma unroll
        for (int j = 0; j < 4; j++) mf[j] = Ms[k][tx * 4 + j];
        #pragma unroll
        for (int i = 0; i < 4; i++)
            #pragma unroll
            for (int j = 0; j < 4; j++)
                acc[i][j] = fmaf(qf[i], mf[j], acc[i][j]);
    }

    #pragma unroll
    for (int i = 0; i < 4; i++) {
        __half2 p0 = __floats2half2_rn(acc[i][0] * 0.125f, acc[i][1] * 0.125f);
        __half2 p1 = __floats2half2_rn(acc[i][2] * 0.125f, acc[i][3] * 0.125f);
        uint2 u;
        u.x = *reinterpret_cast<uint32_t*>(&p0);
        u.y = *reinterpret_cast<uint32_t*>(&p1);
        *reinterpret_cast<uint2*>(Oh + obase + (size_t)(ty * 4 + i) * DM + tx * 4) = u;
    }
}

// ---------------------------------------------------------------------------
// Launch
// ---------------------------------------------------------------------------
extern "C" void kernel_launch(void* const* d_in, const int* in_sizes, int n_in,
                              void* d_out, int out_size)
{
    const float* x    = (const float*)d_in[0];
    const float* wq   = (const float*)d_in[2];
    const float* wk   = (const float*)d_in[3];
    const float* wv   = (const float*)d_in[4];
    const float* wo   = (const float*)d_in[5];
    const float* w1   = (const float*)d_in[6];
    const float* b1   = (const float*)d_in[7];
    const float* w2   = (const float*)d_in[8];
    const float* b2   = (const float*)d_in[9];
    const float* ln1a = (const float*)d_in[10];
    const float* ln1b = (const float*)d_in[11];
    const float* ln2a = (const float*)d_in[12];
    const float* ln2b = (const float*)d_in[13];
    float* out = (float*)d_out;

    half_t *xn1h,*xn1l,*xn2h,*oh,*h1h;
    half_t *wqkvTh,*wqkvTl,*woTh,*woTl,*w1Th,*w1Tl,*w2Th,*w2Tl;
    float *qkv,*x1,*mpart;
    cudaGetSymbolAddress((void**)&xn1h, g_xn1h); cudaGetSymbolAddress((void**)&xn1l, g_xn1l);
    cudaGetSymbolAddress((void**)&xn2h, g_xn2h);
    cudaGetSymbolAddress((void**)&oh,   g_oh);
    cudaGetSymbolAddress((void**)&h1h,  g_h1h);
    cudaGetSymbolAddress((void**)&qkv,  g_qkv);  cudaGetSymbolAddress((void**)&x1, g_x1);
    cudaGetSymbolAddress((void**)&mpart,g_mpart);
    cudaGetSymbolAddress((void**)&wqkvTh, g_wqkvTh); cudaGetSymbolAddress((void**)&wqkvTl, g_wqkvTl);
    cudaGetSymbolAddress((void**)&woTh, g_woTh); cudaGetSymbolAddress((void**)&woTl, g_woTl);
    cudaGetSymbolAddress((void**)&w1Th, g_w1Th); cudaGetSymbolAddress((void**)&w1Tl, g_w1Tl);
    cudaGetSymbolAddress((void**)&w2Th, g_w2Th); cudaGetSymbolAddress((void**)&w2Tl, g_w2Tl);

    cudaFuncSetAttribute(gemm_tc<0,true>,  cudaFuncAttributeMaxDynamicSharedMemorySize, SMEM_TOTAL);
    cudaFuncSetAttribute(gemm_tc<1,false>, cudaFuncAttributeMaxDynamicSharedMemorySize, SMEM_TOTAL);
    cudaFuncSetAttribute(gemm_tc<2,false>, cudaFuncAttributeMaxDynamicSharedMemorySize, SMEM_TOTAL);
    cudaFuncSetAttribute(gemm_tc<3,false>, cudaFuncAttributeMaxDynamicSharedMemorySize, SMEM_TOTAL);

    int nsm = 148;
    cudaDeviceGetAttribute(&nsm, cudaDevAttrMultiProcessorCount, 0);

    // Transpose + split weights into [N, K] fp16 hi/lo.
    tsplit_kernel<<<dim3(DM / 32, DM / 32), 256>>>(wq, wqkvTh,             wqkvTl,             DM, DM);
    tsplit_kernel<<<dim3(DM / 32, DM / 32), 256>>>(wk, wqkvTh + 1024 * DM, wqkvTl + 1024 * DM, DM, DM);
    tsplit_kernel<<<dim3(DM / 32, DM / 32), 256>>>(wv, wqkvTh + 2048 * DM, wqkvTl + 2048 * DM, DM, DM);
    tsplit_kernel<<<dim3(DM / 32, DM / 32), 256>>>(wo, woTh, woTl, DM, DM);
    tsplit_kernel<<<dim3(DFF / 32, DM / 32), 256>>>(w1, w1Th, w1Tl, DM, DFF);
    tsplit_kernel<<<dim3(DM / 32, DFF / 32), 256>>>(w2, w2Th, w2Tl, DFF, DM);

    int tQKV = (NTOK / BM) * (QKVN / BN);   // 768
    int tDM  = (NTOK / BM) * (DM / BN);     // 256
    int tFF  = (NTOK / BM) * (DFF / BN);    // 1024
    int gQKV = tQKV < nsm ? tQKV : nsm;
    int gDM  = tDM  < nsm ? tDM  : nsm;
    int gFF  = tFF  < nsm ? tFF  : nsm;

    // 1) xn1 = LN(x) -> fp16 hi+lo (QKV uses 2-term A for attention-path accuracy)
    ln_kernel<true><<<NTOK, 256>>>(x, ln1a, ln1b, xn1h, xn1l);
    // 2) fused QKV projection (3-MMA split): qkv[M, 3072] fp32
    gemm_tc<0,true><<<gQKV, 256, SMEM_TOTAL>>>(
        xn1h, xn1l, wqkvTh, wqkvTl, qkv, nullptr, QKVN, DM, tQKV, nullptr, nullptr);
    // 3) M = K^T V partials (linear attention; no softmax in reference)
    ktv_kernel<<<BATCH * NH * 8, 256>>>(qkv, mpart);
    // 4) O = Q @ M / 8 -> fp16
    qm_kernel<<<dim3(SEQ / 64, BATCH * NH), 256>>>(qkv, mpart, oh);
    // 5) x1 = x + O @ wo   (2-MMA)
    gemm_tc<1,false><<<gDM, 256, SMEM_TOTAL>>>(
        oh, nullptr, woTh, woTl, x1, nullptr, DM, DM, tDM, nullptr, x);
    // 6) xn2 = LN(x1) -> fp16
    ln_kernel<false><<<NTOK, 256>>>(x1, ln2a, ln2b, xn2h, nullptr);
    // 7) h1 = relu(xn2 @ w1 + b1) -> fp16   (2-MMA)
    gemm_tc<2,false><<<gFF, 256, SMEM_TOTAL>>>(
        xn2h, nullptr, w1Th, w1Tl, nullptr, h1h, DFF, DM, tFF, b1, nullptr);
    // 8) out = x1 + h1 @ w2 + b2   (2-MMA)
    gemm_tc<3,false><<<gDM, 256, SMEM_TOTAL>>>(
        h1h, nullptr, w2Th, w2Tl, out, nullptr, DM, DFF, tDM, b2, x1);
}

// round 9
// speedup vs baseline: 1.2778x; 1.0733x over previous
#include <cuda_runtime.h>
#include <cuda_fp16.h>
#include <math.h>
#include <stdint.h>

typedef __half half_t;

// Problem constants
#define DM    1024
#define DFF   4096
#define NTOK  8192
#define SEQ   2048
#define BATCH 4
#define NH    16
#define DK    64
#define QKVN  3072
#define QKVS  3072

// GEMM tiling
#define BM 256
#define BN 128
#define BK 64
#define SMEM_TOTAL 197632
#define SWZ(x) ((x) ^ (((x) >> 3) & 0x70))

// SMEM slot offsets (3-stage ring): A 3 slots of 32KB at 1024;
// B(hi,lo) 6 slots of 16KB at 99328.
__device__ __forceinline__ uint32_t AOFFS(int buf) {
    return 1024u + (uint32_t)buf * 32768u;
}
__device__ __forceinline__ uint32_t BOFFS(int buf, int t) {
    return 99328u + (uint32_t)(buf * 2 + t) * 16384u;
}

// ---------------------------------------------------------------------------
// Scratch (device globals)
// ---------------------------------------------------------------------------
__device__ half_t g_xn1h[NTOK * DM];
__device__ half_t g_xn2h[NTOK * DM];
__device__ half_t g_oh  [NTOK * DM];
__device__ half_t g_h1h [NTOK * DFF];
__device__ float  g_qkv [NTOK * QKVS];
__device__ float  g_x1  [NTOK * DM];
__device__ float  g_mpart[BATCH * NH * 8 * DK * DK];
__device__ half_t g_wqkvTh[QKVN * DM], g_wqkvTl[QKVN * DM];
__device__ half_t g_woTh[DM * DM],   g_woTl[DM * DM];
__device__ half_t g_w1Th[DFF * DM],  g_w1Tl[DFF * DM];
__device__ half_t g_w2Th[DM * DFF],  g_w2Tl[DM * DFF];

// ---------------------------------------------------------------------------
// Helpers
// ---------------------------------------------------------------------------
__device__ __forceinline__ uint32_t smem_u32(const void* p) {
    return (uint32_t)__cvta_generic_to_shared(p);
}
__device__ __forceinline__ void cp16(uint32_t dst, const void* src) {
    asm volatile("cp.async.cg.shared.global [%0], [%1], 16;\n" :: "r"(dst), "l"(src));
}
__device__ __forceinline__ void split2h(float v, half_t& h, half_t& l) {
    h = __float2half_rn(v);
    l = __float2half_rn(v - __half2float(h));
}
__device__ __forceinline__ void ldmx4u(uint32_t* r, uint32_t addr) {
    asm volatile("ldmatrix.sync.aligned.m8n8.x4.shared.b16 {%0,%1,%2,%3}, [%4];\n"
                 : "=r"(r[0]), "=r"(r[1]), "=r"(r[2]), "=r"(r[3]) : "r"(addr));
}
__device__ __forceinline__ void mma16816h(float* d, const uint32_t* a, uint32_t b0, uint32_t b1) {
    asm volatile(
        "mma.sync.aligned.m16n8k16.row.col.f32.f16.f16.f32 "
        "{%0,%1,%2,%3},{%4,%5,%6,%7},{%8,%9},{%0,%1,%2,%3};\n"
        : "+f"(d[0]), "+f"(d[1]), "+f"(d[2]), "+f"(d[3])
        : "r"(a[0]), "r"(a[1]), "r"(a[2]), "r"(a[3]), "r"(b0), "r"(b1));
}

// ---------------------------------------------------------------------------
// Stage loader: A 256x64 + B(hi,lo) 128x64 fp16, SW128, cp.async.
// ---------------------------------------------------------------------------
__device__ __forceinline__ void stage_load(
    uint32_t smem_base,
    const half_t* __restrict__ Ah,
    const half_t* __restrict__ Bh, const half_t* __restrict__ Bl,
    int m0, int n0, int k0, int K, int tid, int buf)
{
    {
        uint32_t base = smem_base + AOFFS(buf);
        #pragma unroll
        for (int i = 0; i < 8; i++) {
            int chunk = tid + i * 256;
            int r = chunk >> 3, c = chunk & 7;
            uint32_t off = (uint32_t)(r * 128 + c * 16);
            cp16(base + SWZ(off), Ah + (size_t)(m0 + r) * K + k0 + c * 8);
        }
    }
    #pragma unroll
    for (int t = 0; t < 2; t++) {
        const half_t* src = t ? Bl : Bh;
        uint32_t base = smem_base + BOFFS(buf, t);
        #pragma unroll
        for (int i = 0; i < 4; i++) {
            int chunk = tid + i * 256;
            int r = chunk >> 3, c = chunk & 7;
            uint32_t off = (uint32_t)(r * 128 + c * 16);
            cp16(base + SWZ(off), src + (size_t)(n0 + r) * K + k0 + c * 8);
        }
    }
}

// ===========================================================================
// tcgen05-only helpers (compiled only when an 'a' feature target exists)
// ===========================================================================
#if defined(__CUDA_ARCH_FEAT_SM103_ALL) || defined(__CUDA_ARCH_FEAT_SM100_ALL)
#define IDESC_F16 ((1u << 4) | (16u << 17) | (8u << 24))
__device__ __forceinline__ uint32_t elect_one() {
    uint32_t pred;
    asm volatile("{\n .reg .pred p;\n elect.sync _|p, 0xFFFFFFFF;\n selp.b32 %0, 1, 0, p;\n}"
                 : "=r"(pred));
    return pred;
}
__device__ __forceinline__ uint64_t make_desc(uint32_t addr) {
    return ((uint64_t)2 << 61) | ((uint64_t)1 << 46) | ((uint64_t)64 << 32) |
           ((uint64_t)1 << 16) | ((uint64_t)(addr >> 4) & 0x3FFF);
}
__device__ __forceinline__ void mma_f16_ss(uint32_t d, uint64_t a, uint64_t b,
                                           uint32_t idesc, bool en) {
    uint32_t e = en ? 1u : 0u;
    asm volatile(
        "{\n\t"
        ".reg .pred p;\n\t"
        "setp.ne.u32 p, %4, 0;\n\t"
        "tcgen05.mma.cta_group::1.kind::f16 [%0], %1, %2, %3, {%5,%5,%5,%5}, p;\n\t"
        "}"
        :: "r"(d), "l"(a), "l"(b), "r"(idesc), "r"(e), "r"(0u) : "memory");
}
__device__ __forceinline__ void mbar_init(uint32_t a, uint32_t c) {
    asm volatile("mbarrier.init.shared.b64 [%0], %1;" :: "r"(a), "r"(c) : "memory");
}
__device__ __forceinline__ void mbar_wait(uint32_t mbar, uint32_t parity) {
    asm volatile(
        "{\n\t"
        ".reg .pred P1;\n\t"
        "WAIT_LOOP_%=:\n\t"
        "mbarrier.try_wait.parity.acquire.cta.shared::cta.b64 P1, [%0], %1, 0x989680;\n\t"
        "@P1 bra.uni WAIT_DONE_%=;\n\t"
        "bra.uni WAIT_LOOP_%=;\n\t"
        "WAIT_DONE_%=:\n\t"
        "}" :: "r"(mbar), "r"(parity) : "memory");
}
#define TC_ALLOC(sm, n)  asm volatile("tcgen05.alloc.cta_group::1.sync.aligned.shared::cta.b32 [%0], %1;" :: "r"(sm), "r"((uint32_t)(n)) : "memory")
#define TC_RELINQ()      asm volatile("tcgen05.relinquish_alloc_permit.cta_group::1.sync.aligned;")
#define TC_DEALLOC(t, n) asm volatile("tcgen05.dealloc.cta_group::1.sync.aligned.b32 %0, %1;" :: "r"(t), "r"((uint32_t)(n)))
#define TC_COMMIT(mb)    asm volatile("tcgen05.commit.cta_group::1.mbarrier::arrive::one.shared::cluster.b64 [%0];" :: "r"(mb) : "memory")
#define TC_FENCE_AFTER() asm volatile("tcgen05.fence::after_thread_sync;" ::: "memory")
#define TC_FENCE_BEFORE() asm volatile("tcgen05.fence::before_thread_sync;" ::: "memory")
#define TC_WAIT_LD()     asm volatile("tcgen05.wait::ld.sync.aligned;" ::: "memory")
#define FENCE_ASYNC()    asm volatile("fence.proxy.async.shared::cta;" ::: "memory")
#define TC_LD_X32(r, ta) \
    asm volatile( \
        "tcgen05.ld.sync.aligned.32x32b.x32.b32 " \
        "{%0, %1, %2, %3, %4, %5, %6, %7, " \
        " %8, %9, %10, %11, %12, %13, %14, %15, " \
        " %16, %17, %18, %19, %20, %21, %22, %23, " \
        " %24, %25, %26, %27, %28, %29, %30, %31}, [%32];" \
        : "=r"((r)[0]),  "=r"((r)[1]),  "=r"((r)[2]),  "=r"((r)[3]), \
          "=r"((r)[4]),  "=r"((r)[5]),  "=r"((r)[6]),  "=r"((r)[7]), \
          "=r"((r)[8]),  "=r"((r)[9]),  "=r"((r)[10]), "=r"((r)[11]), \
          "=r"((r)[12]), "=r"((r)[13]), "=r"((r)[14]), "=r"((r)[15]), \
          "=r"((r)[16]), "=r"((r)[17]), "=r"((r)[18]), "=r"((r)[19]), \
          "=r"((r)[20]), "=r"((r)[21]), "=r"((r)[22]), "=r"((r)[23]), \
          "=r"((r)[24]), "=r"((r)[25]), "=r"((r)[26]), "=r"((r)[27]), \
          "=r"((r)[28]), "=r"((r)[29]), "=r"((r)[30]), "=r"((r)[31]) \
        : "r"(ta))
#endif

// ---------------------------------------------------------------------------
// Persistent GEMM, 256x128 tiles, fp16: D = a*bh + a*bl (2 MMA, 3-stage ring).
// MODE: 0=plain fp32, 1=+resid fp32, 2=relu(D+bias)->fp16, 3=D+bias+resid fp32.
// ---------------------------------------------------------------------------
template<int MODE>
__global__ __launch_bounds__(256)
void gemm_tc(
    const half_t* __restrict__ Ah,
    const half_t* __restrict__ Bh, const half_t* __restrict__ Bl,
    float* __restrict__ C, half_t* __restrict__ Ch,
    int N, int K, int ntiles,
    const float* __restrict__ bias, const float* __restrict__ resid)
{
    extern __shared__ char smem[];
    uint32_t smem_base = smem_u32(smem);
    int tid = threadIdx.x;
    int wid = tid >> 5, lane = tid & 31;
    int ntn = N / BN;
    int S = K / BK;
    constexpr int NSTAGE = 3;

#if defined(__CUDA_ARCH_FEAT_SM103_ALL) || defined(__CUDA_ARCH_FEAT_SM100_ALL)
    // ======================= tcgen05 path =======================
    if (wid == 0) { TC_ALLOC(smem_base, 512); }
    else if (wid == 1) { TC_RELINQ(); }
    if (tid == 0) { mbar_init(smem_base + 8, 1); mbar_init(smem_base + 16, 1); }
    __syncthreads();
    uint32_t tmem;
    asm volatile("ld.shared.b32 %0, [%1];" : "=r"(tmem) : "r"(smem_base));

    int g = 0, tcount = 0;
    for (int tl = blockIdx.x; tl < ntiles; tl += gridDim.x) {
        int m0 = (tl / ntn) * BM, n0 = (tl % ntn) * BN;
        int tp = tcount & 1; tcount++;
        for (int s = 0; s < S; s++, g++) {
            int buf = g % NSTAGE;
            int mb = g & 1;
            if (g >= 2) mbar_wait(smem_base + 8 + mb * 8, ((g - 2) >> 1) & 1);
            stage_load(smem_base, Ah, Bh, Bl, m0, n0, s * BK, K, tid, buf);
            asm volatile("cp.async.commit_group;\n");
            asm volatile("cp.async.wait_group 0;\n");
            __syncthreads();
            FENCE_ASYNC();
            if (wid == 0 && elect_one()) {
                TC_FENCE_AFTER();
                uint64_t aH = make_desc(smem_base + AOFFS(buf));
                uint64_t bH = make_desc(smem_base + BOFFS(buf, 0));
                uint64_t bL = make_desc(smem_base + BOFFS(buf, 1));
                #pragma unroll
                for (int ks = 0; ks < 4; ks++) {
                    #pragma unroll
                    for (int h = 0; h < 2; h++) {
                        uint64_t ah = aH + h * 1024 + ks * 2;
                        uint32_t d = tmem + tp * 256 + h * 128;
                        mma_f16_ss(d, ah, bH + ks * 2, IDESC_F16, !(s == 0 && ks == 0));
                        mma_f16_ss(d, ah, bL + ks * 2, IDESC_F16, true);
                    }
                }
                TC_COMMIT(smem_base + 8 + mb * 8);
            }
        }
        {
            int mb = (g - 1) & 1;
            mbar_wait(smem_base + 8 + mb * 8, ((g - 1) >> 1) & 1);
        }
        TC_FENCE_AFTER();
        int half0 = wid >> 2;
        int grow = m0 + half0 * 128 + ((wid & 3) << 5) + lane;
        #pragma unroll
        for (int cb = 0; cb < 4; cb++) {
            uint32_t r[32];
            TC_LD_X32(r, tmem + tp * 256 + half0 * 128 + cb * 32);
            TC_WAIT_LD();
            int gcol = n0 + cb * 32;
            size_t base = (size_t)grow * N + gcol;
            #pragma unroll
            for (int j = 0; j < 32; j += 4) {
                float v0 = __uint_as_float(r[j]);
                float v1 = __uint_as_float(r[j + 1]);
                float v2 = __uint_as_float(r[j + 2]);
                float v3 = __uint_as_float(r[j + 3]);
                if (MODE == 2 || MODE == 3) {
                    float4 bb = *reinterpret_cast<const float4*>(bias + gcol + j);
                    v0 += bb.x; v1 += bb.y; v2 += bb.z; v3 += bb.w;
                }
                if (MODE == 2) {
                    v0 = fmaxf(v0, 0.f); v1 = fmaxf(v1, 0.f);
                    v2 = fmaxf(v2, 0.f); v3 = fmaxf(v3, 0.f);
                }
                if (MODE == 1 || MODE == 3) {
                    float4 rr = *reinterpret_cast<const float4*>(resid + base + j);
                    v0 += rr.x; v1 += rr.y; v2 += rr.z; v3 += rr.w;
                }
                if (MODE == 2) {
                    __half2 p0 = __floats2half2_rn(v0, v1);
                    __half2 p1 = __floats2half2_rn(v2, v3);
                    uint2 u;
                    u.x = *reinterpret_cast<uint32_t*>(&p0);
                    u.y = *reinterpret_cast<uint32_t*>(&p1);
                    *reinterpret_cast<uint2*>(Ch + base + j) = u;
                } else {
                    float4 o; o.x = v0; o.y = v1; o.z = v2; o.w = v3;
                    *reinterpret_cast<float4*>(C + base + j) = o;
                }
            }
        }
        TC_FENCE_BEFORE();
        __syncthreads();
    }
    __syncthreads();
    if (wid == 0) { TC_DEALLOC(tmem, 512); }

#else
    // ======================= mma.sync path =======================
    int wm = wid & 3, wn = wid >> 2;
    int arow = wm * 64 + (lane & 15);
    int brow = wn * 64 + (lane & 15);

    for (int tl = blockIdx.x; tl < ntiles; tl += gridDim.x) {
        int m0 = (tl / ntn) * BM, n0 = (tl % ntn) * BN;

        float acc[4][8][4];
        #pragma unroll
        for (int i = 0; i < 4; i++)
            #pragma unroll
            for (int j = 0; j < 8; j++)
                #pragma unroll
                for (int d = 0; d < 4; d++) acc[i][j][d] = 0.0f;

        #pragma unroll
        for (int p = 0; p < NSTAGE - 1; p++) {
            stage_load(smem_base, Ah, Bh, Bl, m0, n0, p * BK, K, tid, p);
            asm volatile("cp.async.commit_group;\n");
        }

        for (int s = 0; s < S; s++) {
            if (s + NSTAGE - 1 <= S) {
                asm volatile("cp.async.wait_group %0;\n" :: "n"(NSTAGE - 2));
            } else {
                asm volatile("cp.async.wait_group 0;\n");
            }
            __syncthreads();
            if (s + NSTAGE - 1 < S) {
                stage_load(smem_base, Ah, Bh, Bl, m0, n0,
                           (s + NSTAGE - 1) * BK, K, tid, (s + NSTAGE - 1) % NSTAGE);
                asm volatile("cp.async.commit_group;\n");
            }
            int buf = s % NSTAGE;
            uint32_t aHb = smem_base + AOFFS(buf);
            uint32_t bHb = smem_base + BOFFS(buf, 0);
            uint32_t bLb = smem_base + BOFFS(buf, 1);

            #pragma unroll
            for (int ks = 0; ks < 4; ks++) {
                int colb = ks * 32 + (lane >> 4) * 16;
                uint32_t fa[4][4], fbH[4][4], fbL[4][4];
                #pragma unroll
                for (int mi = 0; mi < 4; mi++) {
                    uint32_t off = (uint32_t)((arow + mi * 16) * 128 + colb);
                    ldmx4u(fa[mi], aHb + SWZ(off));
                }
                #pragma unroll
                for (int ni = 0; ni < 4; ni++) {
                    uint32_t off = (uint32_t)((brow + ni * 16) * 128 + colb);
                    ldmx4u(fbH[ni], bHb + SWZ(off));
                }
                #pragma unroll
                for (int ni = 0; ni < 4; ni++) {
                    uint32_t off = (uint32_t)((brow + ni * 16) * 128 + colb);
                    ldmx4u(fbL[ni], bLb + SWZ(off));
                }
                // a * b_hi
                #pragma unroll
                for (int mi = 0; mi < 4; mi++)
                    #pragma unroll
                    for (int ni = 0; ni < 4; ni++) {
                        mma16816h(acc[mi][2 * ni],     fa[mi], fbH[ni][0], fbH[ni][2]);
                        mma16816h(acc[mi][2 * ni + 1], fa[mi], fbH[ni][1], fbH[ni][3]);
                    }
                // a * b_lo
                #pragma unroll
                for (int mi = 0; mi < 4; mi++)
                    #pragma unroll
                    for (int ni = 0; ni < 4; ni++) {
                        mma16816h(acc[mi][2 * ni],     fa[mi], fbL[ni][0], fbL[ni][2]);
                        mma16816h(acc[mi][2 * ni + 1], fa[mi], fbL[ni][1], fbL[ni][3]);
                    }
            }
        }

        // Epilogue
        int r0 = lane >> 2, c0 = (lane & 3) * 2;
        #pragma unroll
        for (int mi = 0; mi < 4; mi++) {
            #pragma unroll
            for (int t = 0; t < 8; t++) {
                int col = n0 + wn * 64 + t * 8 + c0;
                #pragma unroll
                for (int hh = 0; hh < 2; hh++) {
                    int row = m0 + wm * 64 + mi * 16 + r0 + hh * 8;
                    float v0 = acc[mi][t][hh * 2];
                    float v1 = acc[mi][t][hh * 2 + 1];
                    size_t base = (size_t)row * N + col;
                    if (MODE == 2 || MODE == 3) { v0 += bias[col]; v1 += bias[col + 1]; }
                    if (MODE == 2) { v0 = fmaxf(v0, 0.f); v1 = fmaxf(v1, 0.f); }
                    if (MODE == 1 || MODE == 3) {
                        float2 rr = *reinterpret_cast<const float2*>(resid + base);
                        v0 += rr.x; v1 += rr.y;
                    }
                    if (MODE == 2) {
                        __half2 hp = __floats2half2_rn(v0, v1);
                        *reinterpret_cast<uint32_t*>(Ch + base) = *reinterpret_cast<uint32_t*>(&hp);
                    } else {
                        float2 o; o.x = v0; o.y = v1;
                        *reinterpret_cast<float2*>(C + base) = o;
                    }
                }
            }
        }
        __syncthreads();
    }
#endif
}

// ---------------------------------------------------------------------------
// Weight transpose + split: w[K,N] fp32 -> out[N,K] fp16 hi/lo
// ---------------------------------------------------------------------------
__global__ __launch_bounds__(256) void tsplit_kernel(
    const float* __restrict__ w, half_t* __restrict__ oh, half_t* __restrict__ ol,
    int K, int N)
{
    __shared__ float t[32][33];
    int k0 = blockIdx.y * 32, n0 = blockIdx.x * 32;
    int tx = threadIdx.x & 31, ty = threadIdx.x >> 5;
    #pragma unroll
    for (int i = 0; i < 4; i++)
        t[ty + 8 * i][tx] = w[(size_t)(k0 + ty + 8 * i) * N + n0 + tx];
    __syncthreads();
    #pragma unroll
    for (int i = 0; i < 4; i++) {
        float v = t[tx][ty + 8 * i];
        half_t h, l; split2h(v, h, l);
        size_t idx = (size_t)(n0 + ty + 8 * i) * K + k0 + tx;
        oh[idx] = h; ol[idx] = l;
    }
}

// ---------------------------------------------------------------------------
// LayerNorm (ddof=1, eps on STD), fp16 output.
// ---------------------------------------------------------------------------
__global__ __launch_bounds__(256) void ln_kernel(
    const float* __restrict__ x, const float* __restrict__ alpha,
    const float* __restrict__ bias, half_t* __restrict__ yh)
{
    int row = blockIdx.x;
    int t = threadIdx.x;
    float4 v = reinterpret_cast<const float4*>(x + (size_t)row * DM)[t];
    float s  = v.x + v.y + v.z + v.w;
    float ss = v.x*v.x + v.y*v.y + v.z*v.z + v.w*v.w;

    __shared__ float reds[8], redss[8], bcast[2];
    #pragma unroll
    for (int off = 16; off; off >>= 1) {
        s  += __shfl_xor_sync(0xffffffffu, s,  off);
        ss += __shfl_xor_sync(0xffffffffu, ss, off);
    }
    int wid = t >> 5, lid = t & 31;
    if (lid == 0) { reds[wid] = s; redss[wid] = ss; }
    __syncthreads();
    if (t == 0) {
        float S = 0.f, SS = 0.f;
        #pragma unroll
        for (int i = 0; i < 8; i++) { S += reds[i]; SS += redss[i]; }
        float mean = S * (1.0f / DM);
        float var = (SS - (float)DM * mean * mean) * (1.0f / (DM - 1));
        var = fmaxf(var, 0.0f);
        bcast[0] = mean;
        bcast[1] = 1.0f / (sqrtf(var) + 1e-6f);
    }
    __syncthreads();
    float mean = bcast[0], inv = bcast[1];

    float4 av = reinterpret_cast<const float4*>(alpha)[t];
    float4 bv = reinterpret_cast<const float4*>(bias)[t];
    float o0 = av.x * (v.x - mean) * inv + bv.x;
    float o1 = av.y * (v.y - mean) * inv + bv.y;
    float o2 = av.z * (v.z - mean) * inv + bv.z;
    float o3 = av.w * (v.w - mean) * inv + bv.w;
    __half2 p0 = __floats2half2_rn(o0, o1);
    __half2 p1 = __floats2half2_rn(o2, o3);
    uint2 u;
    u.x = *reinterpret_cast<uint32_t*>(&p0);
    u.y = *reinterpret_cast<uint32_t*>(&p1);
    *reinterpret_cast<uint2*>(yh + (size_t)row * DM + t * 4) = u;
}

// ---------------------------------------------------------------------------
// KtV partial: per (b,h,chunk of 256 seq rows), Mpart[64,64] = K^T V (fp32).
// ---------------------------------------------------------------------------
__global__ __launch_bounds__(256) void ktv_kernel(
    const float* __restrict__ qkv, float* __restrict__ Mpart)
{
    int bh = blockIdx.x >> 3, cch = blockIdx.x & 7;
    int b = bh >> 4, h = bh & 15;
    const float* Kb = qkv + (size_t)b * SEQ * QKVS + 1024 + h * DK;
    const float* Vb = qkv + (size_t)b * SEQ * QKVS + 2048 + h * DK;

    __shared__ float Ks[64][68];
    __shared__ float Vs[64][68];

    int tid = threadIdx.x;
    int tx = tid & 15, ty = tid >> 4;
    int lr = tid >> 4;
    int lc = (tid & 15) << 2;

    float acc[4][4];
    #pragma unroll
    for (int i = 0; i < 4; i++)
        #pragma unroll
        for (int j = 0; j < 4; j++) acc[i][j] = 0.0f;

    int sbeg = cch * 256;
    for (int s0 = sbeg; s0 < sbeg + 256; s0 += 64) {
        __syncthreads();
        #pragma unroll
        for (int p = 0; p < 4; p++) {
            int r = lr + p * 16;
            *reinterpret_cast<float4*>(&Ks[r][lc]) =
                *reinterpret_cast<const float4*>(Kb + (size_t)(s0 + r) * QKVS + lc);
            *reinterpret_cast<float4*>(&Vs[r][lc]) =
                *reinterpret_cast<const float4*>(Vb + (size_t)(s0 + r) * QKVS + lc);
        }
        __syncthreads();
        #pragma unroll 8
        for (int s = 0; s < 64; s++) {
            float kf[4], vf[4];
            #pragma unroll
            for (int i = 0; i < 4; i++) kf[i] = Ks[s][ty * 4 + i];
            #pragma unroll
            for (int j = 0; j < 4; j++) vf[j] = Vs[s][tx * 4 + j];
            #pragma unroll
            for (int i = 0; i < 4; i++)
                #pragma unroll
                for (int j = 0; j < 4; j++)
                    acc[i][j] = fmaf(kf[i], vf[j], acc[i][j]);
        }
    }

    float* Mb = Mpart + (size_t)blockIdx.x * DK * DK;
    #pragma unroll
    for (int i = 0; i < 4; i++)
        #pragma unroll
        for (int j = 0; j < 4; j++)
            Mb[(ty * 4 + i) * DK + (tx * 4 + j)] = acc[i][j];
}

// ---------------------------------------------------------------------------
// QM: O_bh = (Q_bh @ sum_c Mpart_bh_c) * 0.125, output fp16.
// ---------------------------------------------------------------------------
__global__ __launch_bounds__(256) void qm_kernel(
    const float* __restrict__ qkv, const float* __restrict__ Mp,
    half_t* __restrict__ Oh)
{
    int bh = blockIdx.y;
    int b = bh >> 4, h = bh & 15;
    int rt = blockIdx.x;
    const float* Qb = qkv + (size_t)b * SEQ * QKVS + (size_t)rt * 64 * QKVS + h * DK;
    const float* Mb = Mp + (size_t)bh * 8 * DK * DK;
    size_t obase = (size_t)b * SEQ * DM + (size_t)rt * 64 * DM + h * DK;

    __shared__ float Qs[64][68];
    __shared__ float Ms[64][68];

    int tid = threadIdx.x;
    int tx = tid & 15, ty = tid >> 4;
    int lr = tid >> 4;
    int lc = (tid & 15) << 2;

    #pragma unroll
    for (int p = 0; p < 4; p++) {
        int r = lr + p * 16;
        *reinterpret_cast<float4*>(&Qs[r][lc]) =
            *reinterpret_cast<const float4*>(Qb + (size_t)r * QKVS + lc);
        float4 a = make_float4(0.f, 0.f, 0.f, 0.f);
        #pragma unroll
        for (int cc = 0; cc < 8; cc++) {
            float4 t4 = *reinterpret_cast<const float4*>(Mb + (size_t)cc * DK * DK + (size_t)r * DK + lc);
            a.x += t4.x; a.y += t4.y; a.z += t4.z; a.w += t4.w;
        }
        *reinterpret_cast<float4*>(&Ms[r][lc]) = a;
    }
    __syncthreads();

    float acc[4][4];
    #pragma unroll
    for (int i = 0; i < 4; i++)
        #pragma unroll
        for (int j = 0; j < 4; j++) acc[i][j] = 0.0f;

    #pragma unroll 8
    for (int k = 0; k < 64; k++) {
        float qf[4], mf[4];
        #pragma unroll
        for (int i = 0; i < 4; i++) qf[i] = Qs[ty * 4 + i][k];
        #pragma unroll
        for (int j = 0; j < 4; j++) mf[j] = Ms[k][tx * 4 + j];
        #pragma unroll
        for (int i = 0; i < 4; i++)
            #pragma unroll
            for (int j = 0; j < 4; j++)
                acc[i][j] = fmaf(qf[i], mf[j], acc[i][j]);
    }

    #pragma unroll
    for (int i = 0; i < 4; i++) {
        __half2 p0 = __floats2half2_rn(acc[i][0] * 0.125f, acc[i][1] * 0.125f);
        __half2 p1 = __floats2half2_rn(acc[i][2] * 0.125f, acc[i][3] * 0.125f);
        uint2 u;
        u.x = *reinterpret_cast<uint32_t*>(&p0);
        u.y = *reinterpret_cast<uint32_t*>(&p1);
        *reinterpret_cast<uint2*>(Oh + obase + (size_t)(ty * 4 + i) * DM + tx * 4) = u;
    }
}

// ---------------------------------------------------------------------------
// Launch
// ---------------------------------------------------------------------------
extern "C" void kernel_launch(void* const* d_in, const int* in_sizes, int n_in,
                              void* d_out, int out_size)
{
    const float* x    = (const float*)d_in[0];
    const float* wq   = (const float*)d_in[2];
    const float* wk   = (const float*)d_in[3];
    const float* wv   = (const float*)d_in[4];
    const float* wo   = (const float*)d_in[5];
    const float* w1   = (const float*)d_in[6];
    const float* b1   = (const float*)d_in[7];
    const float* w2   = (const float*)d_in[8];
    const float* b2   = (const float*)d_in[9];
    const float* ln1a = (const float*)d_in[10];
    const float* ln1b = (const float*)d_in[11];
    const float* ln2a = (const float*)d_in[12];
    const float* ln2b = (const float*)d_in[13];
    float* out = (float*)d_out;

    half_t *xn1h,*xn2h,*oh,*h1h;
    half_t *wqkvTh,*wqkvTl,*woTh,*woTl,*w1Th,*w1Tl,*w2Th,*w2Tl;
    float *qkv,*x1,*mpart;
    cudaGetSymbolAddress((void**)&xn1h, g_xn1h);
    cudaGetSymbolAddress((void**)&xn2h, g_xn2h);
    cudaGetSymbolAddress((void**)&oh,   g_oh);
    cudaGetSymbolAddress((void**)&h1h,  g_h1h);
    cudaGetSymbolAddress((void**)&qkv,  g_qkv);  cudaGetSymbolAddress((void**)&x1, g_x1);
    cudaGetSymbolAddress((void**)&mpart,g_mpart);
    cudaGetSymbolAddress((void**)&wqkvTh, g_wqkvTh); cudaGetSymbolAddress((void**)&wqkvTl, g_wqkvTl);
    cudaGetSymbolAddress((void**)&woTh, g_woTh); cudaGetSymbolAddress((void**)&woTl, g_woTl);
    cudaGetSymbolAddress((void**)&w1Th, g_w1Th); cudaGetSymbolAddress((void**)&w1Tl, g_w1Tl);
    cudaGetSymbolAddress((void**)&w2Th, g_w2Th); cudaGetSymbolAddress((void**)&w2Tl, g_w2Tl);

    cudaFuncSetAttribute(gemm_tc<0>, cudaFuncAttributeMaxDynamicSharedMemorySize, SMEM_TOTAL);
    cudaFuncSetAttribute(gemm_tc<1>, cudaFuncAttributeMaxDynamicSharedMemorySize, SMEM_TOTAL);
    cudaFuncSetAttribute(gemm_tc<2>, cudaFuncAttributeMaxDynamicSharedMemorySize, SMEM_TOTAL);
    cudaFuncSetAttribute(gemm_tc<3>, cudaFuncAttributeMaxDynamicSharedMemorySize, SMEM_TOTAL);

    int nsm = 148;
    cudaDeviceGetAttribute(&nsm, cudaDevAttrMultiProcessorCount, 0);

    // Transpose + split weights into [N, K] fp16 hi/lo.
    tsplit_kernel<<<dim3(DM / 32, DM / 32), 256>>>(wq, wqkvTh,             wqkvTl,             DM, DM);
    tsplit_kernel<<<dim3(DM / 32, DM / 32), 256>>>(wk, wqkvTh + 1024 * DM, wqkvTl + 1024 * DM, DM, DM);
    tsplit_kernel<<<dim3(DM / 32, DM / 32), 256>>>(wv, wqkvTh + 2048 * DM, wqkvTl + 2048 * DM, DM, DM);
    tsplit_kernel<<<dim3(DM / 32, DM / 32), 256>>>(wo, woTh, woTl, DM, DM);
    tsplit_kernel<<<dim3(DFF / 32, DM / 32), 256>>>(w1, w1Th, w1Tl, DM, DFF);
    tsplit_kernel<<<dim3(DM / 32, DFF / 32), 256>>>(w2, w2Th, w2Tl, DFF, DM);

    int tQKV = (NTOK / BM) * (QKVN / BN);   // 768
    int tDM  = (NTOK / BM) * (DM / BN);     // 256
    int tFF  = (NTOK / BM) * (DFF / BN);    // 1024
    int gQKV = tQKV < nsm ? tQKV : nsm;
    int gDM  = tDM  < nsm ? tDM  : nsm;
    int gFF  = tFF  < nsm ? tFF  : nsm;

    // 1) xn1 = LN(x) -> fp16
    ln_kernel<<<NTOK, 256>>>(x, ln1a, ln1b, xn1h);
    // 2) fused QKV projection (2-MMA): qkv[M, 3072] fp32
    gemm_tc<0><<<gQKV, 256, SMEM_TOTAL>>>(
        xn1h, wqkvTh, wqkvTl, qkv, nullptr, QKVN, DM, tQKV, nullptr, nullptr);
    // 3) M = K^T V partials (linear attention; no softmax in reference)
    ktv_kernel<<<BATCH * NH * 8, 256>>>(qkv, mpart);
    // 4) O = Q @ M / 8 -> fp16
    qm_kernel<<<dim3(SEQ / 64, BATCH * NH), 256>>>(qkv, mpart, oh);
    // 5) x1 = x + O @ wo   (2-MMA)
    gemm_tc<1><<<gDM, 256, SMEM_TOTAL>>>(
        oh, woTh, woTl, x1, nullptr, DM, DM, tDM, nullptr, x);
    // 6) xn2 = LN(x1) -> fp16
    ln_kernel<<<NTOK, 256>>>(x1, ln2a, ln2b, xn2h);
    // 7) h1 = relu(xn2 @ w1 + b1) -> fp16   (2-MMA)
    gemm_tc<2><<<gFF, 256, SMEM_TOTAL>>>(
        xn2h, w1Th, w1Tl, nullptr, h1h, DFF, DM, tFF, b1, nullptr);
    // 8) out = x1 + h1 @ w2 + b2   (2-MMA)
    gemm_tc<3><<<gDM, 256, SMEM_TOTAL>>>(
        h1h, w2Th, w2Tl, out, nullptr, DM, DFF, tDM, b2, x1);
}

// round 10
// speedup vs baseline: 1.4361x; 1.1239x over previous
#include <cuda_runtime.h>
#include <cuda_fp16.h>
#include <math.h>
#include <stdint.h>

typedef __half half_t;

// Problem constants
#define DM    1024
#define DFF   4096
#define NTOK  8192
#define SEQ   2048
#define BATCH 4
#define NH    16
#define DK    64
#define QKVN  3072
#define QKVS  3072

// GEMM tiling
#define BM 256
#define BN 128
#define BK 64
#define SMEM_TOTAL 197632
#define SWZ(x) ((x) ^ (((x) >> 3) & 0x70))

// SMEM slot offsets (3-stage ring): A 3 slots of 32KB at 1024;
// B(hi,lo) 6 slots of 16KB at 99328.
__device__ __forceinline__ uint32_t AOFFS(int buf) {
    return 1024u + (uint32_t)buf * 32768u;
}
__device__ __forceinline__ uint32_t BOFFS(int buf, int t) {
    return 99328u + (uint32_t)(buf * 2 + t) * 16384u;
}

// ---------------------------------------------------------------------------
// Scratch (device globals)
// ---------------------------------------------------------------------------
__device__ half_t g_xn1h[NTOK * DM];
__device__ half_t g_xn2h[NTOK * DM];
__device__ half_t g_oh  [NTOK * DM];
__device__ half_t g_h1h [NTOK * DFF];
__device__ float  g_qkv [NTOK * QKVS];
__device__ float  g_x1  [NTOK * DM];
__device__ float  g_mpart[BATCH * NH * 8 * DK * DK];
__device__ half_t g_wqkvTh[QKVN * DM], g_wqkvTl[QKVN * DM];
__device__ half_t g_woTh[DM * DM];
__device__ half_t g_w1Th[DFF * DM];
__device__ half_t g_w2Th[DM * DFF];

// ---------------------------------------------------------------------------
// Helpers
// ---------------------------------------------------------------------------
__device__ __forceinline__ uint32_t smem_u32(const void* p) {
    return (uint32_t)__cvta_generic_to_shared(p);
}
__device__ __forceinline__ void cp16(uint32_t dst, const void* src) {
    asm volatile("cp.async.cg.shared.global [%0], [%1], 16;\n" :: "r"(dst), "l"(src));
}
__device__ __forceinline__ void split2h(float v, half_t& h, half_t& l) {
    h = __float2half_rn(v);
    l = __float2half_rn(v - __half2float(h));
}
__device__ __forceinline__ void ldmx4u(uint32_t* r, uint32_t addr) {
    asm volatile("ldmatrix.sync.aligned.m8n8.x4.shared.b16 {%0,%1,%2,%3}, [%4];\n"
                 : "=r"(r[0]), "=r"(r[1]), "=r"(r[2]), "=r"(r[3]) : "r"(addr));
}
__device__ __forceinline__ void mma16816h(float* d, const uint32_t* a, uint32_t b0, uint32_t b1) {
    asm volatile(
        "mma.sync.aligned.m16n8k16.row.col.f32.f16.f16.f32 "
        "{%0,%1,%2,%3},{%4,%5,%6,%7},{%8,%9},{%0,%1,%2,%3};\n"
        : "+f"(d[0]), "+f"(d[1]), "+f"(d[2]), "+f"(d[3])
        : "r"(a[0]), "r"(a[1]), "r"(a[2]), "r"(a[3]), "r"(b0), "r"(b1));
}

// ---------------------------------------------------------------------------
// Stage loader: A 256x64 + B 128x64 (hi [,lo]) fp16, SW128, cp.async.
// ---------------------------------------------------------------------------
template<bool BL>
__device__ __forceinline__ void stage_load(
    uint32_t smem_base,
    const half_t* __restrict__ Ah,
    const half_t* __restrict__ Bh, const half_t* __restrict__ Bl,
    int m0, int n0, int k0, int K, int tid, int buf)
{
    {
        uint32_t base = smem_base + AOFFS(buf);
        #pragma unroll
        for (int i = 0; i < 8; i++) {
            int chunk = tid + i * 256;
            int r = chunk >> 3, c = chunk & 7;
            uint32_t off = (uint32_t)(r * 128 + c * 16);
            cp16(base + SWZ(off), Ah + (size_t)(m0 + r) * K + k0 + c * 8);
        }
    }
    #pragma unroll
    for (int t = 0; t < (BL ? 2 : 1); t++) {
        const half_t* src = t ? Bl : Bh;
        uint32_t base = smem_base + BOFFS(buf, t);
        #pragma unroll
        for (int i = 0; i < 4; i++) {
            int chunk = tid + i * 256;
            int r = chunk >> 3, c = chunk & 7;
            uint32_t off = (uint32_t)(r * 128 + c * 16);
            cp16(base + SWZ(off), src + (size_t)(n0 + r) * K + k0 + c * 8);
        }
    }
}

// ===========================================================================
// tcgen05-only helpers (compiled only when an 'a' feature target exists)
// ===========================================================================
#if defined(__CUDA_ARCH_FEAT_SM103_ALL) || defined(__CUDA_ARCH_FEAT_SM100_ALL)
#define IDESC_F16 ((1u << 4) | (16u << 17) | (8u << 24))
__device__ __forceinline__ uint32_t elect_one() {
    uint32_t pred;
    asm volatile("{\n .reg .pred p;\n elect.sync _|p, 0xFFFFFFFF;\n selp.b32 %0, 1, 0, p;\n}"
                 : "=r"(pred));
    return pred;
}
__device__ __forceinline__ uint64_t make_desc(uint32_t addr) {
    return ((uint64_t)2 << 61) | ((uint64_t)1 << 46) | ((uint64_t)64 << 32) |
           ((uint64_t)1 << 16) | ((uint64_t)(addr >> 4) & 0x3FFF);
}
__device__ __forceinline__ void mma_f16_ss(uint32_t d, uint64_t a, uint64_t b,
                                           uint32_t idesc, bool en) {
    uint32_t e = en ? 1u : 0u;
    asm volatile(
        "{\n\t"
        ".reg .pred p;\n\t"
        "setp.ne.u32 p, %4, 0;\n\t"
        "tcgen05.mma.cta_group::1.kind::f16 [%0], %1, %2, %3, {%5,%5,%5,%5}, p;\n\t"
        "}"
        :: "r"(d), "l"(a), "l"(b), "r"(idesc), "r"(e), "r"(0u) : "memory");
}
__device__ __forceinline__ void mbar_init(uint32_t a, uint32_t c) {
    asm volatile("mbarrier.init.shared.b64 [%0], %1;" :: "r"(a), "r"(c) : "memory");
}
__device__ __forceinline__ void mbar_wait(uint32_t mbar, uint32_t parity) {
    asm volatile(
        "{\n\t"
        ".reg .pred P1;\n\t"
        "WAIT_LOOP_%=:\n\t"
        "mbarrier.try_wait.parity.acquire.cta.shared::cta.b64 P1, [%0], %1, 0x989680;\n\t"
        "@P1 bra.uni WAIT_DONE_%=;\n\t"
        "bra.uni WAIT_LOOP_%=;\n\t"
        "WAIT_DONE_%=:\n\t"
        "}" :: "r"(mbar), "r"(parity) : "memory");
}
#define TC_ALLOC(sm, n)  asm volatile("tcgen05.alloc.cta_group::1.sync.aligned.shared::cta.b32 [%0], %1;" :: "r"(sm), "r"((uint32_t)(n)) : "memory")
#define TC_RELINQ()      asm volatile("tcgen05.relinquish_alloc_permit.cta_group::1.sync.aligned;")
#define TC_DEALLOC(t, n) asm volatile("tcgen05.dealloc.cta_group::1.sync.aligned.b32 %0, %1;" :: "r"(t), "r"((uint32_t)(n)))
#define TC_COMMIT(mb)    asm volatile("tcgen05.commit.cta_group::1.mbarrier::arrive::one.shared::cluster.b64 [%0];" :: "r"(mb) : "memory")
#define TC_FENCE_AFTER() asm volatile("tcgen05.fence::after_thread_sync;" ::: "memory")
#define TC_FENCE_BEFORE() asm volatile("tcgen05.fence::before_thread_sync;" ::: "memory")
#define TC_WAIT_LD()     asm volatile("tcgen05.wait::ld.sync.aligned;" ::: "memory")
#define FENCE_ASYNC()    asm volatile("fence.proxy.async.shared::cta;" ::: "memory")
#define TC_LD_X32(r, ta) \
    asm volatile( \
        "tcgen05.ld.sync.aligned.32x32b.x32.b32 " \
        "{%0, %1, %2, %3, %4, %5, %6, %7, " \
        " %8, %9, %10, %11, %12, %13, %14, %15, " \
        " %16, %17, %18, %19, %20, %21, %22, %23, " \
        " %24, %25, %26, %27, %28, %29, %30, %31}, [%32];" \
        : "=r"((r)[0]),  "=r"((r)[1]),  "=r"((r)[2]),  "=r"((r)[3]), \
          "=r"((r)[4]),  "=r"((r)[5]),  "=r"((r)[6]),  "=r"((r)[7]), \
          "=r"((r)[8]),  "=r"((r)[9]),  "=r"((r)[10]), "=r"((r)[11]), \
          "=r"((r)[12]), "=r"((r)[13]), "=r"((r)[14]), "=r"((r)[15]), \
          "=r"((r)[16]), "=r"((r)[17]), "=r"((r)[18]), "=r"((r)[19]), \
          "=r"((r)[20]), "=r"((r)[21]), "=r"((r)[22]), "=r"((r)[23]), \
          "=r"((r)[24]), "=r"((r)[25]), "=r"((r)[26]), "=r"((r)[27]), \
          "=r"((r)[28]), "=r"((r)[29]), "=r"((r)[30]), "=r"((r)[31]) \
        : "r"(ta))
#endif

// ---------------------------------------------------------------------------
// Persistent GEMM, 256x128 tiles, fp16 (3-stage ring).
//   BL=1: D = a*bh + a*bl (2 MMA).  BL=0: D = a*bh (1 MMA).
// MODE: 0=plain fp32, 1=+resid fp32, 2=relu(D+bias)->fp16, 3=D+bias+resid fp32.
// ---------------------------------------------------------------------------
template<int MODE, bool BL>
__global__ __launch_bounds__(256)
void gemm_tc(
    const half_t* __restrict__ Ah,
    const half_t* __restrict__ Bh, const half_t* __restrict__ Bl,
    float* __restrict__ C, half_t* __restrict__ Ch,
    int N, int K, int ntiles,
    const float* __restrict__ bias, const float* __restrict__ resid)
{
    extern __shared__ char smem[];
    uint32_t smem_base = smem_u32(smem);
    int tid = threadIdx.x;
    int wid = tid >> 5, lane = tid & 31;
    int ntn = N / BN;
    int S = K / BK;
    constexpr int NSTAGE = 3;

#if defined(__CUDA_ARCH_FEAT_SM103_ALL) || defined(__CUDA_ARCH_FEAT_SM100_ALL)
    // ======================= tcgen05 path =======================
    if (wid == 0) { TC_ALLOC(smem_base, 512); }
    else if (wid == 1) { TC_RELINQ(); }
    if (tid == 0) { mbar_init(smem_base + 8, 1); mbar_init(smem_base + 16, 1); }
    __syncthreads();
    uint32_t tmem;
    asm volatile("ld.shared.b32 %0, [%1];" : "=r"(tmem) : "r"(smem_base));

    int g = 0, tcount = 0;
    for (int tl = blockIdx.x; tl < ntiles; tl += gridDim.x) {
        int m0 = (tl / ntn) * BM, n0 = (tl % ntn) * BN;
        int tp = tcount & 1; tcount++;
        for (int s = 0; s < S; s++, g++) {
            int buf = g % NSTAGE;
            int mb = g & 1;
            if (g >= 2) mbar_wait(smem_base + 8 + mb * 8, ((g - 2) >> 1) & 1);
            stage_load<BL>(smem_base, Ah, Bh, Bl, m0, n0, s * BK, K, tid, buf);
            asm volatile("cp.async.commit_group;\n");
            asm volatile("cp.async.wait_group 0;\n");
            __syncthreads();
            FENCE_ASYNC();
            if (wid == 0 && elect_one()) {
                TC_FENCE_AFTER();
                uint64_t aH = make_desc(smem_base + AOFFS(buf));
                uint64_t bH = make_desc(smem_base + BOFFS(buf, 0));
                uint64_t bL = make_desc(smem_base + BOFFS(buf, 1));
                #pragma unroll
                for (int ks = 0; ks < 4; ks++) {
                    #pragma unroll
                    for (int h = 0; h < 2; h++) {
                        uint64_t ah = aH + h * 1024 + ks * 2;
                        uint32_t d = tmem + tp * 256 + h * 128;
                        mma_f16_ss(d, ah, bH + ks * 2, IDESC_F16, !(s == 0 && ks == 0));
                        if (BL) mma_f16_ss(d, ah, bL + ks * 2, IDESC_F16, true);
                    }
                }
                TC_COMMIT(smem_base + 8 + mb * 8);
            }
        }
        {
            int mb = (g - 1) & 1;
            mbar_wait(smem_base + 8 + mb * 8, ((g - 1) >> 1) & 1);
        }
        TC_FENCE_AFTER();
        int half0 = wid >> 2;
        int grow = m0 + half0 * 128 + ((wid & 3) << 5) + lane;
        #pragma unroll
        for (int cb = 0; cb < 4; cb++) {
            uint32_t r[32];
            TC_LD_X32(r, tmem + tp * 256 + half0 * 128 + cb * 32);
            TC_WAIT_LD();
            int gcol = n0 + cb * 32;
            size_t base = (size_t)grow * N + gcol;
            #pragma unroll
            for (int j = 0; j < 32; j += 4) {
                float v0 = __uint_as_float(r[j]);
                float v1 = __uint_as_float(r[j + 1]);
                float v2 = __uint_as_float(r[j + 2]);
                float v3 = __uint_as_float(r[j + 3]);
                if (MODE == 2 || MODE == 3) {
                    float4 bb = *reinterpret_cast<const float4*>(bias + gcol + j);
                    v0 += bb.x; v1 += bb.y; v2 += bb.z; v3 += bb.w;
                }
                if (MODE == 2) {
                    v0 = fmaxf(v0, 0.f); v1 = fmaxf(v1, 0.f);
                    v2 = fmaxf(v2, 0.f); v3 = fmaxf(v3, 0.f);
                }
                if (MODE == 1 || MODE == 3) {
                    float4 rr = *reinterpret_cast<const float4*>(resid + base + j);
                    v0 += rr.x; v1 += rr.y; v2 += rr.z; v3 += rr.w;
                }
                if (MODE == 2) {
                    __half2 p0 = __floats2half2_rn(v0, v1);
                    __half2 p1 = __floats2half2_rn(v2, v3);
                    uint2 u;
                    u.x = *reinterpret_cast<uint32_t*>(&p0);
                    u.y = *reinterpret_cast<uint32_t*>(&p1);
                    *reinterpret_cast<uint2*>(Ch + base + j) = u;
                } else {
                    float4 o; o.x = v0; o.y = v1; o.z = v2; o.w = v3;
                    *reinterpret_cast<float4*>(C + base + j) = o;
                }
            }
        }
        TC_FENCE_BEFORE();
        __syncthreads();
    }
    __syncthreads();
    if (wid == 0) { TC_DEALLOC(tmem, 512); }

#else
    // ======================= mma.sync path =======================
    int wm = wid & 3, wn = wid >> 2;
    int arow = wm * 64 + (lane & 15);
    int brow = wn * 64 + (lane & 15);

    for (int tl = blockIdx.x; tl < ntiles; tl += gridDim.x) {
        int m0 = (tl / ntn) * BM, n0 = (tl % ntn) * BN;

        float acc[4][8][4];
        #pragma unroll
        for (int i = 0; i < 4; i++)
            #pragma unroll
            for (int j = 0; j < 8; j++)
                #pragma unroll
                for (int d = 0; d < 4; d++) acc[i][j][d] = 0.0f;

        #pragma unroll
        for (int p = 0; p < NSTAGE - 1; p++) {
            stage_load<BL>(smem_base, Ah, Bh, Bl, m0, n0, p * BK, K, tid, p);
            asm volatile("cp.async.commit_group;\n");
        }

        for (int s = 0; s < S; s++) {
            if (s + NSTAGE - 1 <= S) {
                asm volatile("cp.async.wait_group %0;\n" :: "n"(NSTAGE - 2));
            } else {
                asm volatile("cp.async.wait_group 0;\n");
            }
            __syncthreads();
            if (s + NSTAGE - 1 < S) {
                stage_load<BL>(smem_base, Ah, Bh, Bl, m0, n0,
                               (s + NSTAGE - 1) * BK, K, tid, (s + NSTAGE - 1) % NSTAGE);
                asm volatile("cp.async.commit_group;\n");
            }
            int buf = s % NSTAGE;
            uint32_t aHb = smem_base + AOFFS(buf);
            uint32_t bHb = smem_base + BOFFS(buf, 0);
            uint32_t bLb = smem_base + BOFFS(buf, 1);

            #pragma unroll
            for (int ks = 0; ks < 4; ks++) {
                int colb = ks * 32 + (lane >> 4) * 16;
                uint32_t fa[4][4], fbH[4][4];
                #pragma unroll
                for (int mi = 0; mi < 4; mi++) {
                    uint32_t off = (uint32_t)((arow + mi * 16) * 128 + colb);
                    ldmx4u(fa[mi], aHb + SWZ(off));
                }
                #pragma unroll
                for (int ni = 0; ni < 4; ni++) {
                    uint32_t off = (uint32_t)((brow + ni * 16) * 128 + colb);
                    ldmx4u(fbH[ni], bHb + SWZ(off));
                }
                // a * b_hi
                #pragma unroll
                for (int mi = 0; mi < 4; mi++)
                    #pragma unroll
                    for (int ni = 0; ni < 4; ni++) {
                        mma16816h(acc[mi][2 * ni],     fa[mi], fbH[ni][0], fbH[ni][2]);
                        mma16816h(acc[mi][2 * ni + 1], fa[mi], fbH[ni][1], fbH[ni][3]);
                    }
                if (BL) {
                    // a * b_lo (reuse fbH regs)
                    #pragma unroll
                    for (int ni = 0; ni < 4; ni++) {
                        uint32_t off = (uint32_t)((brow + ni * 16) * 128 + colb);
                        ldmx4u(fbH[ni], bLb + SWZ(off));
                    }
                    #pragma unroll
                    for (int mi = 0; mi < 4; mi++)
                        #pragma unroll
                        for (int ni = 0; ni < 4; ni++) {
                            mma16816h(acc[mi][2 * ni],     fa[mi], fbH[ni][0], fbH[ni][2]);
                            mma16816h(acc[mi][2 * ni + 1], fa[mi], fbH[ni][1], fbH[ni][3]);
                        }
                }
            }
        }

        // Epilogue
        int r0 = lane >> 2, c0 = (lane & 3) * 2;
        #pragma unroll
        for (int mi = 0; mi < 4; mi++) {
            #pragma unroll
            for (int t = 0; t < 8; t++) {
                int col = n0 + wn * 64 + t * 8 + c0;
                #pragma unroll
                for (int hh = 0; hh < 2; hh++) {
                    int row = m0 + wm * 64 + mi * 16 + r0 + hh * 8;
                    float v0 = acc[mi][t][hh * 2];
                    float v1 = acc[mi][t][hh * 2 + 1];
                    size_t base = (size_t)row * N + col;
                    if (MODE == 2 || MODE == 3) { v0 += bias[col]; v1 += bias[col + 1]; }
                    if (MODE == 2) { v0 = fmaxf(v0, 0.f); v1 = fmaxf(v1, 0.f); }
                    if (MODE == 1 || MODE == 3) {
                        float2 rr = *reinterpret_cast<const float2*>(resid + base);
                        v0 += rr.x; v1 += rr.y;
                    }
                    if (MODE == 2) {
                        __half2 hp = __floats2half2_rn(v0, v1);
                        *reinterpret_cast<uint32_t*>(Ch + base) = *reinterpret_cast<uint32_t*>(&hp);
                    } else {
                        float2 o; o.x = v0; o.y = v1;
                        *reinterpret_cast<float2*>(C + base) = o;
                    }
                }
            }
        }
        __syncthreads();
    }
#endif
}

// ---------------------------------------------------------------------------
// Weight transpose + split: w[K,N] fp32 -> out[N,K] fp16 hi/lo
// ---------------------------------------------------------------------------
__global__ __launch_bounds__(256) void tsplit_kernel(
    const float* __restrict__ w, half_t* __restrict__ oh, half_t* __restrict__ ol,
    int K, int N)
{
    __shared__ float t[32][33];
    int k0 = blockIdx.y * 32, n0 = blockIdx.x * 32;
    int tx = threadIdx.x & 31, ty = threadIdx.x >> 5;
    #pragma unroll
    for (int i = 0; i < 4; i++)
        t[ty + 8 * i][tx] = w[(size_t)(k0 + ty + 8 * i) * N + n0 + tx];
    __syncthreads();
    #pragma unroll
    for (int i = 0; i < 4; i++) {
        float v = t[tx][ty + 8 * i];
        half_t h, l; split2h(v, h, l);
        size_t idx = (size_t)(n0 + ty + 8 * i) * K + k0 + tx;
        oh[idx] = h;
        if (ol) ol[idx] = l;
    }
}

// ---------------------------------------------------------------------------
// LayerNorm (ddof=1, eps on STD), fp16 output.
// ---------------------------------------------------------------------------
__global__ __launch_bounds__(256) void ln_kernel(
    const float* __restrict__ x, const float* __restrict__ alpha,
    const float* __restrict__ bias, half_t* __restrict__ yh)
{
    int row = blockIdx.x;
    int t = threadIdx.x;
    float4 v = reinterpret_cast<const float4*>(x + (size_t)row * DM)[t];
    float s  = v.x + v.y + v.z + v.w;
    float ss = v.x*v.x + v.y*v.y + v.z*v.z + v.w*v.w;

    __shared__ float reds[8], redss[8], bcast[2];
    #pragma unroll
    for (int off = 16; off; off >>= 1) {
        s  += __shfl_xor_sync(0xffffffffu, s,  off);
        ss += __shfl_xor_sync(0xffffffffu, ss, off);
    }
    int wid = t >> 5, lid = t & 31;
    if (lid == 0) { reds[wid] = s; redss[wid] = ss; }
    __syncthreads();
    if (t == 0) {
        float S = 0.f, SS = 0.f;
        #pragma unroll
        for (int i = 0; i < 8; i++) { S += reds[i]; SS += redss[i]; }
        float mean = S * (1.0f / DM);
        float var = (SS - (float)DM * mean * mean) * (1.0f / (DM - 1));
        var = fmaxf(var, 0.0f);
        bcast[0] = mean;
        bcast[1] = 1.0f / (sqrtf(var) + 1e-6f);
    }
    __syncthreads();
    float mean = bcast[0], inv = bcast[1];

    float4 av = reinterpret_cast<const float4*>(alpha)[t];
    float4 bv = reinterpret_cast<const float4*>(bias)[t];
    float o0 = av.x * (v.x - mean) * inv + bv.x;
    float o1 = av.y * (v.y - mean) * inv + bv.y;
    float o2 = av.z * (v.z - mean) * inv + bv.z;
    float o3 = av.w * (v.w - mean) * inv + bv.w;
    __half2 p0 = __floats2half2_rn(o0, o1);
    __half2 p1 = __floats2half2_rn(o2, o3);
    uint2 u;
    u.x = *reinterpret_cast<uint32_t*>(&p0);
    u.y = *reinterpret_cast<uint32_t*>(&p1);
    *reinterpret_cast<uint2*>(yh + (size_t)row * DM + t * 4) = u;
}

// ---------------------------------------------------------------------------
// KtV partial: per (b,h,chunk of 256 seq rows), Mpart[64,64] = K^T V (fp32).
// ---------------------------------------------------------------------------
__global__ __launch_bounds__(256) void ktv_kernel(
    const float* __restrict__ qkv, float* __restrict__ Mpart)
{
    int bh = blockIdx.x >> 3, cch = blockIdx.x & 7;
    int b = bh >> 4, h = bh & 15;
    const float* Kb = qkv + (size_t)b * SEQ * QKVS + 1024 + h * DK;
    const float* Vb = qkv + (size_t)b * SEQ * QKVS + 2048 + h * DK;

    __shared__ float Ks[64][68];
    __shared__ float Vs[64][68];

    int tid = threadIdx.x;
    int tx = tid & 15, ty = tid >> 4;
    int lr = tid >> 4;
    int lc = (tid & 15) << 2;

    float acc[4][4];
    #pragma unroll
    for (int i = 0; i < 4; i++)
        #pragma unroll
        for (int j = 0; j < 4; j++) acc[i][j] = 0.0f;

    int sbeg = cch * 256;
    for (int s0 = sbeg; s0 < sbeg + 256; s0 += 64) {
        __syncthreads();
        #pragma unroll
        for (int p = 0; p < 4; p++) {
            int r = lr + p * 16;
            *reinterpret_cast<float4*>(&Ks[r][lc]) =
                *reinterpret_cast<const float4*>(Kb + (size_t)(s0 + r) * QKVS + lc);
            *reinterpret_cast<float4*>(&Vs[r][lc]) =
                *reinterpret_cast<const float4*>(Vb + (size_t)(s0 + r) * QKVS + lc);
        }
        __syncthreads();
        #pragma unroll 8
        for (int s = 0; s < 64; s++) {
            float kf[4], vf[4];
            #pragma unroll
            for (int i = 0; i < 4; i++) kf[i] = Ks[s][ty * 4 + i];
            #pragma unroll
            for (int j = 0; j < 4; j++) vf[j] = Vs[s][tx * 4 + j];
            #pragma unroll
            for (int i = 0; i < 4; i++)
                #pragma unroll
                for (int j = 0; j < 4; j++)
                    acc[i][j] = fmaf(kf[i], vf[j], acc[i][j]);
        }
    }

    float* Mb = Mpart + (size_t)blockIdx.x * DK * DK;
    #pragma unroll
    for (int i = 0; i < 4; i++)
        #pragma unroll
        for (int j = 0; j < 4; j++)
            Mb[(ty * 4 + i) * DK + (tx * 4 + j)] = acc[i][j];
}

// ---------------------------------------------------------------------------
// QM: O_bh = (Q_bh @ sum_c Mpart_bh_c) * 0.125, output fp16.
// ---------------------------------------------------------------------------
__global__ __launch_bounds__(256) void qm_kernel(
    const float* __restrict__ qkv, const float* __restrict__ Mp,
    half_t* __restrict__ Oh)
{
    int bh = blockIdx.y;
    int b = bh >> 4, h = bh & 15;
    int rt = blockIdx.x;
    const float* Qb = qkv + (size_t)b * SEQ * QKVS + (size_t)rt * 64 * QKVS + h * DK;
    const float* Mb = Mp + (size_t)bh * 8 * DK * DK;
    size_t obase = (size_t)b * SEQ * DM + (size_t)rt * 64 * DM + h * DK;

    __shared__ float Qs[64][68];
    __shared__ float Ms[64][68];

    int tid = threadIdx.x;
    int tx = tid & 15, ty = tid >> 4;
    int lr = tid >> 4;
    int lc = (tid & 15) << 2;

    #pragma unroll
    for (int p = 0; p < 4; p++) {
        int r = lr + p * 16;
        *reinterpret_cast<float4*>(&Qs[r][lc]) =
            *reinterpret_cast<const float4*>(Qb + (size_t)r * QKVS + lc);
        float4 a = make_float4(0.f, 0.f, 0.f, 0.f);
        #pragma unroll
        for (int cc = 0; cc < 8; cc++) {
            float4 t4 = *reinterpret_cast<const float4*>(Mb + (size_t)cc * DK * DK + (size_t)r * DK + lc);
            a.x += t4.x; a.y += t4.y; a.z += t4.z; a.w += t4.w;
        }
        *reinterpret_cast<float4*>(&Ms[r][lc]) = a;
    }
    __syncthreads();

    float acc[4][4];
    #pragma unroll
    for (int i = 0; i < 4; i++)
        #pragma unroll
        for (int j = 0; j < 4; j++) acc[i][j] = 0.0f;

    #pragma unroll 8
    for (int k = 0; k < 64; k++) {
        float qf[4], mf[4];
        #pragma unroll
        for (int i = 0; i < 4; i++) qf[i] = Qs[ty * 4 + i][k];
        #pragma unroll
        for (int j = 0; j < 4; j++) mf[j] = Ms[k][tx * 4 + j];
        #pragma unroll
        for (int i = 0; i < 4; i++)
            #pragma unroll
            for (int j = 0; j < 4; j++)
                acc[i][j] = fmaf(qf[i], mf[j], acc[i][j]);
    }

    #pragma unroll
    for (int i = 0; i < 4; i++) {
        __half2 p0 = __floats2half2_rn(acc[i][0] * 0.125f, acc[i][1] * 0.125f);
        __half2 p1 = __floats2half2_rn(acc[i][2] * 0.125f, acc[i][3] * 0.125f);
        uint2 u;
        u.x = *reinterpret_cast<uint32_t*>(&p0);
        u.y = *reinterpret_cast<uint32_t*>(&p1);
        *reinterpret_cast<uint2*>(Oh + obase + (size_t)(ty * 4 + i) * DM + tx * 4) = u;
    }
}

// ---------------------------------------------------------------------------
// Launch
// ---------------------------------------------------------------------------
extern "C" void kernel_launch(void* const* d_in, const int* in_sizes, int n_in,
                              void* d_out, int out_size)
{
    const float* x    = (const float*)d_in[0];
    const float* wq   = (const float*)d_in[2];
    const float* wk   = (const float*)d_in[3];
    const float* wv   = (const float*)d_in[4];
    const float* wo   = (const float*)d_in[5];
    const float* w1   = (const float*)d_in[6];
    const float* b1   = (const float*)d_in[7];
    const float* w2   = (const float*)d_in[8];
    const float* b2   = (const float*)d_in[9];
    const float* ln1a = (const float*)d_in[10];
    const float* ln1b = (const float*)d_in[11];
    const float* ln2a = (const float*)d_in[12];
    const float* ln2b = (const float*)d_in[13];
    float* out = (float*)d_out;

    half_t *xn1h,*xn2h,*oh,*h1h;
    half_t *wqkvTh,*wqkvTl,*woTh,*w1Th,*w2Th;
    float *qkv,*x1,*mpart;
    cudaGetSymbolAddress((void**)&xn1h, g_xn1h);
    cudaGetSymbolAddress((void**)&xn2h, g_xn2h);
    cudaGetSymbolAddress((void**)&oh,   g_oh);
    cudaGetSymbolAddress((void**)&h1h,  g_h1h);
    cudaGetSymbolAddress((void**)&qkv,  g_qkv);  cudaGetSymbolAddress((void**)&x1, g_x1);
    cudaGetSymbolAddress((void**)&mpart,g_mpart);
    cudaGetSymbolAddress((void**)&wqkvTh, g_wqkvTh); cudaGetSymbolAddress((void**)&wqkvTl, g_wqkvTl);
    cudaGetSymbolAddress((void**)&woTh, g_woTh);
    cudaGetSymbolAddress((void**)&w1Th, g_w1Th);
    cudaGetSymbolAddress((void**)&w2Th, g_w2Th);

    cudaFuncSetAttribute(gemm_tc<0,true>,  cudaFuncAttributeMaxDynamicSharedMemorySize, SMEM_TOTAL);
    cudaFuncSetAttribute(gemm_tc<1,false>, cudaFuncAttributeMaxDynamicSharedMemorySize, SMEM_TOTAL);
    cudaFuncSetAttribute(gemm_tc<2,false>, cudaFuncAttributeMaxDynamicSharedMemorySize, SMEM_TOTAL);
    cudaFuncSetAttribute(gemm_tc<3,false>, cudaFuncAttributeMaxDynamicSharedMemorySize, SMEM_TOTAL);

    int nsm = 148;
    cudaDeviceGetAttribute(&nsm, cudaDevAttrMultiProcessorCount, 0);

    // Transpose + split weights into [N, K] fp16 (hi/lo for QKV; hi-only others).
    tsplit_kernel<<<dim3(DM / 32, DM / 32), 256>>>(wq, wqkvTh,             wqkvTl,             DM, DM);
    tsplit_kernel<<<dim3(DM / 32, DM / 32), 256>>>(wk, wqkvTh + 1024 * DM, wqkvTl + 1024 * DM, DM, DM);
    tsplit_kernel<<<dim3(DM / 32, DM / 32), 256>>>(wv, wqkvTh + 2048 * DM, wqkvTl + 2048 * DM, DM, DM);
    tsplit_kernel<<<dim3(DM / 32, DM / 32), 256>>>(wo, woTh, nullptr, DM, DM);
    tsplit_kernel<<<dim3(DFF / 32, DM / 32), 256>>>(w1, w1Th, nullptr, DM, DFF);
    tsplit_kernel<<<dim3(DM / 32, DFF / 32), 256>>>(w2, w2Th, nullptr, DFF, DM);

    int tQKV = (NTOK / BM) * (QKVN / BN);   // 768
    int tDM  = (NTOK / BM) * (DM / BN);     // 256
    int tFF  = (NTOK / BM) * (DFF / BN);    // 1024
    int gQKV = tQKV < nsm ? tQKV : nsm;
    int gDM  = tDM  < nsm ? tDM  : nsm;
    int gFF  = tFF  < nsm ? tFF  : nsm;

    // 1) xn1 = LN(x) -> fp16
    ln_kernel<<<NTOK, 256>>>(x, ln1a, ln1b, xn1h);
    // 2) fused QKV projection (2-MMA, exact weights): qkv[M, 3072] fp32
    gemm_tc<0,true><<<gQKV, 256, SMEM_TOTAL>>>(
        xn1h, wqkvTh, wqkvTl, qkv, nullptr, QKVN, DM, tQKV, nullptr, nullptr);
    // 3) M = K^T V partials (linear attention; no softmax in reference)
    ktv_kernel<<<BATCH * NH * 8, 256>>>(qkv, mpart);
    // 4) O = Q @ M / 8 -> fp16
    qm_kernel<<<dim3(SEQ / 64, BATCH * NH), 256>>>(qkv, mpart, oh);
    // 5) x1 = x + O @ wo   (1-MMA)
    gemm_tc<1,false><<<gDM, 256, SMEM_TOTAL>>>(
        oh, woTh, nullptr, x1, nullptr, DM, DM, tDM, nullptr, x);
    // 6) xn2 = LN(x1) -> fp16
    ln_kernel<<<NTOK, 256>>>(x1, ln2a, ln2b, xn2h);
    // 7) h1 = relu(xn2 @ w1 + b1) -> fp16   (1-MMA)
    gemm_tc<2,false><<<gFF, 256, SMEM_TOTAL>>>(
        xn2h, w1Th, nullptr, nullptr, h1h, DFF, DM, tFF, b1, nullptr);
    // 8) out = x1 + h1 @ w2 + b2   (1-MMA)
    gemm_tc<3,false><<<gDM, 256, SMEM_TOTAL>>>(
        h1h, w2Th, nullptr, out, nullptr, DM, DFF, tDM, b2, x1);
}

// round 11
// speedup vs baseline: 1.5487x; 1.0784x over previous
#include <cuda_runtime.h>
#include <cuda_fp16.h>
#include <math.h>
#include <stdint.h>

typedef __half half_t;

// Problem constants
#define DM    1024
#define DFF   4096
#define NTOK  8192
#define SEQ   2048
#define BATCH 4
#define NH    16
#define DK    64
#define QKVN  3072
#define QKVS  3072

// GEMM tiling
#define BM 256
#define BN 128
#define BK 64
#define SMEM_TOTAL 197632
#define SWZ(x) ((x) ^ (((x) >> 3) & 0x70))

// SMEM slot offsets (3-stage ring): A 3 slots of 32KB at 1024;
// B(hi,lo) 6 slots of 16KB at 99328.
__device__ __forceinline__ uint32_t AOFFS(int buf) {
    return 1024u + (uint32_t)buf * 32768u;
}
__device__ __forceinline__ uint32_t BOFFS(int buf, int t) {
    return 99328u + (uint32_t)(buf * 2 + t) * 16384u;
}

// ---------------------------------------------------------------------------
// Scratch (device globals)
// ---------------------------------------------------------------------------
__device__ half_t g_xn1h[NTOK * DM];
__device__ half_t g_xn2h[NTOK * DM];
__device__ half_t g_oh  [NTOK * DM];
__device__ half_t g_h1h [NTOK * DFF];
__device__ float  g_qkv [NTOK * QKVS];
__device__ float  g_x1  [NTOK * DM];
__device__ float  g_mpart[BATCH * NH * 8 * DK * DK];
__device__ half_t g_wqkvTh[QKVN * DM];
__device__ half_t g_woTh[DM * DM];
__device__ half_t g_w1Th[DFF * DM];
__device__ half_t g_w2Th[DM * DFF];

// ---------------------------------------------------------------------------
// Helpers
// ---------------------------------------------------------------------------
__device__ __forceinline__ uint32_t smem_u32(const void* p) {
    return (uint32_t)__cvta_generic_to_shared(p);
}
__device__ __forceinline__ void cp16(uint32_t dst, const void* src) {
    asm volatile("cp.async.cg.shared.global [%0], [%1], 16;\n" :: "r"(dst), "l"(src));
}
__device__ __forceinline__ void ldmx4u(uint32_t* r, uint32_t addr) {
    asm volatile("ldmatrix.sync.aligned.m8n8.x4.shared.b16 {%0,%1,%2,%3}, [%4];\n"
                 : "=r"(r[0]), "=r"(r[1]), "=r"(r[2]), "=r"(r[3]) : "r"(addr));
}
__device__ __forceinline__ void mma16816h(float* d, const uint32_t* a, uint32_t b0, uint32_t b1) {
    asm volatile(
        "mma.sync.aligned.m16n8k16.row.col.f32.f16.f16.f32 "
        "{%0,%1,%2,%3},{%4,%5,%6,%7},{%8,%9},{%0,%1,%2,%3};\n"
        : "+f"(d[0]), "+f"(d[1]), "+f"(d[2]), "+f"(d[3])
        : "r"(a[0]), "r"(a[1]), "r"(a[2]), "r"(a[3]), "r"(b0), "r"(b1));
}

// ---------------------------------------------------------------------------
// Stage loader: A 256x64 + B 128x64 (hi [,lo]) fp16, SW128, cp.async.
// ---------------------------------------------------------------------------
template<bool BL>
__device__ __forceinline__ void stage_load(
    uint32_t smem_base,
    const half_t* __restrict__ Ah,
    const half_t* __restrict__ Bh, const half_t* __restrict__ Bl,
    int m0, int n0, int k0, int K, int tid, int buf)
{
    {
        uint32_t base = smem_base + AOFFS(buf);
        #pragma unroll
        for (int i = 0; i < 8; i++) {
            int chunk = tid + i * 256;
            int r = chunk >> 3, c = chunk & 7;
            uint32_t off = (uint32_t)(r * 128 + c * 16);
            cp16(base + SWZ(off), Ah + (size_t)(m0 + r) * K + k0 + c * 8);
        }
    }
    #pragma unroll
    for (int t = 0; t < (BL ? 2 : 1); t++) {
        const half_t* src = t ? Bl : Bh;
        uint32_t base = smem_base + BOFFS(buf, t);
        #pragma unroll
        for (int i = 0; i < 4; i++) {
            int chunk = tid + i * 256;
            int r = chunk >> 3, c = chunk & 7;
            uint32_t off = (uint32_t)(r * 128 + c * 16);
            cp16(base + SWZ(off), src + (size_t)(n0 + r) * K + k0 + c * 8);
        }
    }
}

// ===========================================================================
// tcgen05-only helpers (compiled only when an 'a' feature target exists)
// ===========================================================================
#if defined(__CUDA_ARCH_FEAT_SM103_ALL) || defined(__CUDA_ARCH_FEAT_SM100_ALL)
#define IDESC_F16 ((1u << 4) | (16u << 17) | (8u << 24))
__device__ __forceinline__ uint32_t elect_one() {
    uint32_t pred;
    asm volatile("{\n .reg .pred p;\n elect.sync _|p, 0xFFFFFFFF;\n selp.b32 %0, 1, 0, p;\n}"
                 : "=r"(pred));
    return pred;
}
__device__ __forceinline__ uint64_t make_desc(uint32_t addr) {
    return ((uint64_t)2 << 61) | ((uint64_t)1 << 46) | ((uint64_t)64 << 32) |
           ((uint64_t)1 << 16) | ((uint64_t)(addr >> 4) & 0x3FFF);
}
__device__ __forceinline__ void mma_f16_ss(uint32_t d, uint64_t a, uint64_t b,
                                           uint32_t idesc, bool en) {
    uint32_t e = en ? 1u : 0u;
    asm volatile(
        "{\n\t"
        ".reg .pred p;\n\t"
        "setp.ne.u32 p, %4, 0;\n\t"
        "tcgen05.mma.cta_group::1.kind::f16 [%0], %1, %2, %3, {%5,%5,%5,%5}, p;\n\t"
        "}"
        :: "r"(d), "l"(a), "l"(b), "r"(idesc), "r"(e), "r"(0u) : "memory");
}
__device__ __forceinline__ void mbar_init(uint32_t a, uint32_t c) {
    asm volatile("mbarrier.init.shared.b64 [%0], %1;" :: "r"(a), "r"(c) : "memory");
}
__device__ __forceinline__ void mbar_wait(uint32_t mbar, uint32_t parity) {
    asm volatile(
        "{\n\t"
        ".reg .pred P1;\n\t"
        "WAIT_LOOP_%=:\n\t"
        "mbarrier.try_wait.parity.acquire.cta.shared::cta.b64 P1, [%0], %1, 0x989680;\n\t"
        "@P1 bra.uni WAIT_DONE_%=;\n\t"
        "bra.uni WAIT_LOOP_%=;\n\t"
        "WAIT_DONE_%=:\n\t"
        "}" :: "r"(mbar), "r"(parity) : "memory");
}
#define TC_ALLOC(sm, n)  asm volatile("tcgen05.alloc.cta_group::1.sync.aligned.shared::cta.b32 [%0], %1;" :: "r"(sm), "r"((uint32_t)(n)) : "memory")
#define TC_RELINQ()      asm volatile("tcgen05.relinquish_alloc_permit.cta_group::1.sync.aligned;")
#define TC_DEALLOC(t, n) asm volatile("tcgen05.dealloc.cta_group::1.sync.aligned.b32 %0, %1;" :: "r"(t), "r"((uint32_t)(n)))
#define TC_COMMIT(mb)    asm volatile("tcgen05.commit.cta_group::1.mbarrier::arrive::one.shared::cluster.b64 [%0];" :: "r"(mb) : "memory")
#define TC_FENCE_AFTER() asm volatile("tcgen05.fence::after_thread_sync;" ::: "memory")
#define TC_FENCE_BEFORE() asm volatile("tcgen05.fence::before_thread_sync;" ::: "memory")
#define TC_WAIT_LD()     asm volatile("tcgen05.wait::ld.sync.aligned;" ::: "memory")
#define FENCE_ASYNC()    asm volatile("fence.proxy.async.shared::cta;" ::: "memory")
#define TC_LD_X32(r, ta) \
    asm volatile( \
        "tcgen05.ld.sync.aligned.32x32b.x32.b32 " \
        "{%0, %1, %2, %3, %4, %5, %6, %7, " \
        " %8, %9, %10, %11, %12, %13, %14, %15, " \
        " %16, %17, %18, %19, %20, %21, %22, %23, " \
        " %24, %25, %26, %27, %28, %29, %30, %31}, [%32];" \
        : "=r"((r)[0]),  "=r"((r)[1]),  "=r"((r)[2]),  "=r"((r)[3]), \
          "=r"((r)[4]),  "=r"((r)[5]),  "=r"((r)[6]),  "=r"((r)[7]), \
          "=r"((r)[8]),  "=r"((r)[9]),  "=r"((r)[10]), "=r"((r)[11]), \
          "=r"((r)[12]), "=r"((r)[13]), "=r"((r)[14]), "=r"((r)[15]), \
          "=r"((r)[16]), "=r"((r)[17]), "=r"((r)[18]), "=r"((r)[19]), \
          "=r"((r)[20]), "=r"((r)[21]), "=r"((r)[22]), "=r"((r)[23]), \
          "=r"((r)[24]), "=r"((r)[25]), "=r"((r)[26]), "=r"((r)[27]), \
          "=r"((r)[28]), "=r"((r)[29]), "=r"((r)[30]), "=r"((r)[31]) \
        : "r"(ta))
#endif

// ---------------------------------------------------------------------------
// Persistent GEMM, 256x128 tiles, fp16 (3-stage ring).
//   BL=1: D = a*bh + a*bl (2 MMA).  BL=0: D = a*bh (1 MMA).
// MODE: 0=plain fp32, 1=+resid fp32, 2=relu(D+bias)->fp16, 3=D+bias+resid fp32.
// ---------------------------------------------------------------------------
template<int MODE, bool BL>
__global__ __launch_bounds__(256)
void gemm_tc(
    const half_t* __restrict__ Ah,
    const half_t* __restrict__ Bh, const half_t* __restrict__ Bl,
    float* __restrict__ C, half_t* __restrict__ Ch,
    int N, int K, int ntiles,
    const float* __restrict__ bias, const float* __restrict__ resid)
{
    extern __shared__ char smem[];
    uint32_t smem_base = smem_u32(smem);
    int tid = threadIdx.x;
    int wid = tid >> 5, lane = tid & 31;
    int ntn = N / BN;
    int S = K / BK;
    constexpr int NSTAGE = 3;

#if defined(__CUDA_ARCH_FEAT_SM103_ALL) || defined(__CUDA_ARCH_FEAT_SM100_ALL)
    // ======================= tcgen05 path =======================
    if (wid == 0) { TC_ALLOC(smem_base, 512); }
    else if (wid == 1) { TC_RELINQ(); }
    if (tid == 0) { mbar_init(smem_base + 8, 1); mbar_init(smem_base + 16, 1); }
    __syncthreads();
    uint32_t tmem;
    asm volatile("ld.shared.b32 %0, [%1];" : "=r"(tmem) : "r"(smem_base));

    int g = 0, tcount = 0;
    for (int tl = blockIdx.x; tl < ntiles; tl += gridDim.x) {
        int m0 = (tl / ntn) * BM, n0 = (tl % ntn) * BN;
        int tp = tcount & 1; tcount++;
        for (int s = 0; s < S; s++, g++) {
            int buf = g % NSTAGE;
            int mb = g & 1;
            if (g >= 2) mbar_wait(smem_base + 8 + mb * 8, ((g - 2) >> 1) & 1);
            stage_load<BL>(smem_base, Ah, Bh, Bl, m0, n0, s * BK, K, tid, buf);
            asm volatile("cp.async.commit_group;\n");
            asm volatile("cp.async.wait_group 0;\n");
            __syncthreads();
            FENCE_ASYNC();
            if (wid == 0 && elect_one()) {
                TC_FENCE_AFTER();
                uint64_t aH = make_desc(smem_base + AOFFS(buf));
                uint64_t bH = make_desc(smem_base + BOFFS(buf, 0));
                uint64_t bL = make_desc(smem_base + BOFFS(buf, 1));
                #pragma unroll
                for (int ks = 0; ks < 4; ks++) {
                    #pragma unroll
                    for (int h = 0; h < 2; h++) {
                        uint64_t ah = aH + h * 1024 + ks * 2;
                        uint32_t d = tmem + tp * 256 + h * 128;
                        mma_f16_ss(d, ah, bH + ks * 2, IDESC_F16, !(s == 0 && ks == 0));
                        if (BL) mma_f16_ss(d, ah, bL + ks * 2, IDESC_F16, true);
                    }
                }
                TC_COMMIT(smem_base + 8 + mb * 8);
            }
        }
        {
            int mb = (g - 1) & 1;
            mbar_wait(smem_base + 8 + mb * 8, ((g - 1) >> 1) & 1);
        }
        TC_FENCE_AFTER();
        int half0 = wid >> 2;
        int grow = m0 + half0 * 128 + ((wid & 3) << 5) + lane;
        #pragma unroll
        for (int cb = 0; cb < 4; cb++) {
            uint32_t r[32];
            TC_LD_X32(r, tmem + tp * 256 + half0 * 128 + cb * 32);
            TC_WAIT_LD();
            int gcol = n0 + cb * 32;
            size_t base = (size_t)grow * N + gcol;
            #pragma unroll
            for (int j = 0; j < 32; j += 4) {
                float v0 = __uint_as_float(r[j]);
                float v1 = __uint_as_float(r[j + 1]);
                float v2 = __uint_as_float(r[j + 2]);
                float v3 = __uint_as_float(r[j + 3]);
                if (MODE == 2 || MODE == 3) {
                    float4 bb = *reinterpret_cast<const float4*>(bias + gcol + j);
                    v0 += bb.x; v1 += bb.y; v2 += bb.z; v3 += bb.w;
                }
                if (MODE == 2) {
                    v0 = fmaxf(v0, 0.f); v1 = fmaxf(v1, 0.f);
                    v2 = fmaxf(v2, 0.f); v3 = fmaxf(v3, 0.f);
                }
                if (MODE == 1 || MODE == 3) {
                    float4 rr = *reinterpret_cast<const float4*>(resid + base + j);
                    v0 += rr.x; v1 += rr.y; v2 += rr.z; v3 += rr.w;
                }
                if (MODE == 2) {
                    __half2 p0 = __floats2half2_rn(v0, v1);
                    __half2 p1 = __floats2half2_rn(v2, v3);
                    uint2 u;
                    u.x = *reinterpret_cast<uint32_t*>(&p0);
                    u.y = *reinterpret_cast<uint32_t*>(&p1);
                    *reinterpret_cast<uint2*>(Ch + base + j) = u;
                } else {
                    float4 o; o.x = v0; o.y = v1; o.z = v2; o.w = v3;
                    *reinterpret_cast<float4*>(C + base + j) = o;
                }
            }
        }
        TC_FENCE_BEFORE();
        __syncthreads();
    }
    __syncthreads();
    if (wid == 0) { TC_DEALLOC(tmem, 512); }

#else
    // ======================= mma.sync path =======================
    int wm = wid & 3, wn = wid >> 2;
    int arow = wm * 64 + (lane & 15);
    int brow = wn * 64 + (lane & 15);

    for (int tl = blockIdx.x; tl < ntiles; tl += gridDim.x) {
        int m0 = (tl / ntn) * BM, n0 = (tl % ntn) * BN;

        float acc[4][8][4];
        #pragma unroll
        for (int i = 0; i < 4; i++)
            #pragma unroll
            for (int j = 0; j < 8; j++)
                #pragma unroll
                for (int d = 0; d < 4; d++) acc[i][j][d] = 0.0f;

        #pragma unroll
        for (int p = 0; p < NSTAGE - 1; p++) {
            stage_load<BL>(smem_base, Ah, Bh, Bl, m0, n0, p * BK, K, tid, p);
            asm volatile("cp.async.commit_group;\n");
        }

        for (int s = 0; s < S; s++) {
            if (s + NSTAGE - 1 <= S) {
                asm volatile("cp.async.wait_group %0;\n" :: "n"(NSTAGE - 2));
            } else {
                asm volatile("cp.async.wait_group 0;\n");
            }
            __syncthreads();
            if (s + NSTAGE - 1 < S) {
                stage_load<BL>(smem_base, Ah, Bh, Bl, m0, n0,
                               (s + NSTAGE - 1) * BK, K, tid, (s + NSTAGE - 1) % NSTAGE);
                asm volatile("cp.async.commit_group;\n");
            }
            int buf = s % NSTAGE;
            uint32_t aHb = smem_base + AOFFS(buf);
            uint32_t bHb = smem_base + BOFFS(buf, 0);
            uint32_t bLb = smem_base + BOFFS(buf, 1);

            #pragma unroll
            for (int ks = 0; ks < 4; ks++) {
                int colb = ks * 32 + (lane >> 4) * 16;
                uint32_t fa[4][4], fbH[4][4];
                #pragma unroll
                for (int mi = 0; mi < 4; mi++) {
                    uint32_t off = (uint32_t)((arow + mi * 16) * 128 + colb);
                    ldmx4u(fa[mi], aHb + SWZ(off));
                }
                #pragma unroll
                for (int ni = 0; ni < 4; ni++) {
                    uint32_t off = (uint32_t)((brow + ni * 16) * 128 + colb);
                    ldmx4u(fbH[ni], bHb + SWZ(off));
                }
                // a * b_hi
                #pragma unroll
                for (int mi = 0; mi < 4; mi++)
                    #pragma unroll
                    for (int ni = 0; ni < 4; ni++) {
                        mma16816h(acc[mi][2 * ni],     fa[mi], fbH[ni][0], fbH[ni][2]);
                        mma16816h(acc[mi][2 * ni + 1], fa[mi], fbH[ni][1], fbH[ni][3]);
                    }
                if (BL) {
                    // a * b_lo (reuse fbH regs)
                    #pragma unroll
                    for (int ni = 0; ni < 4; ni++) {
                        uint32_t off = (uint32_t)((brow + ni * 16) * 128 + colb);
                        ldmx4u(fbH[ni], bLb + SWZ(off));
                    }
                    #pragma unroll
                    for (int mi = 0; mi < 4; mi++)
                        #pragma unroll
                        for (int ni = 0; ni < 4; ni++) {
                            mma16816h(acc[mi][2 * ni],     fa[mi], fbH[ni][0], fbH[ni][2]);
                            mma16816h(acc[mi][2 * ni + 1], fa[mi], fbH[ni][1], fbH[ni][3]);
                        }
                }
            }
        }

        // Epilogue
        int r0 = lane >> 2, c0 = (lane & 3) * 2;
        #pragma unroll
        for (int mi = 0; mi < 4; mi++) {
            #pragma unroll
            for (int t = 0; t < 8; t++) {
                int col = n0 + wn * 64 + t * 8 + c0;
                #pragma unroll
                for (int hh = 0; hh < 2; hh++) {
                    int row = m0 + wm * 64 + mi * 16 + r0 + hh * 8;
                    float v0 = acc[mi][t][hh * 2];
                    float v1 = acc[mi][t][hh * 2 + 1];
                    size_t base = (size_t)row * N + col;
                    if (MODE == 2 || MODE == 3) { v0 += bias[col]; v1 += bias[col + 1]; }
                    if (MODE == 2) { v0 = fmaxf(v0, 0.f); v1 = fmaxf(v1, 0.f); }
                    if (MODE == 1 || MODE == 3) {
                        float2 rr = *reinterpret_cast<const float2*>(resid + base);
                        v0 += rr.x; v1 += rr.y;
                    }
                    if (MODE == 2) {
                        __half2 hp = __floats2half2_rn(v0, v1);
                        *reinterpret_cast<uint32_t*>(Ch + base) = *reinterpret_cast<uint32_t*>(&hp);
                    } else {
                        float2 o; o.x = v0; o.y = v1;
                        *reinterpret_cast<float2*>(C + base) = o;
                    }
                }
            }
        }
        __syncthreads();
    }
#endif
}

// ---------------------------------------------------------------------------
// Weight transpose + fp16 convert: w[K,N] fp32 -> out[N,K] fp16 (hi only).
// 64x64 tile per block; both gmem sides coalesced (float4 in, uint4 out).
// ---------------------------------------------------------------------------
__global__ __launch_bounds__(256) void tsplit_kernel(
    const float* __restrict__ w, half_t* __restrict__ oh, int K, int N)
{
    __shared__ float tile[64][65];
    int k0 = blockIdx.y * 64, n0 = blockIdx.x * 64;
    int t = threadIdx.x;
    int lr = t >> 4;            // 0..15
    int lc = (t & 15) * 4;      // 0..60
    #pragma unroll
    for (int i = 0; i < 4; i++) {
        int r = lr + i * 16;
        float4 v = *reinterpret_cast<const float4*>(w + (size_t)(k0 + r) * N + n0 + lc);
        tile[r][lc] = v.x; tile[r][lc + 1] = v.y;
        tile[r][lc + 2] = v.z; tile[r][lc + 3] = v.w;
    }
    __syncthreads();
    #pragma unroll
    for (int o = 0; o < 2; o++) {
        int t2 = t + o * 256;
        int n = t2 >> 3;          // 0..63
        int k8 = (t2 & 7) * 8;    // 0..56
        __half2 h0 = __floats2half2_rn(tile[k8 + 0][n], tile[k8 + 1][n]);
        __half2 h1 = __floats2half2_rn(tile[k8 + 2][n], tile[k8 + 3][n]);
        __half2 h2 = __floats2half2_rn(tile[k8 + 4][n], tile[k8 + 5][n]);
        __half2 h3 = __floats2half2_rn(tile[k8 + 6][n], tile[k8 + 7][n]);
        uint4 u;
        u.x = *reinterpret_cast<uint32_t*>(&h0);
        u.y = *reinterpret_cast<uint32_t*>(&h1);
        u.z = *reinterpret_cast<uint32_t*>(&h2);
        u.w = *reinterpret_cast<uint32_t*>(&h3);
        *reinterpret_cast<uint4*>(oh + (size_t)(n0 + n) * K + k0 + k8) = u;
    }
}

// ---------------------------------------------------------------------------
// LayerNorm (ddof=1, eps on STD), fp16 output.
// ---------------------------------------------------------------------------
__global__ __launch_bounds__(256) void ln_kernel(
    const float* __restrict__ x, const float* __restrict__ alpha,
    const float* __restrict__ bias, half_t* __restrict__ yh)
{
    int row = blockIdx.x;
    int t = threadIdx.x;
    float4 v = reinterpret_cast<const float4*>(x + (size_t)row * DM)[t];
    float s  = v.x + v.y + v.z + v.w;
    float ss = v.x*v.x + v.y*v.y + v.z*v.z + v.w*v.w;

    __shared__ float reds[8], redss[8], bcast[2];
    #pragma unroll
    for (int off = 16; off; off >>= 1) {
        s  += __shfl_xor_sync(0xffffffffu, s,  off);
        ss += __shfl_xor_sync(0xffffffffu, ss, off);
    }
    int wid = t >> 5, lid = t & 31;
    if (lid == 0) { reds[wid] = s; redss[wid] = ss; }
    __syncthreads();
    if (t == 0) {
        float S = 0.f, SS = 0.f;
        #pragma unroll
        for (int i = 0; i < 8; i++) { S += reds[i]; SS += redss[i]; }
        float mean = S * (1.0f / DM);
        float var = (SS - (float)DM * mean * mean) * (1.0f / (DM - 1));
        var = fmaxf(var, 0.0f);
        bcast[0] = mean;
        bcast[1] = 1.0f / (sqrtf(var) + 1e-6f);
    }
    __syncthreads();
    float mean = bcast[0], inv = bcast[1];

    float4 av = reinterpret_cast<const float4*>(alpha)[t];
    float4 bv = reinterpret_cast<const float4*>(bias)[t];
    float o0 = av.x * (v.x - mean) * inv + bv.x;
    float o1 = av.y * (v.y - mean) * inv + bv.y;
    float o2 = av.z * (v.z - mean) * inv + bv.z;
    float o3 = av.w * (v.w - mean) * inv + bv.w;
    __half2 p0 = __floats2half2_rn(o0, o1);
    __half2 p1 = __floats2half2_rn(o2, o3);
    uint2 u;
    u.x = *reinterpret_cast<uint32_t*>(&p0);
    u.y = *reinterpret_cast<uint32_t*>(&p1);
    *reinterpret_cast<uint2*>(yh + (size_t)row * DM + t * 4) = u;
}

// ---------------------------------------------------------------------------
// KtV partial: per (b,h,chunk of 256 seq rows), Mpart[64,64] = K^T V (fp32).
// ---------------------------------------------------------------------------
__global__ __launch_bounds__(256) void ktv_kernel(
    const float* __restrict__ qkv, float* __restrict__ Mpart)
{
    int bh = blockIdx.x >> 3, cch = blockIdx.x & 7;
    int b = bh >> 4, h = bh & 15;
    const float* Kb = qkv + (size_t)b * SEQ * QKVS + 1024 + h * DK;
    const float* Vb = qkv + (size_t)b * SEQ * QKVS + 2048 + h * DK;

    __shared__ float Ks[64][68];
    __shared__ float Vs[64][68];

    int tid = threadIdx.x;
    int tx = tid & 15, ty = tid >> 4;
    int lr = tid >> 4;
    int lc = (tid & 15) << 2;

    float acc[4][4];
    #pragma unroll
    for (int i = 0; i < 4; i++)
        #pragma unroll
        for (int j = 0; j < 4; j++) acc[i][j] = 0.0f;

    int sbeg = cch * 256;
    for (int s0 = sbeg; s0 < sbeg + 256; s0 += 64) {
        __syncthreads();
        #pragma unroll
        for (int p = 0; p < 4; p++) {
            int r = lr + p * 16;
            *reinterpret_cast<float4*>(&Ks[r][lc]) =
                *reinterpret_cast<const float4*>(Kb + (size_t)(s0 + r) * QKVS + lc);
            *reinterpret_cast<float4*>(&Vs[r][lc]) =
                *reinterpret_cast<const float4*>(Vb + (size_t)(s0 + r) * QKVS + lc);
        }
        __syncthreads();
        #pragma unroll 8
        for (int s = 0; s < 64; s++) {
            float kf[4], vf[4];
            #pragma unroll
            for (int i = 0; i < 4; i++) kf[i] = Ks[s][ty * 4 + i];
            #pragma unroll
            for (int j = 0; j < 4; j++) vf[j] = Vs[s][tx * 4 + j];
            #pragma unroll
            for (int i = 0; i < 4; i++)
                #pragma unroll
                for (int j = 0; j < 4; j++)
                    acc[i][j] = fmaf(kf[i], vf[j], acc[i][j]);
        }
    }

    float* Mb = Mpart + (size_t)blockIdx.x * DK * DK;
    #pragma unroll
    for (int i = 0; i < 4; i++)
        #pragma unroll
        for (int j = 0; j < 4; j++)
            Mb[(ty * 4 + i) * DK + (tx * 4 + j)] = acc[i][j];
}

// ---------------------------------------------------------------------------
// QM: O_bh = (Q_bh @ sum_c Mpart_bh_c) * 0.125, output fp16.
// ---------------------------------------------------------------------------
__global__ __launch_bounds__(256) void qm_kernel(
    const float* __restrict__ qkv, const float* __restrict__ Mp,
    half_t* __restrict__ Oh)
{
    int bh = blockIdx.y;
    int b = bh >> 4, h = bh & 15;
    int rt = blockIdx.x;
    const float* Qb = qkv + (size_t)b * SEQ * QKVS + (size_t)rt * 64 * QKVS + h * DK;
    const float* Mb = Mp + (size_t)bh * 8 * DK * DK;
    size_t obase = (size_t)b * SEQ * DM + (size_t)rt * 64 * DM + h * DK;

    __shared__ float Qs[64][68];
    __shared__ float Ms[64][68];

    int tid = threadIdx.x;
    int tx = tid & 15, ty = tid >> 4;
    int lr = tid >> 4;
    int lc = (tid & 15) << 2;

    #pragma unroll
    for (int p = 0; p < 4; p++) {
        int r = lr + p * 16;
        *reinterpret_cast<float4*>(&Qs[r][lc]) =
            *reinterpret_cast<const float4*>(Qb + (size_t)r * QKVS + lc);
        float4 a = make_float4(0.f, 0.f, 0.f, 0.f);
        #pragma unroll
        for (int cc = 0; cc < 8; cc++) {
            float4 t4 = *reinterpret_cast<const float4*>(Mb + (size_t)cc * DK * DK + (size_t)r * DK + lc);
            a.x += t4.x; a.y += t4.y; a.z += t4.z; a.w += t4.w;
        }
        *reinterpret_cast<float4*>(&Ms[r][lc]) = a;
    }
    __syncthreads();

    float acc[4][4];
    #pragma unroll
    for (int i = 0; i < 4; i++)
        #pragma unroll
        for (int j = 0; j < 4; j++) acc[i][j] = 0.0f;

    #pragma unroll 8
    for (int k = 0; k < 64; k++) {
        float qf[4], mf[4];
        #pragma unroll
        for (int i = 0; i < 4; i++) qf[i] = Qs[ty * 4 + i][k];
        #pragma unroll
        for (int j = 0; j < 4; j++) mf[j] = Ms[k][tx * 4 + j];
        #pragma unroll
        for (int i = 0; i < 4; i++)
            #pragma unroll
            for (int j = 0; j < 4; j++)
                acc[i][j] = fmaf(qf[i], mf[j], acc[i][j]);
    }

    #pragma unroll
    for (int i = 0; i < 4; i++) {
        __half2 p0 = __floats2half2_rn(acc[i][0] * 0.125f, acc[i][1] * 0.125f);
        __half2 p1 = __floats2half2_rn(acc[i][2] * 0.125f, acc[i][3] * 0.125f);
        uint2 u;
        u.x = *reinterpret_cast<uint32_t*>(&p0);
        u.y = *reinterpret_cast<uint32_t*>(&p1);
        *reinterpret_cast<uint2*>(Oh + obase + (size_t)(ty * 4 + i) * DM + tx * 4) = u;
    }
}

// ---------------------------------------------------------------------------
// Launch
// ---------------------------------------------------------------------------
extern "C" void kernel_launch(void* const* d_in, const int* in_sizes, int n_in,
                              void* d_out, int out_size)
{
    const float* x    = (const float*)d_in[0];
    const float* wq   = (const float*)d_in[2];
    const float* wk   = (const float*)d_in[3];
    const float* wv   = (const float*)d_in[4];
    const float* wo   = (const float*)d_in[5];
    const float* w1   = (const float*)d_in[6];
    const float* b1   = (const float*)d_in[7];
    const float* w2   = (const float*)d_in[8];
    const float* b2   = (const float*)d_in[9];
    const float* ln1a = (const float*)d_in[10];
    const float* ln1b = (const float*)d_in[11];
    const float* ln2a = (const float*)d_in[12];
    const float* ln2b = (const float*)d_in[13];
    float* out = (float*)d_out;

    half_t *xn1h,*xn2h,*oh,*h1h;
    half_t *wqkvTh,*woTh,*w1Th,*w2Th;
    float *qkv,*x1,*mpart;
    cudaGetSymbolAddress((void**)&xn1h, g_xn1h);
    cudaGetSymbolAddress((void**)&xn2h, g_xn2h);
    cudaGetSymbolAddress((void**)&oh,   g_oh);
    cudaGetSymbolAddress((void**)&h1h,  g_h1h);
    cudaGetSymbolAddress((void**)&qkv,  g_qkv);  cudaGetSymbolAddress((void**)&x1, g_x1);
    cudaGetSymbolAddress((void**)&mpart,g_mpart);
    cudaGetSymbolAddress((void**)&wqkvTh, g_wqkvTh);
    cudaGetSymbolAddress((void**)&woTh, g_woTh);
    cudaGetSymbolAddress((void**)&w1Th, g_w1Th);
    cudaGetSymbolAddress((void**)&w2Th, g_w2Th);

    cudaFuncSetAttribute(gemm_tc<0,false>, cudaFuncAttributeMaxDynamicSharedMemorySize, SMEM_TOTAL);
    cudaFuncSetAttribute(gemm_tc<1,false>, cudaFuncAttributeMaxDynamicSharedMemorySize, SMEM_TOTAL);
    cudaFuncSetAttribute(gemm_tc<2,false>, cudaFuncAttributeMaxDynamicSharedMemorySize, SMEM_TOTAL);
    cudaFuncSetAttribute(gemm_tc<3,false>, cudaFuncAttributeMaxDynamicSharedMemorySize, SMEM_TOTAL);

    int nsm = 148;
    cudaDeviceGetAttribute(&nsm, cudaDevAttrMultiProcessorCount, 0);

    // Transpose + convert weights into [N, K] fp16 (hi only).
    tsplit_kernel<<<dim3(DM / 64, DM / 64), 256>>>(wq, wqkvTh,             DM, DM);
    tsplit_kernel<<<dim3(DM / 64, DM / 64), 256>>>(wk, wqkvTh + 1024 * DM, DM, DM);
    tsplit_kernel<<<dim3(DM / 64, DM / 64), 256>>>(wv, wqkvTh + 2048 * DM, DM, DM);
    tsplit_kernel<<<dim3(DM / 64, DM / 64), 256>>>(wo, woTh, DM, DM);
    tsplit_kernel<<<dim3(DFF / 64, DM / 64), 256>>>(w1, w1Th, DM, DFF);
    tsplit_kernel<<<dim3(DM / 64, DFF / 64), 256>>>(w2, w2Th, DFF, DM);

    int tQKV = (NTOK / BM) * (QKVN / BN);   // 768
    int tDM  = (NTOK / BM) * (DM / BN);     // 256
    int tFF  = (NTOK / BM) * (DFF / BN);    // 1024
    int gQKV = tQKV < nsm ? tQKV : nsm;
    int gDM  = tDM  < nsm ? tDM  : nsm;
    int gFF  = tFF  < nsm ? tFF  : nsm;

    // 1) xn1 = LN(x) -> fp16
    ln_kernel<<<NTOK, 256>>>(x, ln1a, ln1b, xn1h);
    // 2) fused QKV projection (1-MMA): qkv[M, 3072] fp32
    gemm_tc<0,false><<<gQKV, 256, SMEM_TOTAL>>>(
        xn1h, wqkvTh, nullptr, qkv, nullptr, QKVN, DM, tQKV, nullptr, nullptr);
    // 3) M = K^T V partials (linear attention; no softmax in reference)
    ktv_kernel<<<BATCH * NH * 8, 256>>>(qkv, mpart);
    // 4) O = Q @ M / 8 -> fp16
    qm_kernel<<<dim3(SEQ / 64, BATCH * NH), 256>>>(qkv, mpart, oh);
    // 5) x1 = x + O @ wo   (1-MMA)
    gemm_tc<1,false><<<gDM, 256, SMEM_TOTAL>>>(
        oh, woTh, nullptr, x1, nullptr, DM, DM, tDM, nullptr, x);
    // 6) xn2 = LN(x1) -> fp16
    ln_kernel<<<NTOK, 256>>>(x1, ln2a, ln2b, xn2h);
    // 7) h1 = relu(xn2 @ w1 + b1) -> fp16   (1-MMA)
    gemm_tc<2,false><<<gFF, 256, SMEM_TOTAL>>>(
        xn2h, w1Th, nullptr, nullptr, h1h, DFF, DM, tFF, b1, nullptr);
    // 8) out = x1 + h1 @ w2 + b2   (1-MMA)
    gemm_tc<3,false><<<gDM, 256, SMEM_TOTAL>>>(
        h1h, w2Th, nullptr, out, nullptr, DM, DFF, tDM, b2, x1);
}

// round 13
// speedup vs baseline: 1.8262x; 1.1792x over previous
#include <cuda_runtime.h>
#include <cuda_fp16.h>
#include <math.h>
#include <stdint.h>

typedef __half half_t;

// Problem constants
#define DM    1024
#define DFF   4096
#define NTOK  8192
#define SEQ   2048
#define BATCH 4
#define NH    16
#define DK    64
#define QKVN  3072
#define QKVS  3072

// GEMM tiling: 256x128 CTA tile, BK=128 per stage (2 sub-tiles of 64),
// 2-stage ring. SMEM: A 2x64KB at 1024; B 2x32KB at 132096.
#define BM 256
#define BN 128
#define BK 128
#define SMEM_TOTAL 197632
#define SWZ(x) ((x) ^ (((x) >> 3) & 0x70))

__device__ __forceinline__ uint32_t AOFFS(int buf, int sub) {
    return 1024u + (uint32_t)buf * 65536u + (uint32_t)sub * 32768u;
}
__device__ __forceinline__ uint32_t BOFFS(int buf, int sub) {
    return 132096u + (uint32_t)buf * 32768u + (uint32_t)sub * 16384u;
}

// ---------------------------------------------------------------------------
// Scratch (device globals)
// ---------------------------------------------------------------------------
__device__ half_t g_xn1h[NTOK * DM];
__device__ half_t g_xn2h[NTOK * DM];
__device__ half_t g_oh  [NTOK * DM];
__device__ half_t g_h1h [NTOK * DFF];
__device__ float  g_qkv [NTOK * QKVS];
__device__ float  g_x1  [NTOK * DM];
__device__ float  g_mpart[BATCH * NH * 8 * DK * DK];
__device__ half_t g_wqkvTh[QKVN * DM];
__device__ half_t g_woTh[DM * DM];
__device__ half_t g_w1Th[DFF * DM];
__device__ half_t g_w2Th[DM * DFF];

// ---------------------------------------------------------------------------
// Helpers
// ---------------------------------------------------------------------------
__device__ __forceinline__ uint32_t smem_u32(const void* p) {
    return (uint32_t)__cvta_generic_to_shared(p);
}
__device__ __forceinline__ void cp16(uint32_t dst, const void* src) {
    asm volatile("cp.async.cg.shared.global [%0], [%1], 16;\n" :: "r"(dst), "l"(src));
}
__device__ __forceinline__ void ldmx4u(uint32_t* r, uint32_t addr) {
    asm volatile("ldmatrix.sync.aligned.m8n8.x4.shared.b16 {%0,%1,%2,%3}, [%4];\n"
                 : "=r"(r[0]), "=r"(r[1]), "=r"(r[2]), "=r"(r[3]) : "r"(addr));
}
__device__ __forceinline__ void mma16816h(float* d, const uint32_t* a, uint32_t b0, uint32_t b1) {
    asm volatile(
        "mma.sync.aligned.m16n8k16.row.col.f32.f16.f16.f32 "
        "{%0,%1,%2,%3},{%4,%5,%6,%7},{%8,%9},{%0,%1,%2,%3};\n"
        : "+f"(d[0]), "+f"(d[1]), "+f"(d[2]), "+f"(d[3])
        : "r"(a[0]), "r"(a[1]), "r"(a[2]), "r"(a[3]), "r"(b0), "r"(b1));
}

// ---------------------------------------------------------------------------
// Stage loader: A 256x128 + B 128x128 fp16 (two 64-col sub-tiles each),
// SW128, cp.async. 24 cp.async per thread.
// ---------------------------------------------------------------------------
__device__ __forceinline__ void stage_load(
    uint32_t smem_base,
    const half_t* __restrict__ Ah, const half_t* __restrict__ Bh,
    int m0, int n0, int k0, int K, int tid, int buf)
{
    #pragma unroll
    for (int sub = 0; sub < 2; sub++) {
        uint32_t abase = smem_base + AOFFS(buf, sub);
        const half_t* asrc = Ah + (size_t)m0 * K + k0 + sub * 64;
        #pragma unroll
        for (int i = 0; i < 8; i++) {
            int chunk = tid + i * 256;
            int r = chunk >> 3, c = chunk & 7;
            uint32_t off = (uint32_t)(r * 128 + c * 16);
            cp16(abase + SWZ(off), asrc + (size_t)r * K + c * 8);
        }
        uint32_t bbase = smem_base + BOFFS(buf, sub);
        const half_t* bsrc = Bh + (size_t)n0 * K + k0 + sub * 64;
        #pragma unroll
        for (int i = 0; i < 4; i++) {
            int chunk = tid + i * 256;
            int r = chunk >> 3, c = chunk & 7;
            uint32_t off = (uint32_t)(r * 128 + c * 16);
            cp16(bbase + SWZ(off), bsrc + (size_t)r * K + c * 8);
        }
    }
}

// ===========================================================================
// tcgen05-only helpers (compiled only when an 'a' feature target exists)
// ===========================================================================
#if defined(__CUDA_ARCH_FEAT_SM103_ALL) || defined(__CUDA_ARCH_FEAT_SM100_ALL)
#define IDESC_F16 ((1u << 4) | (16u << 17) | (8u << 24))
__device__ __forceinline__ uint32_t elect_one() {
    uint32_t pred;
    asm volatile("{\n .reg .pred p;\n elect.sync _|p, 0xFFFFFFFF;\n selp.b32 %0, 1, 0, p;\n}"
                 : "=r"(pred));
    return pred;
}
__device__ __forceinline__ uint64_t make_desc(uint32_t addr) {
    return ((uint64_t)2 << 61) | ((uint64_t)1 << 46) | ((uint64_t)64 << 32) |
           ((uint64_t)1 << 16) | ((uint64_t)(addr >> 4) & 0x3FFF);
}
__device__ __forceinline__ void mma_f16_ss(uint32_t d, uint64_t a, uint64_t b,
                                           uint32_t idesc, bool en) {
    uint32_t e = en ? 1u : 0u;
    asm volatile(
        "{\n\t"
        ".reg .pred p;\n\t"
        "setp.ne.u32 p, %4, 0;\n\t"
        "tcgen05.mma.cta_group::1.kind::f16 [%0], %1, %2, %3, {%5,%5,%5,%5}, p;\n\t"
        "}"
        :: "r"(d), "l"(a), "l"(b), "r"(idesc), "r"(e), "r"(0u) : "memory");
}
__device__ __forceinline__ void mbar_init(uint32_t a, uint32_t c) {
    asm volatile("mbarrier.init.shared.b64 [%0], %1;" :: "r"(a), "r"(c) : "memory");
}
__device__ __forceinline__ void mbar_wait(uint32_t mbar, uint32_t parity) {
    asm volatile(
        "{\n\t"
        ".reg .pred P1;\n\t"
        "WAIT_LOOP_%=:\n\t"
        "mbarrier.try_wait.parity.acquire.cta.shared::cta.b64 P1, [%0], %1, 0x989680;\n\t"
        "@P1 bra.uni WAIT_DONE_%=;\n\t"
        "bra.uni WAIT_LOOP_%=;\n\t"
        "WAIT_DONE_%=:\n\t"
        "}" :: "r"(mbar), "r"(parity) : "memory");
}
#define TC_ALLOC(sm, n)  asm volatile("tcgen05.alloc.cta_group::1.sync.aligned.shared::cta.b32 [%0], %1;" :: "r"(sm), "r"((uint32_t)(n)) : "memory")
#define TC_RELINQ()      asm volatile("tcgen05.relinquish_alloc_permit.cta_group::1.sync.aligned;")
#define TC_DEALLOC(t, n) asm volatile("tcgen05.dealloc.cta_group::1.sync.aligned.b32 %0, %1;" :: "r"(t), "r"((uint32_t)(n)))
#define TC_COMMIT(mb)    asm volatile("tcgen05.commit.cta_group::1.mbarrier::arrive::one.shared::cluster.b64 [%0];" :: "r"(mb) : "memory")
#define TC_FENCE_AFTER() asm volatile("tcgen05.fence::after_thread_sync;" ::: "memory")
#define TC_FENCE_BEFORE() asm volatile("tcgen05.fence::before_thread_sync;" ::: "memory")
#define TC_WAIT_LD()     asm volatile("tcgen05.wait::ld.sync.aligned;" ::: "memory")
#define FENCE_ASYNC()    asm volatile("fence.proxy.async.shared::cta;" ::: "memory")
#define TC_LD_X32(r, ta) \
    asm volatile( \
        "tcgen05.ld.sync.aligned.32x32b.x32.b32 " \
        "{%0, %1, %2, %3, %4, %5, %6, %7, " \
        " %8, %9, %10, %11, %12, %13, %14, %15, " \
        " %16, %17, %18, %19, %20, %21, %22, %23, " \
        " %24, %25, %26, %27, %28, %29, %30, %31}, [%32];" \
        : "=r"((r)[0]),  "=r"((r)[1]),  "=r"((r)[2]),  "=r"((r)[3]), \
          "=r"((r)[4]),  "=r"((r)[5]),  "=r"((r)[6]),  "=r"((r)[7]), \
          "=r"((r)[8]),  "=r"((r)[9]),  "=r"((r)[10]), "=r"((r)[11]), \
          "=r"((r)[12]), "=r"((r)[13]), "=r"((r)[14]), "=r"((r)[15]), \
          "=r"((r)[16]), "=r"((r)[17]), "=r"((r)[18]), "=r"((r)[19]), \
          "=r"((r)[20]), "=r"((r)[21]), "=r"((r)[22]), "=r"((r)[23]), \
          "=r"((r)[24]), "=r"((r)[25]), "=r"((r)[26]), "=r"((r)[27]), \
          "=r"((r)[28]), "=r"((r)[29]), "=r"((r)[30]), "=r"((r)[31]) \
        : "r"(ta))
#endif

// ---------------------------------------------------------------------------
// Persistent GEMM, 256x128 tiles, single fp16 MMA, BK=128, 2-stage.
// MODE: 0=plain fp32, 1=+resid fp32, 2=relu(D+bias)->fp16, 3=D+bias+resid fp32.
// ---------------------------------------------------------------------------
template<int MODE>
__global__ __launch_bounds__(256)
void gemm_tc(
    const half_t* __restrict__ Ah, const half_t* __restrict__ Bh,
    float* __restrict__ C, half_t* __restrict__ Ch,
    int N, int K, int ntiles,
    const float* __restrict__ bias, const float* __restrict__ resid)
{
    extern __shared__ char smem[];
    uint32_t smem_base = smem_u32(smem);
    int tid = threadIdx.x;
    int wid = tid >> 5, lane = tid & 31;
    int ntn = N / BN;
    int S = K / BK;

#if defined(__CUDA_ARCH_FEAT_SM103_ALL) || defined(__CUDA_ARCH_FEAT_SM100_ALL)
    // ======================= tcgen05 path =======================
    if (wid == 0) { TC_ALLOC(smem_base, 512); }
    else if (wid == 1) { TC_RELINQ(); }
    if (tid == 0) { mbar_init(smem_base + 8, 1); mbar_init(smem_base + 16, 1); }
    __syncthreads();
    uint32_t tmem;
    asm volatile("ld.shared.b32 %0, [%1];" : "=r"(tmem) : "r"(smem_base));

    int g = 0, tcount = 0;
    for (int tl = blockIdx.x; tl < ntiles; tl += gridDim.x) {
        int m0 = (tl / ntn) * BM, n0 = (tl % ntn) * BN;
        int tp = tcount & 1; tcount++;
        for (int s = 0; s < S; s++, g++) {
            int buf = g & 1;
            if (g >= 2) mbar_wait(smem_base + 8 + buf * 8, ((g - 2) >> 1) & 1);
            stage_load(smem_base, Ah, Bh, m0, n0, s * BK, K, tid, buf);
            asm volatile("cp.async.commit_group;\n");
            asm volatile("cp.async.wait_group 0;\n");
            __syncthreads();
            FENCE_ASYNC();
            if (wid == 0 && elect_one()) {
                TC_FENCE_AFTER();
                #pragma unroll
                for (int sub = 0; sub < 2; sub++) {
                    uint64_t aH = make_desc(smem_base + AOFFS(buf, sub));
                    uint64_t bH = make_desc(smem_base + BOFFS(buf, sub));
                    #pragma unroll
                    for (int ks = 0; ks < 4; ks++) {
                        #pragma unroll
                        for (int h = 0; h < 2; h++) {
                            uint64_t ah = aH + h * 1024 + ks * 2;
                            uint32_t d = tmem + tp * 256 + h * 128;
                            mma_f16_ss(d, ah, bH + ks * 2, IDESC_F16,
                                       !(s == 0 && sub == 0 && ks == 0));
                        }
                    }
                }
                TC_COMMIT(smem_base + 8 + buf * 8);
            }
        }
        {
            int buf = (g - 1) & 1;
            mbar_wait(smem_base + 8 + buf * 8, ((g - 1) >> 1) & 1);
        }
        TC_FENCE_AFTER();
        int half0 = wid >> 2;
        int grow = m0 + half0 * 128 + ((wid & 3) << 5) + lane;
        #pragma unroll
        for (int cb = 0; cb < 4; cb++) {
            uint32_t r[32];
            TC_LD_X32(r, tmem + tp * 256 + half0 * 128 + cb * 32);
            TC_WAIT_LD();
            int gcol = n0 + cb * 32;
            size_t base = (size_t)grow * N + gcol;
            #pragma unroll
            for (int j = 0; j < 32; j += 4) {
                float v0 = __uint_as_float(r[j]);
                float v1 = __uint_as_float(r[j + 1]);
                float v2 = __uint_as_float(r[j + 2]);
                float v3 = __uint_as_float(r[j + 3]);
                if (MODE == 2 || MODE == 3) {
                    float4 bb = *reinterpret_cast<const float4*>(bias + gcol + j);
                    v0 += bb.x; v1 += bb.y; v2 += bb.z; v3 += bb.w;
                }
                if (MODE == 2) {
                    v0 = fmaxf(v0, 0.f); v1 = fmaxf(v1, 0.f);
                    v2 = fmaxf(v2, 0.f); v3 = fmaxf(v3, 0.f);
                }
                if (MODE == 1 || MODE == 3) {
                    float4 rr = *reinterpret_cast<const float4*>(resid + base + j);
                    v0 += rr.x; v1 += rr.y; v2 += rr.z; v3 += rr.w;
                }
                if (MODE == 2) {
                    __half2 p0 = __floats2half2_rn(v0, v1);
                    __half2 p1 = __floats2half2_rn(v2, v3);
                    uint2 u;
                    u.x = *reinterpret_cast<uint32_t*>(&p0);
                    u.y = *reinterpret_cast<uint32_t*>(&p1);
                    *reinterpret_cast<uint2*>(Ch + base + j) = u;
                } else {
                    float4 o; o.x = v0; o.y = v1; o.z = v2; o.w = v3;
                    *reinterpret_cast<float4*>(C + base + j) = o;
                }
            }
        }
        TC_FENCE_BEFORE();
        __syncthreads();
    }
    __syncthreads();
    if (wid == 0) { TC_DEALLOC(tmem, 512); }

#else
    // ======================= mma.sync path =======================
    int wm = wid & 3, wn = wid >> 2;
    int arow = wm * 64 + (lane & 15);
    int brow = wn * 64 + (lane & 15);

    for (int tl = blockIdx.x; tl < ntiles; tl += gridDim.x) {
        int m0 = (tl / ntn) * BM, n0 = (tl % ntn) * BN;

        float acc[4][8][4];
        #pragma unroll
        for (int i = 0; i < 4; i++)
            #pragma unroll
            for (int j = 0; j < 8; j++)
                #pragma unroll
                for (int d = 0; d < 4; d++) acc[i][j][d] = 0.0f;

        stage_load(smem_base, Ah, Bh, m0, n0, 0, K, tid, 0);
        asm volatile("cp.async.commit_group;\n");

        for (int s = 0; s < S; s++) {
            asm volatile("cp.async.wait_group 0;\n");
            __syncthreads();
            if (s + 1 < S) {
                stage_load(smem_base, Ah, Bh, m0, n0, (s + 1) * BK, K, tid, (s + 1) & 1);
                asm volatile("cp.async.commit_group;\n");
            }
            int buf = s & 1;
            #pragma unroll
            for (int sub = 0; sub < 2; sub++) {
                uint32_t aHb = smem_base + AOFFS(buf, sub);
                uint32_t bHb = smem_base + BOFFS(buf, sub);
                #pragma unroll
                for (int ks = 0; ks < 4; ks++) {
                    int colb = ks * 32 + (lane >> 4) * 16;
                    uint32_t fa[4][4], fbH[4][4];
                    #pragma unroll
                    for (int mi = 0; mi < 4; mi++) {
                        uint32_t off = (uint32_t)((arow + mi * 16) * 128 + colb);
                        ldmx4u(fa[mi], aHb + SWZ(off));
                    }
                    #pragma unroll
                    for (int ni = 0; ni < 4; ni++) {
                        uint32_t off = (uint32_t)((brow + ni * 16) * 128 + colb);
                        ldmx4u(fbH[ni], bHb + SWZ(off));
                    }
                    #pragma unroll
                    for (int mi = 0; mi < 4; mi++)
                        #pragma unroll
                        for (int ni = 0; ni < 4; ni++) {
                            mma16816h(acc[mi][2 * ni],     fa[mi], fbH[ni][0], fbH[ni][2]);
                            mma16816h(acc[mi][2 * ni + 1], fa[mi], fbH[ni][1], fbH[ni][3]);
                        }
                }
            }
        }

        // Epilogue
        int r0 = lane >> 2, c0 = (lane & 3) * 2;
        #pragma unroll
        for (int mi = 0; mi < 4; mi++) {
            #pragma unroll
            for (int t = 0; t < 8; t++) {
                int col = n0 + wn * 64 + t * 8 + c0;
                #pragma unroll
                for (int hh = 0; hh < 2; hh++) {
                    int row = m0 + wm * 64 + mi * 16 + r0 + hh * 8;
                    float v0 = acc[mi][t][hh * 2];
                    float v1 = acc[mi][t][hh * 2 + 1];
                    size_t base = (size_t)row * N + col;
                    if (MODE == 2 || MODE == 3) { v0 += bias[col]; v1 += bias[col + 1]; }
                    if (MODE == 2) { v0 = fmaxf(v0, 0.f); v1 = fmaxf(v1, 0.f); }
                    if (MODE == 1 || MODE == 3) {
                        float2 rr = *reinterpret_cast<const float2*>(resid + base);
                        v0 += rr.x; v1 += rr.y;
                    }
                    if (MODE == 2) {
                        __half2 hp = __floats2half2_rn(v0, v1);
                        *reinterpret_cast<uint32_t*>(Ch + base) = *reinterpret_cast<uint32_t*>(&hp);
                    } else {
                        float2 o; o.x = v0; o.y = v1;
                        *reinterpret_cast<float2*>(C + base) = o;
                    }
                }
            }
        }
        __syncthreads();
    }
#endif
}

// ---------------------------------------------------------------------------
// Weight transpose + fp16 convert: w[K,N] fp32 -> out[N,K] fp16.
// 64x64 tile per block; coalesced both sides. Batched variant: z selects
// among 4 (src,dst) pairs (all 1024x1024).
// ---------------------------------------------------------------------------
__device__ __forceinline__ void tsplit_tile(
    const float* __restrict__ w, half_t* __restrict__ oh, int K, int N,
    int bx, int by, int t)
{
    __shared__ float tile[64][65];
    int k0 = by * 64, n0 = bx * 64;
    int lr = t >> 4;
    int lc = (t & 15) * 4;
    #pragma unroll
    for (int i = 0; i < 4; i++) {
        int r = lr + i * 16;
        float4 v = *reinterpret_cast<const float4*>(w + (size_t)(k0 + r) * N + n0 + lc);
        tile[r][lc] = v.x; tile[r][lc + 1] = v.y;
        tile[r][lc + 2] = v.z; tile[r][lc + 3] = v.w;
    }
    __syncthreads();
    #pragma unroll
    for (int o = 0; o < 2; o++) {
        int t2 = t + o * 256;
        int n = t2 >> 3;
        int k8 = (t2 & 7) * 8;
        __half2 h0 = __floats2half2_rn(tile[k8 + 0][n], tile[k8 + 1][n]);
        __half2 h1 = __floats2half2_rn(tile[k8 + 2][n], tile[k8 + 3][n]);
        __half2 h2 = __floats2half2_rn(tile[k8 + 4][n], tile[k8 + 5][n]);
        __half2 h3 = __floats2half2_rn(tile[k8 + 6][n], tile[k8 + 7][n]);
        uint4 u;
        u.x = *reinterpret_cast<uint32_t*>(&h0);
        u.y = *reinterpret_cast<uint32_t*>(&h1);
        u.z = *reinterpret_cast<uint32_t*>(&h2);
        u.w = *reinterpret_cast<uint32_t*>(&h3);
        *reinterpret_cast<uint4*>(oh + (size_t)(n0 + n) * K + k0 + k8) = u;
    }
}

__global__ __launch_bounds__(256) void tsplit4_kernel(
    const float* __restrict__ w0, const float* __restrict__ w1,
    const float* __restrict__ w2, const float* __restrict__ w3,
    half_t* __restrict__ d0, half_t* __restrict__ d1,
    half_t* __restrict__ d2, half_t* __restrict__ d3)
{
    const float* w; half_t* d;
    switch (blockIdx.z) {
        case 0: w = w0; d = d0; break;
        case 1: w = w1; d = d1; break;
        case 2: w = w2; d = d2; break;
        default: w = w3; d = d3; break;
    }
    tsplit_tile(w, d, DM, DM, blockIdx.x, blockIdx.y, threadIdx.x);
}

__global__ __launch_bounds__(256) void tsplit_kernel(
    const float* __restrict__ w, half_t* __restrict__ oh, int K, int N)
{
    tsplit_tile(w, oh, K, N, blockIdx.x, blockIdx.y, threadIdx.x);
}

// ---------------------------------------------------------------------------
// LayerNorm (ddof=1, eps on STD), fp16 output.
// ---------------------------------------------------------------------------
__global__ __launch_bounds__(256) void ln_kernel(
    const float* __restrict__ x, const float* __restrict__ alpha,
    const float* __restrict__ bias, half_t* __restrict__ yh)
{
    int row = blockIdx.x;
    int t = threadIdx.x;
    float4 v = reinterpret_cast<const float4*>(x + (size_t)row * DM)[t];
    float s  = v.x + v.y + v.z + v.w;
    float ss = v.x*v.x + v.y*v.y + v.z*v.z + v.w*v.w;

    __shared__ float reds[8], redss[8], bcast[2];
    #pragma unroll
    for (int off = 16; off; off >>= 1) {
        s  += __shfl_xor_sync(0xffffffffu, s,  off);
        ss += __shfl_xor_sync(0xffffffffu, ss, off);
    }
    int wid = t >> 5, lid = t & 31;
    if (lid == 0) { reds[wid] = s; redss[wid] = ss; }
    __syncthreads();
    if (t == 0) {
        float S = 0.f, SS = 0.f;
        #pragma unroll
        for (int i = 0; i < 8; i++) { S += reds[i]; SS += redss[i]; }
        float mean = S * (1.0f / DM);
        float var = (SS - (float)DM * mean * mean) * (1.0f / (DM - 1));
        var = fmaxf(var, 0.0f);
        bcast[0] = mean;
        bcast[1] = 1.0f / (sqrtf(var) + 1e-6f);
    }
    __syncthreads();
    float mean = bcast[0], inv = bcast[1];

    float4 av = reinterpret_cast<const float4*>(alpha)[t];
    float4 bv = reinterpret_cast<const float4*>(bias)[t];
    float o0 = av.x * (v.x - mean) * inv + bv.x;
    float o1 = av.y * (v.y - mean) * inv + bv.y;
    float o2 = av.z * (v.z - mean) * inv + bv.z;
    float o3 = av.w * (v.w - mean) * inv + bv.w;
    __half2 p0 = __floats2half2_rn(o0, o1);
    __half2 p1 = __floats2half2_rn(o2, o3);
    uint2 u;
    u.x = *reinterpret_cast<uint32_t*>(&p0);
    u.y = *reinterpret_cast<uint32_t*>(&p1);
    *reinterpret_cast<uint2*>(yh + (size_t)row * DM + t * 4) = u;
}

// ---------------------------------------------------------------------------
// KtV partial: per (b,h,chunk of 256 seq rows), Mpart[64,64] = K^T V (fp32).
// float4 smem reads.
// ---------------------------------------------------------------------------
__global__ __launch_bounds__(256) void ktv_kernel(
    const float* __restrict__ qkv, float* __restrict__ Mpart)
{
    int bh = blockIdx.x >> 3, cch = blockIdx.x & 7;
    int b = bh >> 4, h = bh & 15;
    const float* Kb = qkv + (size_t)b * SEQ * QKVS + 1024 + h * DK;
    const float* Vb = qkv + (size_t)b * SEQ * QKVS + 2048 + h * DK;

    __shared__ float Ks[64][68];
    __shared__ float Vs[64][68];

    int tid = threadIdx.x;
    int tx = tid & 15, ty = tid >> 4;
    int lr = tid >> 4;
    int lc = (tid & 15) << 2;

    float acc[4][4];
    #pragma unroll
    for (int i = 0; i < 4; i++)
        #pragma unroll
        for (int j = 0; j < 4; j++) acc[i][j] = 0.0f;

    int sbeg = cch * 256;
    for (int s0 = sbeg; s0 < sbeg + 256; s0 += 64) {
        __syncthreads();
        #pragma unroll
        for (int p = 0; p < 4; p++) {
            int r = lr + p * 16;
            *reinterpret_cast<float4*>(&Ks[r][lc]) =
                *reinterpret_cast<const float4*>(Kb + (size_t)(s0 + r) * QKVS + lc);
            *reinterpret_cast<float4*>(&Vs[r][lc]) =
                *reinterpret_cast<const float4*>(Vb + (size_t)(s0 + r) * QKVS + lc);
        }
        __syncthreads();
        #pragma unroll 8
        for (int s = 0; s < 64; s++) {
            float4 kf = *reinterpret_cast<const float4*>(&Ks[s][ty * 4]);
            float4 vf = *reinterpret_cast<const float4*>(&Vs[s][tx * 4]);
            acc[0][0] = fmaf(kf.x, vf.x, acc[0][0]);
            acc[0][1] = fmaf(kf.x, vf.y, acc[0][1]);
            acc[0][2] = fmaf(kf.x, vf.z, acc[0][2]);
            acc[0][3] = fmaf(kf.x, vf.w, acc[0][3]);
            acc[1][0] = fmaf(kf.y, vf.x, acc[1][0]);
            acc[1][1] = fmaf(kf.y, vf.y, acc[1][1]);
            acc[1][2] = fmaf(kf.y, vf.z, acc[1][2]);
            acc[1][3] = fmaf(kf.y, vf.w, acc[1][3]);
            acc[2][0] = fmaf(kf.z, vf.x, acc[2][0]);
            acc[2][1] = fmaf(kf.z, vf.y, acc[2][1]);
            acc[2][2] = fmaf(kf.z, vf.z, acc[2][2]);
            acc[2][3] = fmaf(kf.z, vf.w, acc[2][3]);
            acc[3][0] = fmaf(kf.w, vf.x, acc[3][0]);
            acc[3][1] = fmaf(kf.w, vf.y, acc[3][1]);
            acc[3][2] = fmaf(kf.w, vf.z, acc[3][2]);
            acc[3][3] = fmaf(kf.w, vf.w, acc[3][3]);
        }
    }

    float* Mb = Mpart + (size_t)blockIdx.x * DK * DK;
    #pragma unroll
    for (int i = 0; i < 4; i++)
        #pragma unroll
        for (int j = 0; j < 4; j++)
            Mb[(ty * 4 + i) * DK + (tx * 4 + j)] = acc[i][j];
}

// ---------------------------------------------------------------------------
// QM: O_bh = (Q_bh @ sum_c Mpart_bh_c) * 0.125, output fp16.
// ---------------------------------------------------------------------------
__global__ __launch_bounds__(256) void qm_kernel(
    const float* __restrict__ qkv, const float* __restrict__ Mp,
    half_t* __restrict__ Oh)
{
    int bh = blockIdx.y;
    int b = bh >> 4, h = bh & 15;
    int rt = blockIdx.x;
    const float* Qb = qkv + (size_t)b * SEQ * QKVS + (size_t)rt * 64 * QKVS + h * DK;
    const float* Mb = Mp + (size_t)bh * 8 * DK * DK;
    size_t obase = (size_t)b * SEQ * DM + (size_t)rt * 64 * DM + h * DK;

    __shared__ float Qs[64][68];
    __shared__ float Ms[64][68];

    int tid = threadIdx.x;
    int tx = tid & 15, ty = tid >> 4;
    int lr = tid >> 4;
    int lc = (tid & 15) << 2;

    #pragma unroll
    for (int p = 0; p < 4; p++) {
        int r = lr + p * 16;
        *reinterpret_cast<float4*>(&Qs[r][lc]) =
            *reinterpret_cast<const float4*>(Qb + (size_t)r * QKVS + lc);
        float4 a = make_float4(0.f, 0.f, 0.f, 0.f);
        #pragma unroll
        for (int cc = 0; cc < 8; cc++) {
            float4 t4 = *reinterpret_cast<const float4*>(Mb + (size_t)cc * DK * DK + (size_t)r * DK + lc);
            a.x += t4.x; a.y += t4.y; a.z += t4.z; a.w += t4.w;
        }
        *reinterpret_cast<float4*>(&Ms[r][lc]) = a;
    }
    __syncthreads();

    float acc[4][4];
    #pragma unroll
    for (int i = 0; i < 4; i++)
        #pragma unroll
        for (int j = 0; j < 4; j++) acc[i][j] = 0.0f;

    #pragma unroll 8
    for (int k = 0; k < 64; k++) {
        float4 mf = *reinterpret_cast<const float4*>(&Ms[k][tx * 4]);
        float qf[4];
        #pragma unroll
        for (int i = 0; i < 4; i++) qf[i] = Qs[ty * 4 + i][k];
        #pragma unroll
        for (int i = 0; i < 4; i++) {
            acc[i][0] = fmaf(qf[i], mf.x, acc[i][0]);
            acc[i][1] = fmaf(qf[i], mf.y, acc[i][1]);
            acc[i][2] = fmaf(qf[i], mf.z, acc[i][2]);
            acc[i][3] = fmaf(qf[i], mf.w, acc[i][3]);
        }
    }

    #pragma unroll
    for (int i = 0; i < 4; i++) {
        __half2 p0 = __floats2half2_rn(acc[i][0] * 0.125f, acc[i][1] * 0.125f);
        __half2 p1 = __floats2half2_rn(acc[i][2] * 0.125f, acc[i][3] * 0.125f);
        uint2 u;
        u.x = *reinterpret_cast<uint32_t*>(&p0);
        u.y = *reinterpret_cast<uint32_t*>(&p1);
        *reinterpret_cast<uint2*>(Oh + obase + (size_t)(ty * 4 + i) * DM + tx * 4) = u;
    }
}

// ---------------------------------------------------------------------------
// Launch
// ---------------------------------------------------------------------------
extern "C" void kernel_launch(void* const* d_in, const int* in_sizes, int n_in,
                              void* d_out, int out_size)
{
    const float* x    = (const float*)d_in[0];
    const float* wq   = (const float*)d_in[2];
    const float* wk   = (const float*)d_in[3];
    const float* wv   = (const float*)d_in[4];
    const float* wo   = (const float*)d_in[5];
    const float* w1   = (const float*)d_in[6];
    const float* b1   = (const float*)d_in[7];
    const float* w2   = (const float*)d_in[8];
    const float* b2   = (const float*)d_in[9];
    const float* ln1a = (const float*)d_in[10];
    const float* ln1b = (const float*)d_in[11];
    const float* ln2a = (const float*)d_in[12];
    const float* ln2b = (const float*)d_in[13];
    float* out = (float*)d_out;

    half_t *xn1h,*xn2h,*oh,*h1h;
    half_t *wqkvTh,*woTh,*w1Th,*w2Th;
    float *qkv,*x1,*mpart;
    cudaGetSymbolAddress((void**)&xn1h, g_xn1h);
    cudaGetSymbolAddress((void**)&xn2h, g_xn2h);
    cudaGetSymbolAddress((void**)&oh,   g_oh);
    cudaGetSymbolAddress((void**)&h1h,  g_h1h);
    cudaGetSymbolAddress((void**)&qkv,  g_qkv);  cudaGetSymbolAddress((void**)&x1, g_x1);
    cudaGetSymbolAddress((void**)&mpart,g_mpart);
    cudaGetSymbolAddress((void**)&wqkvTh, g_wqkvTh);
    cudaGetSymbolAddress((void**)&woTh, g_woTh);
    cudaGetSymbolAddress((void**)&w1Th, g_w1Th);
    cudaGetSymbolAddress((void**)&w2Th, g_w2Th);

    cudaFuncSetAttribute(gemm_tc<0>, cudaFuncAttributeMaxDynamicSharedMemorySize, SMEM_TOTAL);
    cudaFuncSetAttribute(gemm_tc<1>, cudaFuncAttributeMaxDynamicSharedMemorySize, SMEM_TOTAL);
    cudaFuncSetAttribute(gemm_tc<2>, cudaFuncAttributeMaxDynamicSharedMemorySize, SMEM_TOTAL);
    cudaFuncSetAttribute(gemm_tc<3>, cudaFuncAttributeMaxDynamicSharedMemorySize, SMEM_TOTAL);

    int nsm = 148;
    cudaDeviceGetAttribute(&nsm, cudaDevAttrMultiProcessorCount, 0);

    // Transpose + convert weights into [N, K] fp16.
    tsplit4_kernel<<<dim3(DM / 64, DM / 64, 4), 256>>>(
        wq, wk, wv, wo,
        wqkvTh, wqkvTh + 1024 * DM, wqkvTh + 2048 * DM, woTh);
    tsplit_kernel<<<dim3(DFF / 64, DM / 64), 256>>>(w1, w1Th, DM, DFF);
    tsplit_kernel<<<dim3(DM / 64, DFF / 64), 256>>>(w2, w2Th, DFF, DM);

    int tQKV = (NTOK / BM) * (QKVN / BN);   // 768
    int tDM  = (NTOK / BM) * (DM / BN);     // 256
    int tFF  = (NTOK / BM) * (DFF / BN);    // 1024
    int gQKV = tQKV < nsm ? tQKV : nsm;
    int gDM  = tDM  < nsm ? tDM  : nsm;
    int gFF  = tFF  < nsm ? tFF  : nsm;

    // 1) xn1 = LN(x) -> fp16
    ln_kernel<<<NTOK, 256>>>(x, ln1a, ln1b, xn1h);
    // 2) fused QKV projection: qkv[M, 3072] fp32
    gemm_tc<0><<<gQKV, 256, SMEM_TOTAL>>>(
        xn1h, wqkvTh, qkv, nullptr, QKVN, DM, tQKV, nullptr, nullptr);
    // 3) M = K^T V partials (linear attention; no softmax in reference)
    ktv_kernel<<<BATCH * NH * 8, 256>>>(qkv, mpart);
    // 4) O = Q @ M / 8 -> fp16
    qm_kernel<<<dim3(SEQ / 64, BATCH * NH), 256>>>(qkv, mpart, oh);
    // 5) x1 = x + O @ wo
    gemm_tc<1><<<gDM, 256, SMEM_TOTAL>>>(
        oh, woTh, x1, nullptr, DM, DM, tDM, nullptr, x);
    // 6) xn2 = LN(x1) -> fp16
    ln_kernel<<<NTOK, 256>>>(x1, ln2a, ln2b, xn2h);
    // 7) h1 = relu(xn2 @ w1 + b1) -> fp16
    gemm_tc<2><<<gFF, 256, SMEM_TOTAL>>>(
        xn2h, w1Th, nullptr, h1h, DFF, DM, tFF, b1, nullptr);
    // 8) out = x1 + h1 @ w2 + b2
    gemm_tc<3><<<gDM, 256, SMEM_TOTAL>>>(
        h1h, w2Th, out, nullptr, DM, DFF, tDM, b2, x1);
}

// round 15
// speedup vs baseline: 1.8746x; 1.0265x over previous
#include <cuda_runtime.h>
#include <cuda_fp16.h>
#include <math.h>
#include <stdint.h>

typedef __half half_t;

// Problem constants
#define DM    1024
#define DFF   4096
#define NTOK  8192
#define SEQ   2048
#define BATCH 4
#define NH    16
#define DK    64
#define QKVN  3072
#define QKVS  3072

// GEMM tiling: 256x128 CTA tile, BK=128 per stage, 2-stage ring.
#define BM 256
#define BN 128
#define BK 128
#define SMEM_TOTAL 197632
#define SWZ(x) ((x) ^ (((x) >> 3) & 0x70))

__device__ __forceinline__ uint32_t AOFFS(int buf, int sub) {
    return 1024u + (uint32_t)buf * 65536u + (uint32_t)sub * 32768u;
}
__device__ __forceinline__ uint32_t BOFFS(int buf, int sub) {
    return 132096u + (uint32_t)buf * 32768u + (uint32_t)sub * 16384u;
}

// ---------------------------------------------------------------------------
// Scratch (device globals)
// ---------------------------------------------------------------------------
__device__ half_t g_xn1h[NTOK * DM];
__device__ half_t g_xn2h[NTOK * DM];
__device__ half_t g_oh  [NTOK * DM];
__device__ half_t g_h1h [NTOK * DFF];
__device__ half_t g_qkv [NTOK * QKVS];
__device__ float  g_x1  [NTOK * DM];
__device__ float  g_mpart[BATCH * NH * 8 * DK * DK];
__device__ float  g_msum [BATCH * NH * DK * DK];
__device__ half_t g_wqkvTh[QKVN * DM];
__device__ half_t g_woTh[DM * DM];
__device__ half_t g_w1Th[DFF * DM];
__device__ half_t g_w2Th[DM * DFF];

// ---------------------------------------------------------------------------
// Helpers
// ---------------------------------------------------------------------------
__device__ __forceinline__ uint32_t smem_u32(const void* p) {
    return (uint32_t)__cvta_generic_to_shared(p);
}
__device__ __forceinline__ void cp16(uint32_t dst, const void* src) {
    asm volatile("cp.async.cg.shared.global [%0], [%1], 16;\n" :: "r"(dst), "l"(src));
}
__device__ __forceinline__ void ldmx4u(uint32_t* r, uint32_t addr) {
    asm volatile("ldmatrix.sync.aligned.m8n8.x4.shared.b16 {%0,%1,%2,%3}, [%4];\n"
                 : "=r"(r[0]), "=r"(r[1]), "=r"(r[2]), "=r"(r[3]) : "r"(addr));
}
__device__ __forceinline__ void mma16816h(float* d, const uint32_t* a, uint32_t b0, uint32_t b1) {
    asm volatile(
        "mma.sync.aligned.m16n8k16.row.col.f32.f16.f16.f32 "
        "{%0,%1,%2,%3},{%4,%5,%6,%7},{%8,%9},{%0,%1,%2,%3};\n"
        : "+f"(d[0]), "+f"(d[1]), "+f"(d[2]), "+f"(d[3])
        : "r"(a[0]), "r"(a[1]), "r"(a[2]), "r"(a[3]), "r"(b0), "r"(b1));
}
// fp16x4 -> float4
__device__ __forceinline__ float4 h4_to_f4(uint2 u) {
    __half2 a = *reinterpret_cast<__half2*>(&u.x);
    __half2 b = *reinterpret_cast<__half2*>(&u.y);
    float2 fa = __half22float2(a);
    float2 fb = __half22float2(b);
    return make_float4(fa.x, fa.y, fb.x, fb.y);
}

// ---------------------------------------------------------------------------
// Stage loader: A 256x128 + B 128x128 fp16 (two 64-col sub-tiles each).
// ---------------------------------------------------------------------------
__device__ __forceinline__ void stage_load(
    uint32_t smem_base,
    const half_t* __restrict__ Ah, const half_t* __restrict__ Bh,
    int m0, int n0, int k0, int K, int tid, int buf)
{
    #pragma unroll
    for (int sub = 0; sub < 2; sub++) {
        uint32_t abase = smem_base + AOFFS(buf, sub);
        const half_t* asrc = Ah + (size_t)m0 * K + k0 + sub * 64;
        #pragma unroll
        for (int i = 0; i < 8; i++) {
            int chunk = tid + i * 256;
            int r = chunk >> 3, c = chunk & 7;
            uint32_t off = (uint32_t)(r * 128 + c * 16);
            cp16(abase + SWZ(off), asrc + (size_t)r * K + c * 8);
        }
        uint32_t bbase = smem_base + BOFFS(buf, sub);
        const half_t* bsrc = Bh + (size_t)n0 * K + k0 + sub * 64;
        #pragma unroll
        for (int i = 0; i < 4; i++) {
            int chunk = tid + i * 256;
            int r = chunk >> 3, c = chunk & 7;
            uint32_t off = (uint32_t)(r * 128 + c * 16);
            cp16(bbase + SWZ(off), bsrc + (size_t)r * K + c * 8);
        }
    }
}

// ===========================================================================
// tcgen05-only helpers (compiled only when an 'a' feature target exists)
// ===========================================================================
#if defined(__CUDA_ARCH_FEAT_SM103_ALL) || defined(__CUDA_ARCH_FEAT_SM100_ALL)
#define IDESC_F16 ((1u << 4) | (16u << 17) | (8u << 24))
__device__ __forceinline__ uint32_t elect_one() {
    uint32_t pred;
    asm volatile("{\n .reg .pred p;\n elect.sync _|p, 0xFFFFFFFF;\n selp.b32 %0, 1, 0, p;\n}"
                 : "=r"(pred));
    return pred;
}
__device__ __forceinline__ uint64_t make_desc(uint32_t addr) {
    return ((uint64_t)2 << 61) | ((uint64_t)1 << 46) | ((uint64_t)64 << 32) |
           ((uint64_t)1 << 16) | ((uint64_t)(addr >> 4) & 0x3FFF);
}
__device__ __forceinline__ void mma_f16_ss(uint32_t d, uint64_t a, uint64_t b,
                                           uint32_t idesc, bool en) {
    uint32_t e = en ? 1u : 0u;
    asm volatile(
        "{\n\t"
        ".reg .pred p;\n\t"
        "setp.ne.u32 p, %4, 0;\n\t"
        "tcgen05.mma.cta_group::1.kind::f16 [%0], %1, %2, %3, {%5,%5,%5,%5}, p;\n\t"
        "}"
        :: "r"(d), "l"(a), "l"(b), "r"(idesc), "r"(e), "r"(0u) : "memory");
}
__device__ __forceinline__ void mbar_init(uint32_t a, uint32_t c) {
    asm volatile("mbarrier.init.shared.b64 [%0], %1;" :: "r"(a), "r"(c) : "memory");
}
__device__ __forceinline__ void mbar_wait(uint32_t mbar, uint32_t parity) {
    asm volatile(
        "{\n\t"
        ".reg .pred P1;\n\t"
        "WAIT_LOOP_%=:\n\t"
        "mbarrier.try_wait.parity.acquire.cta.shared::cta.b64 P1, [%0], %1, 0x989680;\n\t"
        "@P1 bra.uni WAIT_DONE_%=;\n\t"
        "bra.uni WAIT_LOOP_%=;\n\t"
        "WAIT_DONE_%=:\n\t"
        "}" :: "r"(mbar), "r"(parity) : "memory");
}
#define TC_ALLOC(sm, n)  asm volatile("tcgen05.alloc.cta_group::1.sync.aligned.shared::cta.b32 [%0], %1;" :: "r"(sm), "r"((uint32_t)(n)) : "memory")
#define TC_RELINQ()      asm volatile("tcgen05.relinquish_alloc_permit.cta_group::1.sync.aligned;")
#define TC_DEALLOC(t, n) asm volatile("tcgen05.dealloc.cta_group::1.sync.aligned.b32 %0, %1;" :: "r"(t), "r"((uint32_t)(n)))
#define TC_COMMIT(mb)    asm volatile("tcgen05.commit.cta_group::1.mbarrier::arrive::one.shared::cluster.b64 [%0];" :: "r"(mb) : "memory")
#define TC_FENCE_AFTER() asm volatile("tcgen05.fence::after_thread_sync;" ::: "memory")
#define TC_FENCE_BEFORE() asm volatile("tcgen05.fence::before_thread_sync;" ::: "memory")
#define TC_WAIT_LD()     asm volatile("tcgen05.wait::ld.sync.aligned;" ::: "memory")
#define FENCE_ASYNC()    asm volatile("fence.proxy.async.shared::cta;" ::: "memory")
#define TC_LD_X32(r, ta) \
    asm volatile( \
        "tcgen05.ld.sync.aligned.32x32b.x32.b32 " \
        "{%0, %1, %2, %3, %4, %5, %6, %7, " \
        " %8, %9, %10, %11, %12, %13, %14, %15, " \
        " %16, %17, %18, %19, %20, %21, %22, %23, " \
        " %24, %25, %26, %27, %28, %29, %30, %31}, [%32];" \
        : "=r"((r)[0]),  "=r"((r)[1]),  "=r"((r)[2]),  "=r"((r)[3]), \
          "=r"((r)[4]),  "=r"((r)[5]),  "=r"((r)[6]),  "=r"((r)[7]), \
          "=r"((r)[8]),  "=r"((r)[9]),  "=r"((r)[10]), "=r"((r)[11]), \
          "=r"((r)[12]), "=r"((r)[13]), "=r"((r)[14]), "=r"((r)[15]), \
          "=r"((r)[16]), "=r"((r)[17]), "=r"((r)[18]), "=r"((r)[19]), \
          "=r"((r)[20]), "=r"((r)[21]), "=r"((r)[22]), "=r"((r)[23]), \
          "=r"((r)[24]), "=r"((r)[25]), "=r"((r)[26]), "=r"((r)[27]), \
          "=r"((r)[28]), "=r"((r)[29]), "=r"((r)[30]), "=r"((r)[31]) \
        : "r"(ta))
#endif

// ---------------------------------------------------------------------------
// Persistent GEMM, 256x128 tiles, single fp16 MMA, BK=128, 2-stage.
// MODE: 0=plain fp32, 1=+resid fp32, 2=relu(D+bias)->fp16, 3=D+bias+resid fp32,
//       4=plain fp16.
// ---------------------------------------------------------------------------
template<int MODE>
__global__ __launch_bounds__(256)
void gemm_tc(
    const half_t* __restrict__ Ah, const half_t* __restrict__ Bh,
    float* __restrict__ C, half_t* __restrict__ Ch,
    int N, int K, int ntiles,
    const float* __restrict__ bias, const float* __restrict__ resid)
{
    extern __shared__ char smem[];
    uint32_t smem_base = smem_u32(smem);
    int tid = threadIdx.x;
    int wid = tid >> 5, lane = tid & 31;
    int ntn = N / BN;
    int S = K / BK;

#if defined(__CUDA_ARCH_FEAT_SM103_ALL) || defined(__CUDA_ARCH_FEAT_SM100_ALL)
    // ======================= tcgen05 path =======================
    if (wid == 0) { TC_ALLOC(smem_base, 512); }
    else if (wid == 1) { TC_RELINQ(); }
    if (tid == 0) { mbar_init(smem_base + 8, 1); mbar_init(smem_base + 16, 1); }
    __syncthreads();
    uint32_t tmem;
    asm volatile("ld.shared.b32 %0, [%1];" : "=r"(tmem) : "r"(smem_base));

    int g = 0, tcount = 0;
    for (int tl = blockIdx.x; tl < ntiles; tl += gridDim.x) {
        int m0 = (tl / ntn) * BM, n0 = (tl % ntn) * BN;
        int tp = tcount & 1; tcount++;
        for (int s = 0; s < S; s++, g++) {
            int buf = g & 1;
            if (g >= 2) mbar_wait(smem_base + 8 + buf * 8, ((g - 2) >> 1) & 1);
            stage_load(smem_base, Ah, Bh, m0, n0, s * BK, K, tid, buf);
            asm volatile("cp.async.commit_group;\n");
            asm volatile("cp.async.wait_group 0;\n");
            __syncthreads();
            FENCE_ASYNC();
            if (wid == 0 && elect_one()) {
                TC_FENCE_AFTER();
                #pragma unroll
                for (int sub = 0; sub < 2; sub++) {
                    uint64_t aH = make_desc(smem_base + AOFFS(buf, sub));
                    uint64_t bH = make_desc(smem_base + BOFFS(buf, sub));
                    #pragma unroll
                    for (int ks = 0; ks < 4; ks++) {
                        #pragma unroll
                        for (int h = 0; h < 2; h++) {
                            uint64_t ah = aH + h * 1024 + ks * 2;
                            uint32_t d = tmem + tp * 256 + h * 128;
                            mma_f16_ss(d, ah, bH + ks * 2, IDESC_F16,
                                       !(s == 0 && sub == 0 && ks == 0));
                        }
                    }
                }
                TC_COMMIT(smem_base + 8 + buf * 8);
            }
        }
        {
            int buf = (g - 1) & 1;
            mbar_wait(smem_base + 8 + buf * 8, ((g - 1) >> 1) & 1);
        }
        TC_FENCE_AFTER();
        int half0 = wid >> 2;
        int grow = m0 + half0 * 128 + ((wid & 3) << 5) + lane;
        #pragma unroll
        for (int cb = 0; cb < 4; cb++) {
            uint32_t r[32];
            TC_LD_X32(r, tmem + tp * 256 + half0 * 128 + cb * 32);
            TC_WAIT_LD();
            int gcol = n0 + cb * 32;
            size_t base = (size_t)grow * N + gcol;
            #pragma unroll
            for (int j = 0; j < 32; j += 4) {
                float v0 = __uint_as_float(r[j]);
                float v1 = __uint_as_float(r[j + 1]);
                float v2 = __uint_as_float(r[j + 2]);
                float v3 = __uint_as_float(r[j + 3]);
                if (MODE == 2 || MODE == 3) {
                    float4 bb = *reinterpret_cast<const float4*>(bias + gcol + j);
                    v0 += bb.x; v1 += bb.y; v2 += bb.z; v3 += bb.w;
                }
                if (MODE == 2) {
                    v0 = fmaxf(v0, 0.f); v1 = fmaxf(v1, 0.f);
                    v2 = fmaxf(v2, 0.f); v3 = fmaxf(v3, 0.f);
                }
                if (MODE == 1 || MODE == 3) {
                    float4 rr = *reinterpret_cast<const float4*>(resid + base + j);
                    v0 += rr.x; v1 += rr.y; v2 += rr.z; v3 += rr.w;
                }
                if (MODE == 2 || MODE == 4) {
                    __half2 p0 = __floats2half2_rn(v0, v1);
                    __half2 p1 = __floats2half2_rn(v2, v3);
                    uint2 u;
                    u.x = *reinterpret_cast<uint32_t*>(&p0);
                    u.y = *reinterpret_cast<uint32_t*>(&p1);
                    *reinterpret_cast<uint2*>(Ch + base + j) = u;
                } else {
                    float4 o; o.x = v0; o.y = v1; o.z = v2; o.w = v3;
                    *reinterpret_cast<float4*>(C + base + j) = o;
                }
            }
        }
        TC_FENCE_BEFORE();
        __syncthreads();
    }
    __syncthreads();
    if (wid == 0) { TC_DEALLOC(tmem, 512); }

#else
    // ======================= mma.sync path =======================
    int wm = wid & 3, wn = wid >> 2;
    int arow = wm * 64 + (lane & 15);
    int brow = wn * 64 + (lane & 15);

    for (int tl = blockIdx.x; tl < ntiles; tl += gridDim.x) {
        int m0 = (tl / ntn) * BM, n0 = (tl % ntn) * BN;

        float acc[4][8][4];
        #pragma unroll
        for (int i = 0; i < 4; i++)
            #pragma unroll
            for (int j = 0; j < 8; j++)
                #pragma unroll
                for (int d = 0; d < 4; d++) acc[i][j][d] = 0.0f;

        stage_load(smem_base, Ah, Bh, m0, n0, 0, K, tid, 0);
        asm volatile("cp.async.commit_group;\n");

        for (int s = 0; s < S; s++) {
            asm volatile("cp.async.wait_group 0;\n");
            __syncthreads();
            if (s + 1 < S) {
                stage_load(smem_base, Ah, Bh, m0, n0, (s + 1) * BK, K, tid, (s + 1) & 1);
                asm volatile("cp.async.commit_group;\n");
            }
            int buf = s & 1;
            #pragma unroll
            for (int sub = 0; sub < 2; sub++) {
                uint32_t aHb = smem_base + AOFFS(buf, sub);
                uint32_t bHb = smem_base + BOFFS(buf, sub);
                #pragma unroll
                for (int ks = 0; ks < 4; ks++) {
                    int colb = ks * 32 + (lane >> 4) * 16;
                    uint32_t fa[4][4], fbH[4][4];
                    #pragma unroll
                    for (int mi = 0; mi < 4; mi++) {
                        uint32_t off = (uint32_t)((arow + mi * 16) * 128 + colb);
                        ldmx4u(fa[mi], aHb + SWZ(off));
                    }
                    #pragma unroll
                    for (int ni = 0; ni < 4; ni++) {
                        uint32_t off = (uint32_t)((brow + ni * 16) * 128 + colb);
                        ldmx4u(fbH[ni], bHb + SWZ(off));
                    }
                    #pragma unroll
                    for (int mi = 0; mi < 4; mi++)
                        #pragma unroll
                        for (int ni = 0; ni < 4; ni++) {
                            mma16816h(acc[mi][2 * ni],     fa[mi], fbH[ni][0], fbH[ni][2]);
                            mma16816h(acc[mi][2 * ni + 1], fa[mi], fbH[ni][1], fbH[ni][3]);
                        }
                }
            }
        }

        // Epilogue
        int r0 = lane >> 2, c0 = (lane & 3) * 2;
        #pragma unroll
        for (int mi = 0; mi < 4; mi++) {
            #pragma unroll
            for (int t = 0; t < 8; t++) {
                int col = n0 + wn * 64 + t * 8 + c0;
                #pragma unroll
                for (int hh = 0; hh < 2; hh++) {
                    int row = m0 + wm * 64 + mi * 16 + r0 + hh * 8;
                    float v0 = acc[mi][t][hh * 2];
                    float v1 = acc[mi][t][hh * 2 + 1];
                    size_t base = (size_t)row * N + col;
                    if (MODE == 2 || MODE == 3) { v0 += bias[col]; v1 += bias[col + 1]; }
                    if (MODE == 2) { v0 = fmaxf(v0, 0.f); v1 = fmaxf(v1, 0.f); }
                    if (MODE == 1 || MODE == 3) {
                        float2 rr = *reinterpret_cast<const float2*>(resid + base);
                        v0 += rr.x; v1 += rr.y;
                    }
                    if (MODE == 2 || MODE == 4) {
                        __half2 hp = __floats2half2_rn(v0, v1);
                        *reinterpret_cast<uint32_t*>(Ch + base) = *reinterpret_cast<uint32_t*>(&hp);
                    } else {
                        float2 o; o.x = v0; o.y = v1;
                        *reinterpret_cast<float2*>(C + base) = o;
                    }
                }
            }
        }
        __syncthreads();
    }
#endif
}

// ---------------------------------------------------------------------------
// Weight transpose + fp16 convert: w[K,N] fp32 -> out[N,K] fp16.
// ---------------------------------------------------------------------------
__device__ __forceinline__ void tsplit_tile(
    const float* __restrict__ w, half_t* __restrict__ oh, int K, int N,
    int bx, int by, int t)
{
    __shared__ float tile[64][65];
    int k0 = by * 64, n0 = bx * 64;
    int lr = t >> 4;
    int lc = (t & 15) * 4;
    #pragma unroll
    for (int i = 0; i < 4; i++) {
        int r = lr + i * 16;
        float4 v = *reinterpret_cast<const float4*>(w + (size_t)(k0 + r) * N + n0 + lc);
        tile[r][lc] = v.x; tile[r][lc + 1] = v.y;
        tile[r][lc + 2] = v.z; tile[r][lc + 3] = v.w;
    }
    __syncthreads();
    #pragma unroll
    for (int o = 0; o < 2; o++) {
        int t2 = t + o * 256;
        int n = t2 >> 3;
        int k8 = (t2 & 7) * 8;
        __half2 h0 = __floats2half2_rn(tile[k8 + 0][n], tile[k8 + 1][n]);
        __half2 h1 = __floats2half2_rn(tile[k8 + 2][n], tile[k8 + 3][n]);
        __half2 h2 = __floats2half2_rn(tile[k8 + 4][n], tile[k8 + 5][n]);
        __half2 h3 = __floats2half2_rn(tile[k8 + 6][n], tile[k8 + 7][n]);
        uint4 u;
        u.x = *reinterpret_cast<uint32_t*>(&h0);
        u.y = *reinterpret_cast<uint32_t*>(&h1);
        u.z = *reinterpret_cast<uint32_t*>(&h2);
        u.w = *reinterpret_cast<uint32_t*>(&h3);
        *reinterpret_cast<uint4*>(oh + (size_t)(n0 + n) * K + k0 + k8) = u;
    }
}

__global__ __launch_bounds__(256) void tsplit4_kernel(
    const float* __restrict__ w0, const float* __restrict__ w1,
    const float* __restrict__ w2, const float* __restrict__ w3,
    half_t* __restrict__ d0, half_t* __restrict__ d1,
    half_t* __restrict__ d2, half_t* __restrict__ d3)
{
    const float* w; half_t* d;
    switch (blockIdx.z) {
        case 0: w = w0; d = d0; break;
        case 1: w = w1; d = d1; break;
        case 2: w = w2; d = d2; break;
        default: w = w3; d = d3; break;
    }
    tsplit_tile(w, d, DM, DM, blockIdx.x, blockIdx.y, threadIdx.x);
}

__global__ __launch_bounds__(256) void tsplit_kernel(
    const float* __restrict__ w, half_t* __restrict__ oh, int K, int N)
{
    tsplit_tile(w, oh, K, N, blockIdx.x, blockIdx.y, threadIdx.x);
}

// ---------------------------------------------------------------------------
// LayerNorm (ddof=1, eps on STD), fp16 output.
// ---------------------------------------------------------------------------
__global__ __launch_bounds__(256) void ln_kernel(
    const float* __restrict__ x, const float* __restrict__ alpha,
    const float* __restrict__ bias, half_t* __restrict__ yh)
{
    int row = blockIdx.x;
    int t = threadIdx.x;
    float4 v = reinterpret_cast<const float4*>(x + (size_t)row * DM)[t];
    float s  = v.x + v.y + v.z + v.w;
    float ss = v.x*v.x + v.y*v.y + v.z*v.z + v.w*v.w;

    __shared__ float reds[8], redss[8], bcast[2];
    #pragma unroll
    for (int off = 16; off; off >>= 1) {
        s  += __shfl_xor_sync(0xffffffffu, s,  off);
        ss += __shfl_xor_sync(0xffffffffu, ss, off);
    }
    int wid = t >> 5, lid = t & 31;
    if (lid == 0) { reds[wid] = s; redss[wid] = ss; }
    __syncthreads();
    if (t == 0) {
        float S = 0.f, SS = 0.f;
        #pragma unroll
        for (int i = 0; i < 8; i++) { S += reds[i]; SS += redss[i]; }
        float mean = S * (1.0f / DM);
        float var = (SS - (float)DM * mean * mean) * (1.0f / (DM - 1));
        var = fmaxf(var, 0.0f);
        bcast[0] = mean;
        bcast[1] = 1.0f / (sqrtf(var) + 1e-6f);
    }
    __syncthreads();
    float mean = bcast[0], inv = bcast[1];

    float4 av = reinterpret_cast<const float4*>(alpha)[t];
    float4 bv = reinterpret_cast<const float4*>(bias)[t];
    float o0 = av.x * (v.x - mean) * inv + bv.x;
    float o1 = av.y * (v.y - mean) * inv + bv.y;
    float o2 = av.z * (v.z - mean) * inv + bv.z;
    float o3 = av.w * (v.w - mean) * inv + bv.w;
    __half2 p0 = __floats2half2_rn(o0, o1);
    __half2 p1 = __floats2half2_rn(o2, o3);
    uint2 u;
    u.x = *reinterpret_cast<uint32_t*>(&p0);
    u.y = *reinterpret_cast<uint32_t*>(&p1);
    *reinterpret_cast<uint2*>(yh + (size_t)row * DM + t * 4) = u;
}

// ---------------------------------------------------------------------------
// KtV partial: per (b,h,chunk of 256 seq rows), Mpart[64,64] = K^T V (fp32).
// Inputs fp16, converted on smem fill; compute identical to before.
// ---------------------------------------------------------------------------
__global__ __launch_bounds__(256) void ktv_kernel(
    const half_t* __restrict__ qkv, float* __restrict__ Mpart)
{
    int bh = blockIdx.x >> 3, cch = blockIdx.x & 7;
    int b = bh >> 4, h = bh & 15;
    const half_t* Kb = qkv + (size_t)b * SEQ * QKVS + 1024 + h * DK;
    const half_t* Vb = qkv + (size_t)b * SEQ * QKVS + 2048 + h * DK;

    __shared__ float Ks[64][68];
    __shared__ float Vs[64][68];

    int tid = threadIdx.x;
    int tx = tid & 15, ty = tid >> 4;
    int lr = tid >> 4;
    int lc = (tid & 15) << 2;

    float acc[4][4];
    #pragma unroll
    for (int i = 0; i < 4; i++)
        #pragma unroll
        for (int j = 0; j < 4; j++) acc[i][j] = 0.0f;

    int sbeg = cch * 256;
    for (int s0 = sbeg; s0 < sbeg + 256; s0 += 64) {
        __syncthreads();
        #pragma unroll
        for (int p = 0; p < 4; p++) {
            int r = lr + p * 16;
            uint2 ku = *reinterpret_cast<const uint2*>(Kb + (size_t)(s0 + r) * QKVS + lc);
            uint2 vu = *reinterpret_cast<const uint2*>(Vb + (size_t)(s0 + r) * QKVS + lc);
            *reinterpret_cast<float4*>(&Ks[r][lc]) = h4_to_f4(ku);
            *reinterpret_cast<float4*>(&Vs[r][lc]) = h4_to_f4(vu);
        }
        __syncthreads();
        #pragma unroll 8
        for (int s = 0; s < 64; s++) {
            float4 kf = *reinterpret_cast<const float4*>(&Ks[s][ty * 4]);
            float4 vf = *reinterpret_cast<const float4*>(&Vs[s][tx * 4]);
            acc[0][0] = fmaf(kf.x, vf.x, acc[0][0]);
            acc[0][1] = fmaf(kf.x, vf.y, acc[0][1]);
            acc[0][2] = fmaf(kf.x, vf.z, acc[0][2]);
            acc[0][3] = fmaf(kf.x, vf.w, acc[0][3]);
            acc[1][0] = fmaf(kf.y, vf.x, acc[1][0]);
            acc[1][1] = fmaf(kf.y, vf.y, acc[1][1]);
            acc[1][2] = fmaf(kf.y, vf.z, acc[1][2]);
            acc[1][3] = fmaf(kf.y, vf.w, acc[1][3]);
            acc[2][0] = fmaf(kf.z, vf.x, acc[2][0]);
            acc[2][1] = fmaf(kf.z, vf.y, acc[2][1]);
            acc[2][2] = fmaf(kf.z, vf.z, acc[2][2]);
            acc[2][3] = fmaf(kf.z, vf.w, acc[2][3]);
            acc[3][0] = fmaf(kf.w, vf.x, acc[3][0]);
            acc[3][1] = fmaf(kf.w, vf.y, acc[3][1]);
            acc[3][2] = fmaf(kf.w, vf.z, acc[3][2]);
            acc[3][3] = fmaf(kf.w, vf.w, acc[3][3]);
        }
    }

    float* Mb = Mpart + (size_t)blockIdx.x * DK * DK;
    #pragma unroll
    for (int i = 0; i < 4; i++)
        #pragma unroll
        for (int j = 0; j < 4; j++)
            Mb[(ty * 4 + i) * DK + (tx * 4 + j)] = acc[i][j];
}

// ---------------------------------------------------------------------------
// Reduce 8 KtV partials per (b,h): Msum = sum_c Mpart[c]. Same add order
// (cc = 0..7 ascending) as the previous in-qm sum.
// ---------------------------------------------------------------------------
__global__ __launch_bounds__(256) void ktv_reduce_kernel(
    const float* __restrict__ Mpart, float* __restrict__ Msum)
{
    int bh = blockIdx.x;
    int t = threadIdx.x;
    const float* base = Mpart + (size_t)bh * 8 * DK * DK;
    float* outp = Msum + (size_t)bh * DK * DK;
    #pragma unroll
    for (int i = 0; i < 4; i++) {
        int idx4 = t + i * 256;            // float4 index within 4096 elems
        float4 a = make_float4(0.f, 0.f, 0.f, 0.f);
        #pragma unroll
        for (int cc = 0; cc < 8; cc++) {
            float4 v = *reinterpret_cast<const float4*>(base + (size_t)cc * DK * DK + idx4 * 4);
            a.x += v.x; a.y += v.y; a.z += v.z; a.w += v.w;
        }
        *reinterpret_cast<float4*>(outp + idx4 * 4) = a;
    }
}

// ---------------------------------------------------------------------------
// QM: O_bh = (Q_bh @ Msum_bh) * 0.125, output fp16. Q loaded fp16.
// ---------------------------------------------------------------------------
__global__ __launch_bounds__(256) void qm_kernel(
    const half_t* __restrict__ qkv, const float* __restrict__ Msum,
    half_t* __restrict__ Oh)
{
    int bh = blockIdx.y;
    int b = bh >> 4, h = bh & 15;
    int rt = blockIdx.x;
    const half_t* Qb = qkv + (size_t)b * SEQ * QKVS + (size_t)rt * 64 * QKVS + h * DK;
    const float* Mb = Msum + (size_t)bh * DK * DK;
    size_t obase = (size_t)b * SEQ * DM + (size_t)rt * 64 * DM + h * DK;

    __shared__ float Qs[64][68];
    __shared__ float Ms[64][68];

    int tid = threadIdx.x;
    int tx = tid & 15, ty = tid >> 4;
    int lr = tid >> 4;
    int lc = (tid & 15) << 2;

    #pragma unroll
    for (int p = 0; p < 4; p++) {
        int r = lr + p * 16;
        uint2 qu = *reinterpret_cast<const uint2*>(Qb + (size_t)r * QKVS + lc);
        *reinterpret_cast<float4*>(&Qs[r][lc]) = h4_to_f4(qu);
        *reinterpret_cast<float4*>(&Ms[r][lc]) =
            *reinterpret_cast<const float4*>(Mb + (size_t)r * DK + lc);
    }
    __syncthreads();

    float acc[4][4];
    #pragma unroll
    for (int i = 0; i < 4; i++)
        #pragma unroll
        for (int j = 0; j < 4; j++) acc[i][j] = 0.0f;

    #pragma unroll 8
    for (int k = 0; k < 64; k++) {
        float4 mf = *reinterpret_cast<const float4*>(&Ms[k][tx * 4]);
        float qf[4];
        #pragma unroll
        for (int i = 0; i < 4; i++) qf[i] = Qs[ty * 4 + i][k];
        #pragma unroll
        for (int i = 0; i < 4; i++) {
            acc[i][0] = fmaf(qf[i], mf.x, acc[i][0]);
            acc[i][1] = fmaf(qf[i], mf.y, acc[i][1]);
            acc[i][2] = fmaf(qf[i], mf.z, acc[i][2]);
            acc[i][3] = fmaf(qf[i], mf.w, acc[i][3]);
        }
    }

    #pragma unroll
    for (int i = 0; i < 4; i++) {
        __half2 p0 = __floats2half2_rn(acc[i][0] * 0.125f, acc[i][1] * 0.125f);
        __half2 p1 = __floats2half2_rn(acc[i][2] * 0.125f, acc[i][3] * 0.125f);
        uint2 u;
        u.x = *reinterpret_cast<uint32_t*>(&p0);
        u.y = *reinterpret_cast<uint32_t*>(&p1);
        *reinterpret_cast<uint2*>(Oh + obase + (size_t)(ty * 4 + i) * DM + tx * 4) = u;
    }
}

// ---------------------------------------------------------------------------
// Launch
// ---------------------------------------------------------------------------
extern "C" void kernel_launch(void* const* d_in, const int* in_sizes, int n_in,
                              void* d_out, int out_size)
{
    const float* x    = (const float*)d_in[0];
    const float* wq   = (const float*)d_in[2];
    const float* wk   = (const float*)d_in[3];
    const float* wv   = (const float*)d_in[4];
    const float* wo   = (const float*)d_in[5];
    const float* w1   = (const float*)d_in[6];
    const float* b1   = (const float*)d_in[7];
    const float* w2   = (const float*)d_in[8];
    const float* b2   = (const float*)d_in[9];
    const float* ln1a = (const float*)d_in[10];
    const float* ln1b = (const float*)d_in[11];
    const float* ln2a = (const float*)d_in[12];
    const float* ln2b = (const float*)d_in[13];
    float* out = (float*)d_out;

    half_t *xn1h,*xn2h,*oh,*h1h,*qkv;
    half_t *wqkvTh,*woTh,*w1Th,*w2Th;
    float *x1,*mpart,*msum;
    cudaGetSymbolAddress((void**)&xn1h, g_xn1h);
    cudaGetSymbolAddress((void**)&xn2h, g_xn2h);
    cudaGetSymbolAddress((void**)&oh,   g_oh);
    cudaGetSymbolAddress((void**)&h1h,  g_h1h);
    cudaGetSymbolAddress((void**)&qkv,  g_qkv);  cudaGetSymbolAddress((void**)&x1, g_x1);
    cudaGetSymbolAddress((void**)&mpart,g_mpart);
    cudaGetSymbolAddress((void**)&msum, g_msum);
    cudaGetSymbolAddress((void**)&wqkvTh, g_wqkvTh);
    cudaGetSymbolAddress((void**)&woTh, g_woTh);
    cudaGetSymbolAddress((void**)&w1Th, g_w1Th);
    cudaGetSymbolAddress((void**)&w2Th, g_w2Th);

    cudaFuncSetAttribute(gemm_tc<1>, cudaFuncAttributeMaxDynamicSharedMemorySize, SMEM_TOTAL);
    cudaFuncSetAttribute(gemm_tc<2>, cudaFuncAttributeMaxDynamicSharedMemorySize, SMEM_TOTAL);
    cudaFuncSetAttribute(gemm_tc<3>, cudaFuncAttributeMaxDynamicSharedMemorySize, SMEM_TOTAL);
    cudaFuncSetAttribute(gemm_tc<4>, cudaFuncAttributeMaxDynamicSharedMemorySize, SMEM_TOTAL);

    int nsm = 148;
    cudaDeviceGetAttribute(&nsm, cudaDevAttrMultiProcessorCount, 0);

    // Transpose + convert weights into [N, K] fp16.
    tsplit4_kernel<<<dim3(DM / 64, DM / 64, 4), 256>>>(
        wq, wk, wv, wo,
        wqkvTh, wqkvTh + 1024 * DM, wqkvTh + 2048 * DM, woTh);
    tsplit_kernel<<<dim3(DFF / 64, DM / 64), 256>>>(w1, w1Th, DM, DFF);
    tsplit_kernel<<<dim3(DM / 64, DFF / 64), 256>>>(w2, w2Th, DFF, DM);

    int tQKV = (NTOK / BM) * (QKVN / BN);   // 768
    int tDM  = (NTOK / BM) * (DM / BN);     // 256
    int tFF  = (NTOK / BM) * (DFF / BN);    // 1024
    int gQKV = tQKV < nsm ? tQKV : nsm;
    int gDM  = tDM  < nsm ? tDM  : nsm;
    int gFF  = tFF  < nsm ? tFF  : nsm;

    // 1) xn1 = LN(x) -> fp16
    ln_kernel<<<NTOK, 256>>>(x, ln1a, ln1b, xn1h);
    // 2) fused QKV projection: qkv[M, 3072] -> fp16
    gemm_tc<4><<<gQKV, 256, SMEM_TOTAL>>>(
        xn1h, wqkvTh, nullptr, qkv, QKVN, DM, tQKV, nullptr, nullptr);
    // 3) M = K^T V partials + reduce (linear attention; no softmax in reference)
    ktv_kernel<<<BATCH * NH * 8, 256>>>(qkv, mpart);
    ktv_reduce_kernel<<<BATCH * NH, 256>>>(mpart, msum);
    // 4) O = Q @ M / 8 -> fp16
    qm_kernel<<<dim3(SEQ / 64, BATCH * NH), 256>>>(qkv, msum, oh);
    // 5) x1 = x + O @ wo
    gemm_tc<1><<<gDM, 256, SMEM_TOTAL>>>(
        oh, woTh, x1, nullptr, DM, DM, tDM, nullptr, x);
    // 6) xn2 = LN(x1) -> fp16
    ln_kernel<<<NTOK, 256>>>(x1, ln2a, ln2b, xn2h);
    // 7) h1 = relu(xn2 @ w1 + b1) -> fp16
    gemm_tc<2><<<gFF, 256, SMEM_TOTAL>>>(
        xn2h, w1Th, nullptr, h1h, DFF, DM, tFF, b1, nullptr);
    // 8) out = x1 + h1 @ w2 + b2
    gemm_tc<3><<<gDM, 256, SMEM_TOTAL>>>(
        h1h, w2Th, out, nullptr, DM, DFF, tDM, b2, x1);
}